// round 1
// baseline (speedup 1.0000x reference)
#include <cuda_runtime.h>
#include <cuda_bf16.h>
#include <math.h>

// Problem constants
#define SEQ   2048
#define HID   4096
#define NH    32
#define NKV   8
#define HD    128
#define KVHID 1024   // NKV*HD

// Scratch (device globals; allocation-free rule)
__device__ float g_q[SEQ * HID];      // (s, h, d)
__device__ float g_k[SEQ * KVHID];    // (s, kvh, d)
__device__ float g_v[SEQ * KVHID];
__device__ float g_attn[SEQ * HID];   // attention output before o_proj

// ---------------------------------------------------------------------------
// SGEMM: C[M,N] = A[M,K] @ W[N,K]^T   (A, W row-major, K contiguous in both)
// BM=BN=128, BK=16, 256 threads, 8x8 per-thread microtile.
// ---------------------------------------------------------------------------
__global__ __launch_bounds__(256) void sgemm_nt(const float* __restrict__ A,
                                                const float* __restrict__ W,
                                                float* __restrict__ C,
                                                int M, int N, int K) {
    constexpr int BM = 128, BN = 128, BK = 16;
    __shared__ float As[BK][BM + 4];
    __shared__ float Bs[BK][BN + 4];

    const int tid = threadIdx.x;
    const int mb = blockIdx.y * BM;
    const int nb = blockIdx.x * BN;
    const int lr = tid >> 2;          // 0..63   (load row)
    const int lc = (tid & 3) << 2;    // 0,4,8,12 (load k-col, float4)
    const int tr = (tid >> 4) << 3;   // compute row base
    const int tc = (tid & 15) << 3;   // compute col base

    float acc[8][8];
#pragma unroll
    for (int i = 0; i < 8; i++)
#pragma unroll
        for (int j = 0; j < 8; j++) acc[i][j] = 0.f;

    const float* Ap = A + (size_t)mb * K;
    const float* Wp = W + (size_t)nb * K;

    for (int k0 = 0; k0 < K; k0 += BK) {
#pragma unroll
        for (int ro = 0; ro < BM; ro += 64) {
            float4 a = *(const float4*)(Ap + (size_t)(lr + ro) * K + k0 + lc);
            As[lc + 0][lr + ro] = a.x;
            As[lc + 1][lr + ro] = a.y;
            As[lc + 2][lr + ro] = a.z;
            As[lc + 3][lr + ro] = a.w;
            float4 b = *(const float4*)(Wp + (size_t)(lr + ro) * K + k0 + lc);
            Bs[lc + 0][lr + ro] = b.x;
            Bs[lc + 1][lr + ro] = b.y;
            Bs[lc + 2][lr + ro] = b.z;
            Bs[lc + 3][lr + ro] = b.w;
        }
        __syncthreads();
#pragma unroll
        for (int kk = 0; kk < BK; kk++) {
            float ra[8], rb[8];
            *(float4*)&ra[0] = *(const float4*)&As[kk][tr];
            *(float4*)&ra[4] = *(const float4*)&As[kk][tr + 4];
            *(float4*)&rb[0] = *(const float4*)&Bs[kk][tc];
            *(float4*)&rb[4] = *(const float4*)&Bs[kk][tc + 4];
#pragma unroll
            for (int i = 0; i < 8; i++)
#pragma unroll
                for (int j = 0; j < 8; j++)
                    acc[i][j] = fmaf(ra[i], rb[j], acc[i][j]);
        }
        __syncthreads();
    }

#pragma unroll
    for (int i = 0; i < 8; i++) {
        float* cp = C + (size_t)(mb + tr + i) * N + nb + tc;
        *(float4*)(cp)     = make_float4(acc[i][0], acc[i][1], acc[i][2], acc[i][3]);
        *(float4*)(cp + 4) = make_float4(acc[i][4], acc[i][5], acc[i][6], acc[i][7]);
    }
}

// ---------------------------------------------------------------------------
// RoPE: applied in-place to g_q (32 heads) and g_k (8 heads).
// grid (SEQ, NH+NKV), block 64 (one thread per rotation pair).
// ---------------------------------------------------------------------------
__global__ void rope_kernel(float* __restrict__ q, float* __restrict__ k,
                            const int* __restrict__ pos_ids) {
    const int s = blockIdx.x;
    const int h = blockIdx.y;
    const int d = threadIdx.x;  // 0..63

    float* row = (h < NH) ? (q + (size_t)s * HID + h * HD)
                          : (k + (size_t)s * KVHID + (h - NH) * HD);

    // inv_freq = 500000 ^ (-d/64) = exp(-d * ln(500000)/64)
    const float cexp = 0.20503692556210917f;  // ln(500000)/64
    float inv_freq = expf(-(float)d * cexp);
    float freq = (float)pos_ids[s] * inv_freq;
    float cs, sn;
    sincosf(freq, &sn, &cs);

    float x1 = row[d];
    float x2 = row[d + 64];
    row[d]      = x1 * cs - x2 * sn;
    row[d + 64] = x2 * cs + x1 * sn;
}

// ---------------------------------------------------------------------------
// Flash attention, fp32, non-causal over all 2048 keys (== ring combine).
// 64 queries x 64 keys per inner tile, 256 threads, D=128.
// Smem tiles use block-granular XOR swizzle: phys_blk = blk ^ ((row>>2)&7)
// (rows in compute loops are spaced 4 apart; this is the swizzle that
//  spreads them across all 32 banks while keeping float4 alignment).
// ---------------------------------------------------------------------------
#define ATTN_SMEM ((3 * 64 * 128 + 64 * 68 + 3 * 64) * 4)

__global__ __launch_bounds__(256) void attn_kernel(const float* __restrict__ Q,
                                                   const float* __restrict__ K,
                                                   const float* __restrict__ V,
                                                   float* __restrict__ O) {
    extern __shared__ float sm[];
    float* Qs  = sm;                 // 64 x 128 (swizzled)
    float* Ks  = Qs + 64 * 128;
    float* Vs  = Ks + 64 * 128;
    float* Ss  = Vs + 64 * 128;      // 64 x 68
    float* ms  = Ss + 64 * 68;       // 64
    float* ls  = ms + 64;            // 64
    float* fct = ls + 64;            // 64

    const int tid = threadIdx.x;
    const int ti = tid >> 4;         // 0..15
    const int tj = tid & 15;         // 0..15
    const int r0  = ti << 2;         // query rows owned (4)
    const int c0  = tj << 2;         // score cols owned (4)
    const int oc0 = tj << 3;         // output cols owned (8)
    const int qsw = ti & 7;
    const int ksw = tj & 7;

    const int qt   = blockIdx.x;     // query tile (0..31)
    const int head = blockIdx.y;     // 0..31
    const int kvh  = head >> 2;
    const float sm_scale = 0.08838834764831845f; // 1/sqrt(128)

    // --- load Q tile (scaled) ---
    const float* qp = Q + (size_t)qt * 64 * HID + head * HD;
    for (int i = tid; i < 64 * 32; i += 256) {
        int row = i >> 5, b = i & 31;
        float4 x = *(const float4*)(qp + (size_t)row * HID + b * 4);
        x.x *= sm_scale; x.y *= sm_scale; x.z *= sm_scale; x.w *= sm_scale;
        int pb = b ^ ((row >> 2) & 7);
        *(float4*)(Qs + row * 128 + pb * 4) = x;
    }
    if (tid < 64) { ms[tid] = -1e30f; ls[tid] = 0.f; }

    float acc[4][8];
#pragma unroll
    for (int r = 0; r < 4; r++)
#pragma unroll
        for (int j = 0; j < 8; j++) acc[r][j] = 0.f;

    const float* kp = K + kvh * HD;
    const float* vp = V + kvh * HD;

    for (int kt = 0; kt < SEQ / 64; kt++) {
        // --- load K, V tiles ---
        for (int i = tid; i < 64 * 32; i += 256) {
            int row = i >> 5, b = i & 31;
            int pb = b ^ ((row >> 2) & 7);
            size_t g = (size_t)(kt * 64 + row) * KVHID + b * 4;
            *(float4*)(Ks + row * 128 + pb * 4) = *(const float4*)(kp + g);
            *(float4*)(Vs + row * 128 + pb * 4) = *(const float4*)(vp + g);
        }
        __syncthreads();

        // --- S = Q K^T (4x4 microtile per thread) ---
        float sv[4][4];
#pragma unroll
        for (int r = 0; r < 4; r++)
#pragma unroll
            for (int c = 0; c < 4; c++) sv[r][c] = 0.f;

#pragma unroll 8
        for (int d = 0; d < 128; d += 4) {
            int blk = d >> 2;
            float4 qv[4], kv[4];
#pragma unroll
            for (int r = 0; r < 4; r++)
                qv[r] = *(const float4*)(Qs + (r0 + r) * 128 + ((blk ^ qsw) << 2));
#pragma unroll
            for (int c = 0; c < 4; c++)
                kv[c] = *(const float4*)(Ks + (c0 + c) * 128 + ((blk ^ ksw) << 2));
#pragma unroll
            for (int r = 0; r < 4; r++)
#pragma unroll
                for (int c = 0; c < 4; c++) {
                    sv[r][c] = fmaf(qv[r].x, kv[c].x, sv[r][c]);
                    sv[r][c] = fmaf(qv[r].y, kv[c].y, sv[r][c]);
                    sv[r][c] = fmaf(qv[r].z, kv[c].z, sv[r][c]);
                    sv[r][c] = fmaf(qv[r].w, kv[c].w, sv[r][c]);
                }
        }
#pragma unroll
        for (int r = 0; r < 4; r++)
#pragma unroll
            for (int c = 0; c < 4; c++)
                Ss[(r0 + r) * 68 + c0 + c] = sv[r][c];
        __syncthreads();

        // --- online softmax row pass (4 lanes per row) ---
        {
            int row = tid >> 2, qq = tid & 3;
            float* srow = Ss + row * 68 + qq * 16;
            float mx = srow[0];
#pragma unroll
            for (int j = 1; j < 16; j++) mx = fmaxf(mx, srow[j]);
            mx = fmaxf(mx, __shfl_xor_sync(0xffffffffu, mx, 1));
            mx = fmaxf(mx, __shfl_xor_sync(0xffffffffu, mx, 2));
            float m_old = ms[row];
            float m_new = fmaxf(m_old, mx);
            float sum = 0.f;
#pragma unroll
            for (int j = 0; j < 16; j++) {
                float p = __expf(srow[j] - m_new);
                srow[j] = p;
                sum += p;
            }
            sum += __shfl_xor_sync(0xffffffffu, sum, 1);
            sum += __shfl_xor_sync(0xffffffffu, sum, 2);
            if (qq == 0) {
                float f = __expf(m_old - m_new);
                fct[row] = f;
                ls[row] = ls[row] * f + sum;
                ms[row] = m_new;
            }
        }
        __syncthreads();

        // --- rescale accumulators, then O += P V ---
        float f[4];
#pragma unroll
        for (int r = 0; r < 4; r++) f[r] = fct[r0 + r];
#pragma unroll
        for (int r = 0; r < 4; r++)
#pragma unroll
            for (int j = 0; j < 8; j++) acc[r][j] *= f[r];

#pragma unroll 4
        for (int kk = 0; kk < 64; kk++) {
            int sw = (kk >> 2) & 7;
            float4 v0 = *(const float4*)(Vs + kk * 128 + (((tj * 2)     ^ sw) << 2));
            float4 v1 = *(const float4*)(Vs + kk * 128 + (((tj * 2 + 1) ^ sw) << 2));
            float p[4];
#pragma unroll
            for (int r = 0; r < 4; r++) p[r] = Ss[(r0 + r) * 68 + kk];
#pragma unroll
            for (int r = 0; r < 4; r++) {
                acc[r][0] = fmaf(p[r], v0.x, acc[r][0]);
                acc[r][1] = fmaf(p[r], v0.y, acc[r][1]);
                acc[r][2] = fmaf(p[r], v0.z, acc[r][2]);
                acc[r][3] = fmaf(p[r], v0.w, acc[r][3]);
                acc[r][4] = fmaf(p[r], v1.x, acc[r][4]);
                acc[r][5] = fmaf(p[r], v1.y, acc[r][5]);
                acc[r][6] = fmaf(p[r], v1.z, acc[r][6]);
                acc[r][7] = fmaf(p[r], v1.w, acc[r][7]);
            }
        }
        __syncthreads();
    }

    // --- finalize: divide by l, write out ---
    float* op = O + (size_t)qt * 64 * HID + head * HD;
#pragma unroll
    for (int r = 0; r < 4; r++) {
        float inv = 1.0f / ls[r0 + r];
        float* p = op + (size_t)(r0 + r) * HID + oc0;
        *(float4*)(p)     = make_float4(acc[r][0] * inv, acc[r][1] * inv,
                                        acc[r][2] * inv, acc[r][3] * inv);
        *(float4*)(p + 4) = make_float4(acc[r][4] * inv, acc[r][5] * inv,
                                        acc[r][6] * inv, acc[r][7] * inv);
    }
}

// ---------------------------------------------------------------------------
// Launch
// ---------------------------------------------------------------------------
extern "C" void kernel_launch(void* const* d_in, const int* in_sizes, int n_in,
                              void* d_out, int out_size) {
    (void)in_sizes; (void)n_in; (void)out_size;
    const float* hs  = (const float*)d_in[0];
    const int*   pos = (const int*)d_in[1];
    const float* qw  = (const float*)d_in[2];
    const float* kw  = (const float*)d_in[3];
    const float* vw  = (const float*)d_in[4];
    const float* ow  = (const float*)d_in[5];
    float* out = (float*)d_out;

    float *q, *k, *v, *attn;
    cudaGetSymbolAddress((void**)&q, g_q);
    cudaGetSymbolAddress((void**)&k, g_k);
    cudaGetSymbolAddress((void**)&v, g_v);
    cudaGetSymbolAddress((void**)&attn, g_attn);

    cudaFuncSetAttribute(attn_kernel,
                         cudaFuncAttributeMaxDynamicSharedMemorySize, ATTN_SMEM);

    // QKV projections
    sgemm_nt<<<dim3(HID / 128, SEQ / 128), 256>>>(hs, qw, q, SEQ, HID, HID);
    sgemm_nt<<<dim3(KVHID / 128, SEQ / 128), 256>>>(hs, kw, k, SEQ, KVHID, HID);
    sgemm_nt<<<dim3(KVHID / 128, SEQ / 128), 256>>>(hs, vw, v, SEQ, KVHID, HID);

    // RoPE on Q and K
    rope_kernel<<<dim3(SEQ, NH + NKV), 64>>>(q, k, pos);

    // Attention (global softmax == ring-block softmax + LSE recombine)
    attn_kernel<<<dim3(SEQ / 64, NH), 256, ATTN_SMEM>>>(q, k, v, attn);

    // Output projection
    sgemm_nt<<<dim3(HID / 128, SEQ / 128), 256>>>(attn, ow, out, SEQ, HID, HID);
}

// round 3
// speedup vs baseline: 1.7028x; 1.7028x over previous
#include <cuda_runtime.h>
#include <cuda_bf16.h>
#include <stdint.h>
#include <math.h>

// Problem constants
#define SEQ   2048
#define HID   4096
#define NH    32
#define NKV   8
#define HD    128
#define KVHID 1024   // NKV*HD

// Scratch (device globals; allocation-free rule)
__device__ float g_q[SEQ * HID];      // (s, h, d)
__device__ float g_k[SEQ * KVHID];    // (s, kvh, d)
__device__ float g_v[SEQ * KVHID];
__device__ float g_attn[SEQ * HID];   // attention output before o_proj

// ---------------------------------------------------------------------------
// TF32 helpers
// ---------------------------------------------------------------------------
__device__ __forceinline__ uint32_t f2t(float x) {
    uint32_t u;
    asm("cvt.rna.tf32.f32 %0, %1;" : "=r"(u) : "f"(x));
    return u;
}

__device__ __forceinline__ void mma_tf32(float* c, const uint32_t* a,
                                         const uint32_t* b) {
    asm volatile(
        "mma.sync.aligned.m16n8k8.row.col.f32.tf32.tf32.f32 "
        "{%0,%1,%2,%3}, {%4,%5,%6,%7}, {%8,%9}, {%0,%1,%2,%3};"
        : "+f"(c[0]), "+f"(c[1]), "+f"(c[2]), "+f"(c[3])
        : "r"(a[0]), "r"(a[1]), "r"(a[2]), "r"(a[3]), "r"(b[0]), "r"(b[1]));
}

// ---------------------------------------------------------------------------
// TF32 tensor-core GEMM: C[M,N] = A[M,K] @ W[N,K]^T  (both row-major, K contig)
// CTA tile 128x128, BK=16, 256 threads, 8 warps in 4(m) x 2(n),
// warp tile 32x64 = 2(m16) x 8(n8) mma tiles. Double-buffered smem.
// Smem layout [row][k] stride 20 words: fragment LDS pattern
// (20*g + tg) % 32 covers 32 distinct banks -> conflict-free.
// ---------------------------------------------------------------------------
#define LDS_STRIDE 20

__global__ __launch_bounds__(256) void gemm_tf32(const float* __restrict__ A,
                                                 const float* __restrict__ W,
                                                 float* __restrict__ C,
                                                 int M, int N, int K) {
    __shared__ uint32_t As[2][128 * LDS_STRIDE];
    __shared__ uint32_t Bs[2][128 * LDS_STRIDE];

    const int tid  = threadIdx.x;
    const int mb   = blockIdx.y * 128;
    const int nb   = blockIdx.x * 128;
    const int lane = tid & 31;
    const int wid  = tid >> 5;
    const int g    = lane >> 2;   // groupID 0..7
    const int tg   = lane & 3;    // thread-in-group 0..3
    const int wm   = (wid >> 1) * 32;  // warp row base
    const int wn   = (wid & 1) * 64;   // warp col base

    // loader mapping: 512 float4 per 128x16 tile, 2 per thread
    const int lrow0 = tid >> 2;            // rows tid>>2 and 64+(tid>>2)
    const int lkc   = (tid & 3) * 4;       // k sub-col (float4)

    const float* Ap = A + (size_t)mb * K;
    const float* Wp = W + (size_t)nb * K;

    float acc[2][8][4];
#pragma unroll
    for (int i = 0; i < 2; i++)
#pragma unroll
        for (int j = 0; j < 8; j++)
#pragma unroll
            for (int t = 0; t < 4; t++) acc[i][j][t] = 0.f;

    // --- preload first chunk ---
    {
#pragma unroll
        for (int h = 0; h < 2; h++) {
            int row = lrow0 + h * 64;
            float4 a = *(const float4*)(Ap + (size_t)row * K + lkc);
            uint32_t* d = &As[0][row * LDS_STRIDE + lkc];
            d[0] = f2t(a.x); d[1] = f2t(a.y); d[2] = f2t(a.z); d[3] = f2t(a.w);
            float4 b = *(const float4*)(Wp + (size_t)row * K + lkc);
            uint32_t* e = &Bs[0][row * LDS_STRIDE + lkc];
            e[0] = f2t(b.x); e[1] = f2t(b.y); e[2] = f2t(b.z); e[3] = f2t(b.w);
        }
    }
    __syncthreads();

    int buf = 0;
    for (int k0 = 0; k0 < K; k0 += 16) {
        // prefetch next chunk into registers
        float4 pa[2], pb[2];
        const bool has_next = (k0 + 16) < K;
        if (has_next) {
#pragma unroll
            for (int h = 0; h < 2; h++) {
                int row = lrow0 + h * 64;
                pa[h] = *(const float4*)(Ap + (size_t)row * K + k0 + 16 + lkc);
                pb[h] = *(const float4*)(Wp + (size_t)row * K + k0 + 16 + lkc);
            }
        }

        // compute on current buffer
        const uint32_t* asb = As[buf];
        const uint32_t* bsb = Bs[buf];
#pragma unroll
        for (int kk = 0; kk < 16; kk += 8) {
            uint32_t af[2][4], bf[8][2];
#pragma unroll
            for (int i = 0; i < 2; i++) {
                int r = wm + i * 16;
                af[i][0] = asb[(r + g) * LDS_STRIDE + kk + tg];
                af[i][1] = asb[(r + g + 8) * LDS_STRIDE + kk + tg];
                af[i][2] = asb[(r + g) * LDS_STRIDE + kk + tg + 4];
                af[i][3] = asb[(r + g + 8) * LDS_STRIDE + kk + tg + 4];
            }
#pragma unroll
            for (int j = 0; j < 8; j++) {
                int c = wn + j * 8;
                bf[j][0] = bsb[(c + g) * LDS_STRIDE + kk + tg];
                bf[j][1] = bsb[(c + g) * LDS_STRIDE + kk + tg + 4];
            }
#pragma unroll
            for (int i = 0; i < 2; i++)
#pragma unroll
                for (int j = 0; j < 8; j++)
                    mma_tf32(acc[i][j], af[i], bf[j]);
        }

        // store prefetched chunk to other buffer
        if (has_next) {
#pragma unroll
            for (int h = 0; h < 2; h++) {
                int row = lrow0 + h * 64;
                uint32_t* d = &As[buf ^ 1][row * LDS_STRIDE + lkc];
                d[0] = f2t(pa[h].x); d[1] = f2t(pa[h].y);
                d[2] = f2t(pa[h].z); d[3] = f2t(pa[h].w);
                uint32_t* e = &Bs[buf ^ 1][row * LDS_STRIDE + lkc];
                e[0] = f2t(pb[h].x); e[1] = f2t(pb[h].y);
                e[2] = f2t(pb[h].z); e[3] = f2t(pb[h].w);
            }
        }
        __syncthreads();
        buf ^= 1;
    }

    // epilogue: c0,c1 contiguous -> float2 stores
#pragma unroll
    for (int i = 0; i < 2; i++) {
        int row = mb + wm + i * 16 + g;
#pragma unroll
        for (int j = 0; j < 8; j++) {
            int col = nb + wn + j * 8 + tg * 2;
            *(float2*)(C + (size_t)row * N + col) =
                make_float2(acc[i][j][0], acc[i][j][1]);
            *(float2*)(C + (size_t)(row + 8) * N + col) =
                make_float2(acc[i][j][2], acc[i][j][3]);
        }
    }
}

// ---------------------------------------------------------------------------
// RoPE: applied in-place to g_q (32 heads) and g_k (8 heads).
// ---------------------------------------------------------------------------
__global__ void rope_kernel(float* __restrict__ q, float* __restrict__ k,
                            const int* __restrict__ pos_ids) {
    const int s = blockIdx.x;
    const int h = blockIdx.y;
    const int d = threadIdx.x;  // 0..63

    float* row = (h < NH) ? (q + (size_t)s * HID + h * HD)
                          : (k + (size_t)s * KVHID + (h - NH) * HD);

    const float cexp = 0.20503692556210917f;  // ln(500000)/64
    float inv_freq = expf(-(float)d * cexp);
    float freq = (float)pos_ids[s] * inv_freq;
    float cs, sn;
    sincosf(freq, &sn, &cs);

    float x1 = row[d];
    float x2 = row[d + 64];
    row[d]      = x1 * cs - x2 * sn;
    row[d + 64] = x2 * cs + x1 * sn;
}

// ---------------------------------------------------------------------------
// Flash attention, fp32, non-causal over all 2048 keys (== ring combine).
// ---------------------------------------------------------------------------
#define ATTN_SMEM ((3 * 64 * 128 + 64 * 68 + 3 * 64) * 4)

__global__ __launch_bounds__(256) void attn_kernel(const float* __restrict__ Q,
                                                   const float* __restrict__ K,
                                                   const float* __restrict__ V,
                                                   float* __restrict__ O) {
    extern __shared__ float sm[];
    float* Qs  = sm;                 // 64 x 128 (swizzled)
    float* Ks  = Qs + 64 * 128;
    float* Vs  = Ks + 64 * 128;
    float* Ss  = Vs + 64 * 128;      // 64 x 68
    float* ms  = Ss + 64 * 68;       // 64
    float* ls  = ms + 64;            // 64
    float* fct = ls + 64;            // 64

    const int tid = threadIdx.x;
    const int ti = tid >> 4;         // 0..15
    const int tj = tid & 15;         // 0..15
    const int r0  = ti << 2;         // query rows owned (4)
    const int c0  = tj << 2;         // score cols owned (4)
    const int oc0 = tj << 3;         // output cols owned (8)
    const int qsw = ti & 7;
    const int ksw = tj & 7;

    const int qt   = blockIdx.x;     // query tile (0..31)
    const int head = blockIdx.y;     // 0..31
    const int kvh  = head >> 2;
    const float sm_scale = 0.08838834764831845f; // 1/sqrt(128)

    // --- load Q tile (scaled) ---
    const float* qp = Q + (size_t)qt * 64 * HID + head * HD;
    for (int i = tid; i < 64 * 32; i += 256) {
        int row = i >> 5, b = i & 31;
        float4 x = *(const float4*)(qp + (size_t)row * HID + b * 4);
        x.x *= sm_scale; x.y *= sm_scale; x.z *= sm_scale; x.w *= sm_scale;
        int pb = b ^ ((row >> 2) & 7);
        *(float4*)(Qs + row * 128 + pb * 4) = x;
    }
    if (tid < 64) { ms[tid] = -1e30f; ls[tid] = 0.f; }

    float acc[4][8];
#pragma unroll
    for (int r = 0; r < 4; r++)
#pragma unroll
        for (int j = 0; j < 8; j++) acc[r][j] = 0.f;

    const float* kp = K + kvh * HD;
    const float* vp = V + kvh * HD;

    for (int kt = 0; kt < SEQ / 64; kt++) {
        // --- load K, V tiles ---
        for (int i = tid; i < 64 * 32; i += 256) {
            int row = i >> 5, b = i & 31;
            int pb = b ^ ((row >> 2) & 7);
            size_t gidx = (size_t)(kt * 64 + row) * KVHID + b * 4;
            *(float4*)(Ks + row * 128 + pb * 4) = *(const float4*)(kp + gidx);
            *(float4*)(Vs + row * 128 + pb * 4) = *(const float4*)(vp + gidx);
        }
        __syncthreads();

        // --- S = Q K^T (4x4 microtile per thread) ---
        float sv[4][4];
#pragma unroll
        for (int r = 0; r < 4; r++)
#pragma unroll
            for (int c = 0; c < 4; c++) sv[r][c] = 0.f;

#pragma unroll 8
        for (int d = 0; d < 128; d += 4) {
            int blk = d >> 2;
            float4 qv[4], kv[4];
#pragma unroll
            for (int r = 0; r < 4; r++)
                qv[r] = *(const float4*)(Qs + (r0 + r) * 128 + ((blk ^ qsw) << 2));
#pragma unroll
            for (int c = 0; c < 4; c++)
                kv[c] = *(const float4*)(Ks + (c0 + c) * 128 + ((blk ^ ksw) << 2));
#pragma unroll
            for (int r = 0; r < 4; r++)
#pragma unroll
                for (int c = 0; c < 4; c++) {
                    sv[r][c] = fmaf(qv[r].x, kv[c].x, sv[r][c]);
                    sv[r][c] = fmaf(qv[r].y, kv[c].y, sv[r][c]);
                    sv[r][c] = fmaf(qv[r].z, kv[c].z, sv[r][c]);
                    sv[r][c] = fmaf(qv[r].w, kv[c].w, sv[r][c]);
                }
        }
#pragma unroll
        for (int r = 0; r < 4; r++)
#pragma unroll
            for (int c = 0; c < 4; c++)
                Ss[(r0 + r) * 68 + c0 + c] = sv[r][c];
        __syncthreads();

        // --- online softmax row pass (4 lanes per row) ---
        {
            int row = tid >> 2, qq = tid & 3;
            float* srow = Ss + row * 68 + qq * 16;
            float mx = srow[0];
#pragma unroll
            for (int j = 1; j < 16; j++) mx = fmaxf(mx, srow[j]);
            mx = fmaxf(mx, __shfl_xor_sync(0xffffffffu, mx, 1));
            mx = fmaxf(mx, __shfl_xor_sync(0xffffffffu, mx, 2));
            float m_old = ms[row];
            float m_new = fmaxf(m_old, mx);
            float sum = 0.f;
#pragma unroll
            for (int j = 0; j < 16; j++) {
                float p = __expf(srow[j] - m_new);
                srow[j] = p;
                sum += p;
            }
            sum += __shfl_xor_sync(0xffffffffu, sum, 1);
            sum += __shfl_xor_sync(0xffffffffu, sum, 2);
            if (qq == 0) {
                float f = __expf(m_old - m_new);
                fct[row] = f;
                ls[row] = ls[row] * f + sum;
                ms[row] = m_new;
            }
        }
        __syncthreads();

        // --- rescale accumulators, then O += P V ---
        float f[4];
#pragma unroll
        for (int r = 0; r < 4; r++) f[r] = fct[r0 + r];
#pragma unroll
        for (int r = 0; r < 4; r++)
#pragma unroll
            for (int j = 0; j < 8; j++) acc[r][j] *= f[r];

#pragma unroll 4
        for (int kk = 0; kk < 64; kk++) {
            int sw = (kk >> 2) & 7;
            float4 v0 = *(const float4*)(Vs + kk * 128 + (((tj * 2)     ^ sw) << 2));
            float4 v1 = *(const float4*)(Vs + kk * 128 + (((tj * 2 + 1) ^ sw) << 2));
            float p[4];
#pragma unroll
            for (int r = 0; r < 4; r++) p[r] = Ss[(r0 + r) * 68 + kk];
#pragma unroll
            for (int r = 0; r < 4; r++) {
                acc[r][0] = fmaf(p[r], v0.x, acc[r][0]);
                acc[r][1] = fmaf(p[r], v0.y, acc[r][1]);
                acc[r][2] = fmaf(p[r], v0.z, acc[r][2]);
                acc[r][3] = fmaf(p[r], v0.w, acc[r][3]);
                acc[r][4] = fmaf(p[r], v1.x, acc[r][4]);
                acc[r][5] = fmaf(p[r], v1.y, acc[r][5]);
                acc[r][6] = fmaf(p[r], v1.z, acc[r][6]);
                acc[r][7] = fmaf(p[r], v1.w, acc[r][7]);
            }
        }
        __syncthreads();
    }

    // --- finalize: divide by l, write out ---
    float* op = O + (size_t)qt * 64 * HID + head * HD;
#pragma unroll
    for (int r = 0; r < 4; r++) {
        float inv = 1.0f / ls[r0 + r];
        float* p = op + (size_t)(r0 + r) * HID + oc0;
        *(float4*)(p)     = make_float4(acc[r][0] * inv, acc[r][1] * inv,
                                        acc[r][2] * inv, acc[r][3] * inv);
        *(float4*)(p + 4) = make_float4(acc[r][4] * inv, acc[r][5] * inv,
                                        acc[r][6] * inv, acc[r][7] * inv);
    }
}

// ---------------------------------------------------------------------------
// Launch
// ---------------------------------------------------------------------------
extern "C" void kernel_launch(void* const* d_in, const int* in_sizes, int n_in,
                              void* d_out, int out_size) {
    (void)in_sizes; (void)n_in; (void)out_size;
    const float* hs  = (const float*)d_in[0];
    const int*   pos = (const int*)d_in[1];
    const float* qw  = (const float*)d_in[2];
    const float* kw  = (const float*)d_in[3];
    const float* vw  = (const float*)d_in[4];
    const float* ow  = (const float*)d_in[5];
    float* out = (float*)d_out;

    float *q, *k, *v, *attn;
    cudaGetSymbolAddress((void**)&q, g_q);
    cudaGetSymbolAddress((void**)&k, g_k);
    cudaGetSymbolAddress((void**)&v, g_v);
    cudaGetSymbolAddress((void**)&attn, g_attn);

    cudaFuncSetAttribute(attn_kernel,
                         cudaFuncAttributeMaxDynamicSharedMemorySize, ATTN_SMEM);

    // QKV projections (TF32 tensor cores)
    gemm_tf32<<<dim3(HID / 128, SEQ / 128), 256>>>(hs, qw, q, SEQ, HID, HID);
    gemm_tf32<<<dim3(KVHID / 128, SEQ / 128), 256>>>(hs, kw, k, SEQ, KVHID, HID);
    gemm_tf32<<<dim3(KVHID / 128, SEQ / 128), 256>>>(hs, vw, v, SEQ, KVHID, HID);

    // RoPE on Q and K
    rope_kernel<<<dim3(SEQ, NH + NKV), 64>>>(q, k, pos);

    // Attention (global softmax == ring-block softmax + LSE recombine)
    attn_kernel<<<dim3(SEQ / 64, NH), 256, ATTN_SMEM>>>(q, k, v, attn);

    // Output projection
    gemm_tf32<<<dim3(HID / 128, SEQ / 128), 256>>>(attn, ow, out, SEQ, HID, HID);
}

// round 4
// speedup vs baseline: 2.3985x; 1.4086x over previous
#include <cuda_runtime.h>
#include <cuda_bf16.h>
#include <stdint.h>
#include <math.h>

// Problem constants
#define SEQ   2048
#define HID   4096
#define NH    32
#define NKV   8
#define HD    128
#define KVHID 1024   // NKV*HD

// Scratch (device globals; allocation-free rule)
__device__ float g_q[SEQ * HID];      // (s, h, d)
__device__ float g_k[SEQ * KVHID];    // (s, kvh, d)
__device__ float g_v[SEQ * KVHID];
__device__ float g_attn[SEQ * HID];   // attention output before o_proj

// ---------------------------------------------------------------------------
// TF32 helpers
// ---------------------------------------------------------------------------
__device__ __forceinline__ uint32_t f2t(float x) {
    uint32_t u;
    asm("cvt.rna.tf32.f32 %0, %1;" : "=r"(u) : "f"(x));
    return u;
}

__device__ __forceinline__ void mma_tf32(float* c, const uint32_t* a,
                                         const uint32_t* b) {
    asm volatile(
        "mma.sync.aligned.m16n8k8.row.col.f32.tf32.tf32.f32 "
        "{%0,%1,%2,%3}, {%4,%5,%6,%7}, {%8,%9}, {%0,%1,%2,%3};"
        : "+f"(c[0]), "+f"(c[1]), "+f"(c[2]), "+f"(c[3])
        : "r"(a[0]), "r"(a[1]), "r"(a[2]), "r"(a[3]), "r"(b[0]), "r"(b[1]));
}

// ---------------------------------------------------------------------------
// TF32 tensor-core GEMM: C[M,N] = A[M,K] @ W[N,K]^T  (both row-major, K contig)
// (unchanged from round 3 — proven)
// ---------------------------------------------------------------------------
#define LDS_STRIDE 20

__global__ __launch_bounds__(256) void gemm_tf32(const float* __restrict__ A,
                                                 const float* __restrict__ W,
                                                 float* __restrict__ C,
                                                 int M, int N, int K) {
    __shared__ uint32_t As[2][128 * LDS_STRIDE];
    __shared__ uint32_t Bs[2][128 * LDS_STRIDE];

    const int tid  = threadIdx.x;
    const int mb   = blockIdx.y * 128;
    const int nb   = blockIdx.x * 128;
    const int lane = tid & 31;
    const int wid  = tid >> 5;
    const int g    = lane >> 2;
    const int tg   = lane & 3;
    const int wm   = (wid >> 1) * 32;
    const int wn   = (wid & 1) * 64;

    const int lrow0 = tid >> 2;
    const int lkc   = (tid & 3) * 4;

    const float* Ap = A + (size_t)mb * K;
    const float* Wp = W + (size_t)nb * K;

    float acc[2][8][4];
#pragma unroll
    for (int i = 0; i < 2; i++)
#pragma unroll
        for (int j = 0; j < 8; j++)
#pragma unroll
            for (int t = 0; t < 4; t++) acc[i][j][t] = 0.f;

    {
#pragma unroll
        for (int h = 0; h < 2; h++) {
            int row = lrow0 + h * 64;
            float4 a = *(const float4*)(Ap + (size_t)row * K + lkc);
            uint32_t* d = &As[0][row * LDS_STRIDE + lkc];
            d[0] = f2t(a.x); d[1] = f2t(a.y); d[2] = f2t(a.z); d[3] = f2t(a.w);
            float4 b = *(const float4*)(Wp + (size_t)row * K + lkc);
            uint32_t* e = &Bs[0][row * LDS_STRIDE + lkc];
            e[0] = f2t(b.x); e[1] = f2t(b.y); e[2] = f2t(b.z); e[3] = f2t(b.w);
        }
    }
    __syncthreads();

    int buf = 0;
    for (int k0 = 0; k0 < K; k0 += 16) {
        float4 pa[2], pb[2];
        const bool has_next = (k0 + 16) < K;
        if (has_next) {
#pragma unroll
            for (int h = 0; h < 2; h++) {
                int row = lrow0 + h * 64;
                pa[h] = *(const float4*)(Ap + (size_t)row * K + k0 + 16 + lkc);
                pb[h] = *(const float4*)(Wp + (size_t)row * K + k0 + 16 + lkc);
            }
        }

        const uint32_t* asb = As[buf];
        const uint32_t* bsb = Bs[buf];
#pragma unroll
        for (int kk = 0; kk < 16; kk += 8) {
            uint32_t af[2][4], bf[8][2];
#pragma unroll
            for (int i = 0; i < 2; i++) {
                int r = wm + i * 16;
                af[i][0] = asb[(r + g) * LDS_STRIDE + kk + tg];
                af[i][1] = asb[(r + g + 8) * LDS_STRIDE + kk + tg];
                af[i][2] = asb[(r + g) * LDS_STRIDE + kk + tg + 4];
                af[i][3] = asb[(r + g + 8) * LDS_STRIDE + kk + tg + 4];
            }
#pragma unroll
            for (int j = 0; j < 8; j++) {
                int c = wn + j * 8;
                bf[j][0] = bsb[(c + g) * LDS_STRIDE + kk + tg];
                bf[j][1] = bsb[(c + g) * LDS_STRIDE + kk + tg + 4];
            }
#pragma unroll
            for (int i = 0; i < 2; i++)
#pragma unroll
                for (int j = 0; j < 8; j++)
                    mma_tf32(acc[i][j], af[i], bf[j]);
        }

        if (has_next) {
#pragma unroll
            for (int h = 0; h < 2; h++) {
                int row = lrow0 + h * 64;
                uint32_t* d = &As[buf ^ 1][row * LDS_STRIDE + lkc];
                d[0] = f2t(pa[h].x); d[1] = f2t(pa[h].y);
                d[2] = f2t(pa[h].z); d[3] = f2t(pa[h].w);
                uint32_t* e = &Bs[buf ^ 1][row * LDS_STRIDE + lkc];
                e[0] = f2t(pb[h].x); e[1] = f2t(pb[h].y);
                e[2] = f2t(pb[h].z); e[3] = f2t(pb[h].w);
            }
        }
        __syncthreads();
        buf ^= 1;
    }

#pragma unroll
    for (int i = 0; i < 2; i++) {
        int row = mb + wm + i * 16 + g;
#pragma unroll
        for (int j = 0; j < 8; j++) {
            int col = nb + wn + j * 8 + tg * 2;
            *(float2*)(C + (size_t)row * N + col) =
                make_float2(acc[i][j][0], acc[i][j][1]);
            *(float2*)(C + (size_t)(row + 8) * N + col) =
                make_float2(acc[i][j][2], acc[i][j][3]);
        }
    }
}

// ---------------------------------------------------------------------------
// RoPE: applied in-place to g_q (32 heads) and g_k (8 heads).
// ---------------------------------------------------------------------------
__global__ void rope_kernel(float* __restrict__ q, float* __restrict__ k,
                            const int* __restrict__ pos_ids) {
    const int s = blockIdx.x;
    const int h = blockIdx.y;
    const int d = threadIdx.x;  // 0..63

    float* row = (h < NH) ? (q + (size_t)s * HID + h * HD)
                          : (k + (size_t)s * KVHID + (h - NH) * HD);

    const float cexp = 0.20503692556210917f;  // ln(500000)/64
    float inv_freq = expf(-(float)d * cexp);
    float freq = (float)pos_ids[s] * inv_freq;
    float cs, sn;
    sincosf(freq, &sn, &cs);

    float x1 = row[d];
    float x2 = row[d + 64];
    row[d]      = x1 * cs - x2 * sn;
    row[d + 64] = x2 * cs + x1 * sn;
}

// ---------------------------------------------------------------------------
// TF32 mma flash attention.
// 64 queries/CTA x 1 head, 64-key inner tiles, D=128, 512 threads (16 warps).
// QK^T uses Q hi/lo split (2 mmas) -> score error from K rounding only.
// PV plain tf32. Softmax fp32 in smem (unchanged math).
// Smem strides: Q/K = 132 (bank 4g+tg = lane, conflict-free),
//               V = 136 (bank 8tg+g, conflict-free), S/P = 68 (4g+tg).
// ---------------------------------------------------------------------------
#define QK_STRIDE 132
#define V_STRIDE  136
#define S_STRIDE  68
#define ATTN_SMEM ((3 * 64 * QK_STRIDE + 64 * V_STRIDE + 64 * S_STRIDE + 3 * 64) * 4)

__global__ __launch_bounds__(512) void attn_mma(const float* __restrict__ Q,
                                                const float* __restrict__ K,
                                                const float* __restrict__ V,
                                                float* __restrict__ O) {
    extern __shared__ uint32_t sm[];
    uint32_t* Qh = sm;                         // 64 x 132 (tf32 hi)
    uint32_t* Ql = Qh + 64 * QK_STRIDE;        // 64 x 132 (tf32 lo)
    uint32_t* Ks = Ql + 64 * QK_STRIDE;        // 64 x 132 (tf32)
    uint32_t* Vs = Ks + 64 * QK_STRIDE;        // 64 x 136 (tf32)
    float*    Ss = (float*)(Vs + 64 * V_STRIDE); // 64 x 68 (scores -> P)
    float*    ms = Ss + 64 * S_STRIDE;
    float*    ls = ms + 64;
    float*    fct = ls + 64;

    const int tid  = threadIdx.x;
    const int lane = tid & 31;
    const int wid  = tid >> 5;           // 0..15
    const int g    = lane >> 2;          // 0..7
    const int tg   = lane & 3;           // 0..3
    const int m0   = (wid >> 2) * 16;    // query-row group
    const int nS0  = (wid & 3) * 16;     // score-col group (QK)
    const int nO0  = (wid & 3) * 32;     // output-col group (PV)

    const int qt   = blockIdx.x;         // 0..31
    const int head = blockIdx.y;         // 0..31
    const int kvh  = head >> 2;
    const float sm_scale = 0.08838834764831845f;  // 1/sqrt(128)

    // --- load Q tile: scale, hi/lo tf32 split ---
    const float* qp = Q + (size_t)qt * 64 * HID + head * HD;
    for (int i = tid; i < 64 * 32; i += 512) {
        int row = i >> 5, c = (i & 31) * 4;
        float4 x = *(const float4*)(qp + (size_t)row * HID + c);
        float xv[4] = {x.x * sm_scale, x.y * sm_scale, x.z * sm_scale, x.w * sm_scale};
        uint32_t* qh = Qh + row * QK_STRIDE + c;
        uint32_t* ql = Ql + row * QK_STRIDE + c;
#pragma unroll
        for (int j = 0; j < 4; j++) {
            uint32_t hb = f2t(xv[j]);
            qh[j] = hb;
            ql[j] = f2t(xv[j] - __uint_as_float(hb));
        }
    }
    if (tid < 64) { ms[tid] = -1e30f; ls[tid] = 0.f; }

    float accO[4][4];
#pragma unroll
    for (int nt = 0; nt < 4; nt++)
#pragma unroll
        for (int t = 0; t < 4; t++) accO[nt][t] = 0.f;

    const float* kp = K + kvh * HD;
    const float* vp = V + kvh * HD;

    for (int kt = 0; kt < SEQ / 64; kt++) {
        // --- load K, V tiles (tf32 convert at load) ---
        for (int i = tid; i < 64 * 32; i += 512) {
            int row = i >> 5, c = (i & 31) * 4;
            size_t gofs = (size_t)(kt * 64 + row) * KVHID + c;
            float4 kx = *(const float4*)(kp + gofs);
            uint32_t* kd = Ks + row * QK_STRIDE + c;
            kd[0] = f2t(kx.x); kd[1] = f2t(kx.y); kd[2] = f2t(kx.z); kd[3] = f2t(kx.w);
            float4 vx = *(const float4*)(vp + gofs);
            uint32_t* vd = Vs + row * V_STRIDE + c;
            vd[0] = f2t(vx.x); vd[1] = f2t(vx.y); vd[2] = f2t(vx.z); vd[3] = f2t(vx.w);
        }
        __syncthreads();

        // --- S = Q K^T via mma (Q split: hi + lo) ---
        float accS[2][4];
#pragma unroll
        for (int nt = 0; nt < 2; nt++)
#pragma unroll
            for (int t = 0; t < 4; t++) accS[nt][t] = 0.f;

#pragma unroll
        for (int k0 = 0; k0 < 128; k0 += 8) {
            uint32_t ah[4], al[4];
            const int ra = (m0 + g) * QK_STRIDE + k0 + tg;
            const int rb = (m0 + g + 8) * QK_STRIDE + k0 + tg;
            ah[0] = Qh[ra];     ah[1] = Qh[rb];
            ah[2] = Qh[ra + 4]; ah[3] = Qh[rb + 4];
            al[0] = Ql[ra];     al[1] = Ql[rb];
            al[2] = Ql[ra + 4]; al[3] = Ql[rb + 4];
#pragma unroll
            for (int nt = 0; nt < 2; nt++) {
                uint32_t bb[2];
                const int kb = (nS0 + nt * 8 + g) * QK_STRIDE + k0 + tg;
                bb[0] = Ks[kb];
                bb[1] = Ks[kb + 4];
                mma_tf32(accS[nt], ah, bb);
                mma_tf32(accS[nt], al, bb);
            }
        }

        // --- write scores to smem ---
#pragma unroll
        for (int nt = 0; nt < 2; nt++) {
            int col = nS0 + nt * 8 + tg * 2;
            *(float2*)(Ss + (m0 + g) * S_STRIDE + col) =
                make_float2(accS[nt][0], accS[nt][1]);
            *(float2*)(Ss + (m0 + g + 8) * S_STRIDE + col) =
                make_float2(accS[nt][2], accS[nt][3]);
        }
        __syncthreads();

        // --- online softmax (8 lanes per row, 8 cols each) ---
        {
            int row = tid >> 3, qq = tid & 7;
            float* srow = Ss + row * S_STRIDE + qq * 8;
            float mx = srow[0];
#pragma unroll
            for (int j = 1; j < 8; j++) mx = fmaxf(mx, srow[j]);
            mx = fmaxf(mx, __shfl_xor_sync(0xffffffffu, mx, 1));
            mx = fmaxf(mx, __shfl_xor_sync(0xffffffffu, mx, 2));
            mx = fmaxf(mx, __shfl_xor_sync(0xffffffffu, mx, 4));
            float m_old = ms[row];
            float m_new = fmaxf(m_old, mx);
            float sum = 0.f;
#pragma unroll
            for (int j = 0; j < 8; j++) {
                float p = __expf(srow[j] - m_new);
                srow[j] = p;
                sum += p;
            }
            sum += __shfl_xor_sync(0xffffffffu, sum, 1);
            sum += __shfl_xor_sync(0xffffffffu, sum, 2);
            sum += __shfl_xor_sync(0xffffffffu, sum, 4);
            if (qq == 0) {
                float f = __expf(m_old - m_new);
                fct[row] = f;
                ls[row] = ls[row] * f + sum;
                ms[row] = m_new;
            }
        }
        __syncthreads();

        // --- rescale accumulators, O += P V via mma ---
        {
            float f0 = fct[m0 + g];
            float f1 = fct[m0 + g + 8];
#pragma unroll
            for (int nt = 0; nt < 4; nt++) {
                accO[nt][0] *= f0; accO[nt][1] *= f0;
                accO[nt][2] *= f1; accO[nt][3] *= f1;
            }
        }
#pragma unroll
        for (int k0 = 0; k0 < 64; k0 += 8) {
            uint32_t pa[4];
            pa[0] = f2t(Ss[(m0 + g) * S_STRIDE + k0 + tg]);
            pa[1] = f2t(Ss[(m0 + g + 8) * S_STRIDE + k0 + tg]);
            pa[2] = f2t(Ss[(m0 + g) * S_STRIDE + k0 + tg + 4]);
            pa[3] = f2t(Ss[(m0 + g + 8) * S_STRIDE + k0 + tg + 4]);
#pragma unroll
            for (int nt = 0; nt < 4; nt++) {
                uint32_t vb[2];
                int col = nO0 + nt * 8 + g;
                vb[0] = Vs[(k0 + tg) * V_STRIDE + col];
                vb[1] = Vs[(k0 + tg + 4) * V_STRIDE + col];
                mma_tf32(accO[nt], pa, vb);
            }
        }
        __syncthreads();
    }

    // --- finalize: divide by l, write out ---
    float inv0 = 1.0f / ls[m0 + g];
    float inv1 = 1.0f / ls[m0 + g + 8];
    float* op = O + (size_t)qt * 64 * HID + head * HD;
#pragma unroll
    for (int nt = 0; nt < 4; nt++) {
        int col = nO0 + nt * 8 + tg * 2;
        *(float2*)(op + (size_t)(m0 + g) * HID + col) =
            make_float2(accO[nt][0] * inv0, accO[nt][1] * inv0);
        *(float2*)(op + (size_t)(m0 + g + 8) * HID + col) =
            make_float2(accO[nt][2] * inv1, accO[nt][3] * inv1);
    }
}

// ---------------------------------------------------------------------------
// Launch
// ---------------------------------------------------------------------------
extern "C" void kernel_launch(void* const* d_in, const int* in_sizes, int n_in,
                              void* d_out, int out_size) {
    (void)in_sizes; (void)n_in; (void)out_size;
    const float* hs  = (const float*)d_in[0];
    const int*   pos = (const int*)d_in[1];
    const float* qw  = (const float*)d_in[2];
    const float* kw  = (const float*)d_in[3];
    const float* vw  = (const float*)d_in[4];
    const float* ow  = (const float*)d_in[5];
    float* out = (float*)d_out;

    float *q, *k, *v, *attn;
    cudaGetSymbolAddress((void**)&q, g_q);
    cudaGetSymbolAddress((void**)&k, g_k);
    cudaGetSymbolAddress((void**)&v, g_v);
    cudaGetSymbolAddress((void**)&attn, g_attn);

    cudaFuncSetAttribute(attn_mma,
                         cudaFuncAttributeMaxDynamicSharedMemorySize, ATTN_SMEM);

    // QKV projections (TF32 tensor cores)
    gemm_tf32<<<dim3(HID / 128, SEQ / 128), 256>>>(hs, qw, q, SEQ, HID, HID);
    gemm_tf32<<<dim3(KVHID / 128, SEQ / 128), 256>>>(hs, kw, k, SEQ, KVHID, HID);
    gemm_tf32<<<dim3(KVHID / 128, SEQ / 128), 256>>>(hs, vw, v, SEQ, KVHID, HID);

    // RoPE on Q and K
    rope_kernel<<<dim3(SEQ, NH + NKV), 64>>>(q, k, pos);

    // Attention (global softmax == ring-block softmax + LSE recombine)
    attn_mma<<<dim3(SEQ / 64, NH), 512, ATTN_SMEM>>>(q, k, v, attn);

    // Output projection
    gemm_tf32<<<dim3(HID / 128, SEQ / 128), 256>>>(attn, ow, out, SEQ, HID, HID);
}

// round 5
// speedup vs baseline: 2.6842x; 1.1191x over previous
#include <cuda_runtime.h>
#include <cuda_bf16.h>
#include <stdint.h>
#include <math.h>

// Problem constants
#define SEQ   2048
#define HID   4096
#define NH    32
#define NKV   8
#define HD    128
#define KVHID 1024   // NKV*HD

// Scratch (device globals; allocation-free rule)
__device__ float g_q[SEQ * HID];      // (s, h, d)
__device__ float g_k[SEQ * KVHID];    // (s, kvh, d)
__device__ float g_v[SEQ * KVHID];
__device__ float g_attn[SEQ * HID];   // attention output before o_proj

// ---------------------------------------------------------------------------
// TF32 helpers
// ---------------------------------------------------------------------------
__device__ __forceinline__ uint32_t f2t(float x) {
    uint32_t u;
    asm("cvt.rna.tf32.f32 %0, %1;" : "=r"(u) : "f"(x));
    return u;
}

__device__ __forceinline__ void mma_tf32(float* c, const uint32_t* a,
                                         const uint32_t* b) {
    asm volatile(
        "mma.sync.aligned.m16n8k8.row.col.f32.tf32.tf32.f32 "
        "{%0,%1,%2,%3}, {%4,%5,%6,%7}, {%8,%9}, {%0,%1,%2,%3};"
        : "+f"(c[0]), "+f"(c[1]), "+f"(c[2]), "+f"(c[3])
        : "r"(a[0]), "r"(a[1]), "r"(a[2]), "r"(a[3]), "r"(b[0]), "r"(b[1]));
}

__device__ __forceinline__ void cp16(uint32_t saddr, const void* gaddr) {
    asm volatile("cp.async.cg.shared.global [%0], [%1], 16;"
                 :: "r"(saddr), "l"(gaddr));
}
__device__ __forceinline__ void cp_commit() {
    asm volatile("cp.async.commit_group;");
}
template <int N>
__device__ __forceinline__ void cp_wait() {
    asm volatile("cp.async.wait_group %0;" :: "n"(N));
}

// ---------------------------------------------------------------------------
// TF32 tensor-core GEMM v2: C[M,N] = A[M,K] @ W[N,K]^T (row-major, K contig).
// CTA tile 128x128, BK=32, 256 threads, 8 warps 4(m) x 2(n), warp tile 32x64.
// cp.async 3-stage ring of raw fp32 tiles; cvt.rna applied after fragment LDS.
// Smem stride 36 words (mod 32 = 4): fragment LDS bank = (4g+tg) -> 32
// distinct banks, conflict-free; rows 16B-aligned for cp.async.
// ---------------------------------------------------------------------------
#define GSTRIDE 36
#define GSTAGES 3
#define GEMM_SMEM (GSTAGES * 2 * 128 * GSTRIDE * 4)

__global__ __launch_bounds__(256, 2) void gemm_tf32(const float* __restrict__ A,
                                                    const float* __restrict__ W,
                                                    float* __restrict__ C,
                                                    int M, int N, int K) {
    extern __shared__ float gsm[];
    float* As = gsm;                            // [GSTAGES][128][36]
    float* Bs = gsm + GSTAGES * 128 * GSTRIDE;

    const int tid  = threadIdx.x;
    const int mb   = blockIdx.y * 128;
    const int nb   = blockIdx.x * 128;
    const int lane = tid & 31;
    const int wid  = tid >> 5;
    const int g    = lane >> 2;
    const int tg   = lane & 3;
    const int wm   = (wid >> 1) * 32;
    const int wn   = (wid & 1) * 64;

    const float* Ap = A + (size_t)mb * K;
    const float* Wp = W + (size_t)nb * K;

    const uint32_t sA = (uint32_t)__cvta_generic_to_shared(As);
    const uint32_t sB = (uint32_t)__cvta_generic_to_shared(Bs);

    // cp.async mapping: 1024 float4 per 128x32 tile, 4 per thread per matrix.
    // idx = tid + 256*j : row = idx>>3, 16B chunk = idx&7.
    auto issue_stage = [&](int stage, int k0) {
        const uint32_t so = (uint32_t)(stage * 128 * GSTRIDE * 4);
#pragma unroll
        for (int j = 0; j < 4; j++) {
            int idx = tid + 256 * j;
            int row = idx >> 3, ch = (idx & 7) * 4;
            uint32_t sofs = so + (uint32_t)(row * GSTRIDE + ch) * 4;
            cp16(sA + sofs, Ap + (size_t)row * K + k0 + ch);
            cp16(sB + sofs, Wp + (size_t)row * K + k0 + ch);
        }
    };

    float acc[2][8][4];
#pragma unroll
    for (int i = 0; i < 2; i++)
#pragma unroll
        for (int j = 0; j < 8; j++)
#pragma unroll
            for (int t = 0; t < 4; t++) acc[i][j][t] = 0.f;

    const int NIT = K / 32;
    issue_stage(0, 0);  cp_commit();
    issue_stage(1, 32); cp_commit();
    cp_wait<1>();
    __syncthreads();

    for (int it = 0; it < NIT; it++) {
        const int s = it % GSTAGES;
        const float* as = As + s * 128 * GSTRIDE;
        const float* bs = Bs + s * 128 * GSTRIDE;

#pragma unroll
        for (int kk = 0; kk < 32; kk += 8) {
            uint32_t af[2][4], bf[8][2];
#pragma unroll
            for (int i = 0; i < 2; i++) {
                const float* ar = as + (wm + i * 16 + g) * GSTRIDE + kk + tg;
                af[i][0] = f2t(ar[0]);
                af[i][1] = f2t(ar[8 * GSTRIDE]);
                af[i][2] = f2t(ar[4]);
                af[i][3] = f2t(ar[8 * GSTRIDE + 4]);
            }
#pragma unroll
            for (int j = 0; j < 8; j++) {
                const float* br = bs + (wn + j * 8 + g) * GSTRIDE + kk + tg;
                bf[j][0] = f2t(br[0]);
                bf[j][1] = f2t(br[4]);
            }
#pragma unroll
            for (int i = 0; i < 2; i++)
#pragma unroll
                for (int j = 0; j < 8; j++)
                    mma_tf32(acc[i][j], af[i], bf[j]);
        }

        if (it + 2 < NIT) issue_stage((it + 2) % GSTAGES, (it + 2) * 32);
        cp_commit();                 // empty commits keep group accounting uniform
        cp_wait<1>();
        __syncthreads();
    }

    // epilogue: c0,c1 contiguous -> float2 stores
#pragma unroll
    for (int i = 0; i < 2; i++) {
        int row = mb + wm + i * 16 + g;
#pragma unroll
        for (int j = 0; j < 8; j++) {
            int col = nb + wn + j * 8 + tg * 2;
            *(float2*)(C + (size_t)row * N + col) =
                make_float2(acc[i][j][0], acc[i][j][1]);
            *(float2*)(C + (size_t)(row + 8) * N + col) =
                make_float2(acc[i][j][2], acc[i][j][3]);
        }
    }
}

// ---------------------------------------------------------------------------
// RoPE: applied in-place to g_q (32 heads) and g_k (8 heads).
// ---------------------------------------------------------------------------
__global__ void rope_kernel(float* __restrict__ q, float* __restrict__ k,
                            const int* __restrict__ pos_ids) {
    const int s = blockIdx.x;
    const int h = blockIdx.y;
    const int d = threadIdx.x;  // 0..63

    float* row = (h < NH) ? (q + (size_t)s * HID + h * HD)
                          : (k + (size_t)s * KVHID + (h - NH) * HD);

    const float cexp = 0.20503692556210917f;  // ln(500000)/64
    float inv_freq = expf(-(float)d * cexp);
    float freq = (float)pos_ids[s] * inv_freq;
    float cs, sn;
    sincosf(freq, &sn, &cs);

    float x1 = row[d];
    float x2 = row[d + 64];
    row[d]      = x1 * cs - x2 * sn;
    row[d + 64] = x2 * cs + x1 * sn;
}

// ---------------------------------------------------------------------------
// TF32 mma flash attention (unchanged from round 4 — proven).
// ---------------------------------------------------------------------------
#define QK_STRIDE 132
#define V_STRIDE  136
#define S_STRIDE  68
#define ATTN_SMEM ((3 * 64 * QK_STRIDE + 64 * V_STRIDE + 64 * S_STRIDE + 3 * 64) * 4)

__global__ __launch_bounds__(512) void attn_mma(const float* __restrict__ Q,
                                                const float* __restrict__ K,
                                                const float* __restrict__ V,
                                                float* __restrict__ O) {
    extern __shared__ uint32_t sm[];
    uint32_t* Qh = sm;                         // 64 x 132 (tf32 hi)
    uint32_t* Ql = Qh + 64 * QK_STRIDE;        // 64 x 132 (tf32 lo)
    uint32_t* Ks = Ql + 64 * QK_STRIDE;        // 64 x 132 (tf32)
    uint32_t* Vs = Ks + 64 * QK_STRIDE;        // 64 x 136 (tf32)
    float*    Ss = (float*)(Vs + 64 * V_STRIDE); // 64 x 68 (scores -> P)
    float*    ms = Ss + 64 * S_STRIDE;
    float*    ls = ms + 64;
    float*    fct = ls + 64;

    const int tid  = threadIdx.x;
    const int lane = tid & 31;
    const int wid  = tid >> 5;           // 0..15
    const int g    = lane >> 2;          // 0..7
    const int tg   = lane & 3;           // 0..3
    const int m0   = (wid >> 2) * 16;    // query-row group
    const int nS0  = (wid & 3) * 16;     // score-col group (QK)
    const int nO0  = (wid & 3) * 32;     // output-col group (PV)

    const int qt   = blockIdx.x;         // 0..31
    const int head = blockIdx.y;         // 0..31
    const int kvh  = head >> 2;
    const float sm_scale = 0.08838834764831845f;  // 1/sqrt(128)

    // --- load Q tile: scale, hi/lo tf32 split ---
    const float* qp = Q + (size_t)qt * 64 * HID + head * HD;
    for (int i = tid; i < 64 * 32; i += 512) {
        int row = i >> 5, c = (i & 31) * 4;
        float4 x = *(const float4*)(qp + (size_t)row * HID + c);
        float xv[4] = {x.x * sm_scale, x.y * sm_scale, x.z * sm_scale, x.w * sm_scale};
        uint32_t* qh = Qh + row * QK_STRIDE + c;
        uint32_t* ql = Ql + row * QK_STRIDE + c;
#pragma unroll
        for (int j = 0; j < 4; j++) {
            uint32_t hb = f2t(xv[j]);
            qh[j] = hb;
            ql[j] = f2t(xv[j] - __uint_as_float(hb));
        }
    }
    if (tid < 64) { ms[tid] = -1e30f; ls[tid] = 0.f; }

    float accO[4][4];
#pragma unroll
    for (int nt = 0; nt < 4; nt++)
#pragma unroll
        for (int t = 0; t < 4; t++) accO[nt][t] = 0.f;

    const float* kp = K + kvh * HD;
    const float* vp = V + kvh * HD;

    for (int kt = 0; kt < SEQ / 64; kt++) {
        // --- load K, V tiles (tf32 convert at load) ---
        for (int i = tid; i < 64 * 32; i += 512) {
            int row = i >> 5, c = (i & 31) * 4;
            size_t gofs = (size_t)(kt * 64 + row) * KVHID + c;
            float4 kx = *(const float4*)(kp + gofs);
            uint32_t* kd = Ks + row * QK_STRIDE + c;
            kd[0] = f2t(kx.x); kd[1] = f2t(kx.y); kd[2] = f2t(kx.z); kd[3] = f2t(kx.w);
            float4 vx = *(const float4*)(vp + gofs);
            uint32_t* vd = Vs + row * V_STRIDE + c;
            vd[0] = f2t(vx.x); vd[1] = f2t(vx.y); vd[2] = f2t(vx.z); vd[3] = f2t(vx.w);
        }
        __syncthreads();

        // --- S = Q K^T via mma (Q split: hi + lo) ---
        float accS[2][4];
#pragma unroll
        for (int nt = 0; nt < 2; nt++)
#pragma unroll
            for (int t = 0; t < 4; t++) accS[nt][t] = 0.f;

#pragma unroll
        for (int k0 = 0; k0 < 128; k0 += 8) {
            uint32_t ah[4], al[4];
            const int ra = (m0 + g) * QK_STRIDE + k0 + tg;
            const int rb = (m0 + g + 8) * QK_STRIDE + k0 + tg;
            ah[0] = Qh[ra];     ah[1] = Qh[rb];
            ah[2] = Qh[ra + 4]; ah[3] = Qh[rb + 4];
            al[0] = Ql[ra];     al[1] = Ql[rb];
            al[2] = Ql[ra + 4]; al[3] = Ql[rb + 4];
#pragma unroll
            for (int nt = 0; nt < 2; nt++) {
                uint32_t bb[2];
                const int kb = (nS0 + nt * 8 + g) * QK_STRIDE + k0 + tg;
                bb[0] = Ks[kb];
                bb[1] = Ks[kb + 4];
                mma_tf32(accS[nt], ah, bb);
                mma_tf32(accS[nt], al, bb);
            }
        }

        // --- write scores to smem ---
#pragma unroll
        for (int nt = 0; nt < 2; nt++) {
            int col = nS0 + nt * 8 + tg * 2;
            *(float2*)(Ss + (m0 + g) * S_STRIDE + col) =
                make_float2(accS[nt][0], accS[nt][1]);
            *(float2*)(Ss + (m0 + g + 8) * S_STRIDE + col) =
                make_float2(accS[nt][2], accS[nt][3]);
        }
        __syncthreads();

        // --- online softmax (8 lanes per row, 8 cols each) ---
        {
            int row = tid >> 3, qq = tid & 7;
            float* srow = Ss + row * S_STRIDE + qq * 8;
            float mx = srow[0];
#pragma unroll
            for (int j = 1; j < 8; j++) mx = fmaxf(mx, srow[j]);
            mx = fmaxf(mx, __shfl_xor_sync(0xffffffffu, mx, 1));
            mx = fmaxf(mx, __shfl_xor_sync(0xffffffffu, mx, 2));
            mx = fmaxf(mx, __shfl_xor_sync(0xffffffffu, mx, 4));
            float m_old = ms[row];
            float m_new = fmaxf(m_old, mx);
            float sum = 0.f;
#pragma unroll
            for (int j = 0; j < 8; j++) {
                float p = __expf(srow[j] - m_new);
                srow[j] = p;
                sum += p;
            }
            sum += __shfl_xor_sync(0xffffffffu, sum, 1);
            sum += __shfl_xor_sync(0xffffffffu, sum, 2);
            sum += __shfl_xor_sync(0xffffffffu, sum, 4);
            if (qq == 0) {
                float f = __expf(m_old - m_new);
                fct[row] = f;
                ls[row] = ls[row] * f + sum;
                ms[row] = m_new;
            }
        }
        __syncthreads();

        // --- rescale accumulators, O += P V via mma ---
        {
            float f0 = fct[m0 + g];
            float f1 = fct[m0 + g + 8];
#pragma unroll
            for (int nt = 0; nt < 4; nt++) {
                accO[nt][0] *= f0; accO[nt][1] *= f0;
                accO[nt][2] *= f1; accO[nt][3] *= f1;
            }
        }
#pragma unroll
        for (int k0 = 0; k0 < 64; k0 += 8) {
            uint32_t pa[4];
            pa[0] = f2t(Ss[(m0 + g) * S_STRIDE + k0 + tg]);
            pa[1] = f2t(Ss[(m0 + g + 8) * S_STRIDE + k0 + tg]);
            pa[2] = f2t(Ss[(m0 + g) * S_STRIDE + k0 + tg + 4]);
            pa[3] = f2t(Ss[(m0 + g + 8) * S_STRIDE + k0 + tg + 4]);
#pragma unroll
            for (int nt = 0; nt < 4; nt++) {
                uint32_t vb[2];
                int col = nO0 + nt * 8 + g;
                vb[0] = Vs[(k0 + tg) * V_STRIDE + col];
                vb[1] = Vs[(k0 + tg + 4) * V_STRIDE + col];
                mma_tf32(accO[nt], pa, vb);
            }
        }
        __syncthreads();
    }

    // --- finalize: divide by l, write out ---
    float inv0 = 1.0f / ls[m0 + g];
    float inv1 = 1.0f / ls[m0 + g + 8];
    float* op = O + (size_t)qt * 64 * HID + head * HD;
#pragma unroll
    for (int nt = 0; nt < 4; nt++) {
        int col = nO0 + nt * 8 + tg * 2;
        *(float2*)(op + (size_t)(m0 + g) * HID + col) =
            make_float2(accO[nt][0] * inv0, accO[nt][1] * inv0);
        *(float2*)(op + (size_t)(m0 + g + 8) * HID + col) =
            make_float2(accO[nt][2] * inv1, accO[nt][3] * inv1);
    }
}

// ---------------------------------------------------------------------------
// Launch
// ---------------------------------------------------------------------------
extern "C" void kernel_launch(void* const* d_in, const int* in_sizes, int n_in,
                              void* d_out, int out_size) {
    (void)in_sizes; (void)n_in; (void)out_size;
    const float* hs  = (const float*)d_in[0];
    const int*   pos = (const int*)d_in[1];
    const float* qw  = (const float*)d_in[2];
    const float* kw  = (const float*)d_in[3];
    const float* vw  = (const float*)d_in[4];
    const float* ow  = (const float*)d_in[5];
    float* out = (float*)d_out;

    float *q, *k, *v, *attn;
    cudaGetSymbolAddress((void**)&q, g_q);
    cudaGetSymbolAddress((void**)&k, g_k);
    cudaGetSymbolAddress((void**)&v, g_v);
    cudaGetSymbolAddress((void**)&attn, g_attn);

    cudaFuncSetAttribute(gemm_tf32,
                         cudaFuncAttributeMaxDynamicSharedMemorySize, GEMM_SMEM);
    cudaFuncSetAttribute(attn_mma,
                         cudaFuncAttributeMaxDynamicSharedMemorySize, ATTN_SMEM);

    // QKV projections (TF32 tensor cores, cp.async pipelined)
    gemm_tf32<<<dim3(HID / 128, SEQ / 128), 256, GEMM_SMEM>>>(hs, qw, q, SEQ, HID, HID);
    gemm_tf32<<<dim3(KVHID / 128, SEQ / 128), 256, GEMM_SMEM>>>(hs, kw, k, SEQ, KVHID, HID);
    gemm_tf32<<<dim3(KVHID / 128, SEQ / 128), 256, GEMM_SMEM>>>(hs, vw, v, SEQ, KVHID, HID);

    // RoPE on Q and K
    rope_kernel<<<dim3(SEQ, NH + NKV), 64>>>(q, k, pos);

    // Attention (global softmax == ring-block softmax + LSE recombine)
    attn_mma<<<dim3(SEQ / 64, NH), 512, ATTN_SMEM>>>(q, k, v, attn);

    // Output projection
    gemm_tf32<<<dim3(HID / 128, SEQ / 128), 256, GEMM_SMEM>>>(attn, ow, out, SEQ, HID, HID);
}

// round 6
// speedup vs baseline: 2.9452x; 1.0972x over previous
#include <cuda_runtime.h>
#include <cuda_bf16.h>
#include <stdint.h>
#include <math.h>

// Problem constants
#define SEQ   2048
#define HID   4096
#define NH    32
#define NKV   8
#define HD    128
#define KVHID 1024   // NKV*HD

// Scratch (device globals; allocation-free rule)
__device__ float g_q[SEQ * HID];      // (s, h, d)
__device__ float g_k[SEQ * KVHID];    // (s, kvh, d)
__device__ float g_v[SEQ * KVHID];
__device__ float g_attn[SEQ * HID];   // attention output (tf32-rounded)

// Pre-truncated (tf32-representable fp32) copies of inputs
__device__ float g_hst[SEQ * HID];
__device__ float g_qwt[HID * HID];
__device__ float g_kwt[KVHID * HID];
__device__ float g_vwt[KVHID * HID];
__device__ float g_owt[HID * HID];

// ---------------------------------------------------------------------------
// TF32 helpers
// ---------------------------------------------------------------------------
__device__ __forceinline__ uint32_t f2t(float x) {
    uint32_t u;
    asm("cvt.rna.tf32.f32 %0, %1;" : "=r"(u) : "f"(x));
    return u;
}

__device__ __forceinline__ void mma_tf32(float* c, const uint32_t* a,
                                         const uint32_t* b) {
    asm volatile(
        "mma.sync.aligned.m16n8k8.row.col.f32.tf32.tf32.f32 "
        "{%0,%1,%2,%3}, {%4,%5,%6,%7}, {%8,%9}, {%0,%1,%2,%3};"
        : "+f"(c[0]), "+f"(c[1]), "+f"(c[2]), "+f"(c[3])
        : "r"(a[0]), "r"(a[1]), "r"(a[2]), "r"(a[3]), "r"(b[0]), "r"(b[1]));
}

__device__ __forceinline__ void cp16(uint32_t saddr, const void* gaddr) {
    asm volatile("cp.async.cg.shared.global [%0], [%1], 16;"
                 :: "r"(saddr), "l"(gaddr));
}
__device__ __forceinline__ void cp_commit() {
    asm volatile("cp.async.commit_group;");
}
template <int N>
__device__ __forceinline__ void cp_wait() {
    asm volatile("cp.async.wait_group %0;" :: "n"(N));
}

// ---------------------------------------------------------------------------
// Elementwise tf32 pre-truncation: out[i] = round_tf32(in[i]).
// Idempotent; keeps GEMM hot loops conversion-free.
// ---------------------------------------------------------------------------
__global__ __launch_bounds__(256) void trunc_tf32(const float* __restrict__ in,
                                                  float* __restrict__ out,
                                                  int n4) {
    int i = blockIdx.x * 256 + threadIdx.x;
    if (i < n4) {
        float4 x = ((const float4*)in)[i];
        x.x = __uint_as_float(f2t(x.x));
        x.y = __uint_as_float(f2t(x.y));
        x.z = __uint_as_float(f2t(x.z));
        x.w = __uint_as_float(f2t(x.w));
        ((float4*)out)[i] = x;
    }
}

// ---------------------------------------------------------------------------
// TF32 tensor-core GEMM v3: C[M,N] = A[M,K] @ W[N,K]^T (row-major, K contig).
// Inputs must already be tf32-representable. No cvt in mainloop.
// CTA tile 128x128, BK=32, 256 threads, 8 warps 4(m) x 2(n), warp tile 32x64.
// cp.async 3-stage ring. Smem stride 36 words (mod 32 = 4): fragment LDS bank
// = (4g+tg) -> 32 distinct banks, conflict-free; rows 16B-aligned.
// ---------------------------------------------------------------------------
#define GSTRIDE 36
#define GSTAGES 3
#define GEMM_SMEM (GSTAGES * 2 * 128 * GSTRIDE * 4)

__global__ __launch_bounds__(256, 2) void gemm_tf32(const float* __restrict__ A,
                                                    const float* __restrict__ W,
                                                    float* __restrict__ C,
                                                    int M, int N, int K) {
    extern __shared__ float gsm[];
    float* As = gsm;                            // [GSTAGES][128][36]
    float* Bs = gsm + GSTAGES * 128 * GSTRIDE;

    const int tid  = threadIdx.x;
    const int mb   = blockIdx.y * 128;
    const int nb   = blockIdx.x * 128;
    const int lane = tid & 31;
    const int wid  = tid >> 5;
    const int g    = lane >> 2;
    const int tg   = lane & 3;
    const int wm   = (wid >> 1) * 32;
    const int wn   = (wid & 1) * 64;

    const float* Ap = A + (size_t)mb * K;
    const float* Wp = W + (size_t)nb * K;

    const uint32_t sA = (uint32_t)__cvta_generic_to_shared(As);
    const uint32_t sB = (uint32_t)__cvta_generic_to_shared(Bs);

    auto issue_stage = [&](int stage, int k0) {
        const uint32_t so = (uint32_t)(stage * 128 * GSTRIDE * 4);
#pragma unroll
        for (int j = 0; j < 4; j++) {
            int idx = tid + 256 * j;
            int row = idx >> 3, ch = (idx & 7) * 4;
            uint32_t sofs = so + (uint32_t)(row * GSTRIDE + ch) * 4;
            cp16(sA + sofs, Ap + (size_t)row * K + k0 + ch);
            cp16(sB + sofs, Wp + (size_t)row * K + k0 + ch);
        }
    };

    float acc[2][8][4];
#pragma unroll
    for (int i = 0; i < 2; i++)
#pragma unroll
        for (int j = 0; j < 8; j++)
#pragma unroll
            for (int t = 0; t < 4; t++) acc[i][j][t] = 0.f;

    const int NIT = K / 32;
    issue_stage(0, 0);  cp_commit();
    issue_stage(1, 32); cp_commit();
    cp_wait<1>();
    __syncthreads();

    for (int it = 0; it < NIT; it++) {
        const int s = it % GSTAGES;
        const float* as = As + s * 128 * GSTRIDE;
        const float* bs = Bs + s * 128 * GSTRIDE;

#pragma unroll
        for (int kk = 0; kk < 32; kk += 8) {
            uint32_t af[2][4], bf[8][2];
#pragma unroll
            for (int i = 0; i < 2; i++) {
                const float* ar = as + (wm + i * 16 + g) * GSTRIDE + kk + tg;
                af[i][0] = __float_as_uint(ar[0]);
                af[i][1] = __float_as_uint(ar[8 * GSTRIDE]);
                af[i][2] = __float_as_uint(ar[4]);
                af[i][3] = __float_as_uint(ar[8 * GSTRIDE + 4]);
            }
#pragma unroll
            for (int j = 0; j < 8; j++) {
                const float* br = bs + (wn + j * 8 + g) * GSTRIDE + kk + tg;
                bf[j][0] = __float_as_uint(br[0]);
                bf[j][1] = __float_as_uint(br[4]);
            }
#pragma unroll
            for (int i = 0; i < 2; i++)
#pragma unroll
                for (int j = 0; j < 8; j++)
                    mma_tf32(acc[i][j], af[i], bf[j]);
        }

        if (it + 2 < NIT) issue_stage((it + 2) % GSTAGES, (it + 2) * 32);
        cp_commit();
        cp_wait<1>();
        __syncthreads();
    }

#pragma unroll
    for (int i = 0; i < 2; i++) {
        int row = mb + wm + i * 16 + g;
#pragma unroll
        for (int j = 0; j < 8; j++) {
            int col = nb + wn + j * 8 + tg * 2;
            *(float2*)(C + (size_t)row * N + col) =
                make_float2(acc[i][j][0], acc[i][j][1]);
            *(float2*)(C + (size_t)(row + 8) * N + col) =
                make_float2(acc[i][j][2], acc[i][j][3]);
        }
    }
}

// ---------------------------------------------------------------------------
// RoPE: applied in-place to g_q (32 heads) and g_k (8 heads).
// ---------------------------------------------------------------------------
__global__ void rope_kernel(float* __restrict__ q, float* __restrict__ k,
                            const int* __restrict__ pos_ids) {
    const int s = blockIdx.x;
    const int h = blockIdx.y;
    const int d = threadIdx.x;  // 0..63

    float* row = (h < NH) ? (q + (size_t)s * HID + h * HD)
                          : (k + (size_t)s * KVHID + (h - NH) * HD);

    const float cexp = 0.20503692556210917f;  // ln(500000)/64
    float inv_freq = expf(-(float)d * cexp);
    float freq = (float)pos_ids[s] * inv_freq;
    float cs, sn;
    sincosf(freq, &sn, &cs);

    float x1 = row[d];
    float x2 = row[d + 64];
    row[d]      = x1 * cs - x2 * sn;
    row[d + 64] = x2 * cs + x1 * sn;
}

// ---------------------------------------------------------------------------
// TF32 mma flash attention (round-4 proven; epilogue now tf32-rounds output
// so the o_proj GEMM can skip conversion).
// ---------------------------------------------------------------------------
#define QK_STRIDE 132
#define V_STRIDE  136
#define S_STRIDE  68
#define ATTN_SMEM ((3 * 64 * QK_STRIDE + 64 * V_STRIDE + 64 * S_STRIDE + 3 * 64) * 4)

__global__ __launch_bounds__(512) void attn_mma(const float* __restrict__ Q,
                                                const float* __restrict__ K,
                                                const float* __restrict__ V,
                                                float* __restrict__ O) {
    extern __shared__ uint32_t sm[];
    uint32_t* Qh = sm;                         // 64 x 132 (tf32 hi)
    uint32_t* Ql = Qh + 64 * QK_STRIDE;        // 64 x 132 (tf32 lo)
    uint32_t* Ks = Ql + 64 * QK_STRIDE;        // 64 x 132 (tf32)
    uint32_t* Vs = Ks + 64 * QK_STRIDE;        // 64 x 136 (tf32)
    float*    Ss = (float*)(Vs + 64 * V_STRIDE); // 64 x 68 (scores -> P)
    float*    ms = Ss + 64 * S_STRIDE;
    float*    ls = ms + 64;
    float*    fct = ls + 64;

    const int tid  = threadIdx.x;
    const int lane = tid & 31;
    const int wid  = tid >> 5;           // 0..15
    const int g    = lane >> 2;          // 0..7
    const int tg   = lane & 3;           // 0..3
    const int m0   = (wid >> 2) * 16;    // query-row group
    const int nS0  = (wid & 3) * 16;     // score-col group (QK)
    const int nO0  = (wid & 3) * 32;     // output-col group (PV)

    const int qt   = blockIdx.x;         // 0..31
    const int head = blockIdx.y;         // 0..31
    const int kvh  = head >> 2;
    const float sm_scale = 0.08838834764831845f;  // 1/sqrt(128)

    // --- load Q tile: scale, hi/lo tf32 split ---
    const float* qp = Q + (size_t)qt * 64 * HID + head * HD;
    for (int i = tid; i < 64 * 32; i += 512) {
        int row = i >> 5, c = (i & 31) * 4;
        float4 x = *(const float4*)(qp + (size_t)row * HID + c);
        float xv[4] = {x.x * sm_scale, x.y * sm_scale, x.z * sm_scale, x.w * sm_scale};
        uint32_t* qh = Qh + row * QK_STRIDE + c;
        uint32_t* ql = Ql + row * QK_STRIDE + c;
#pragma unroll
        for (int j = 0; j < 4; j++) {
            uint32_t hb = f2t(xv[j]);
            qh[j] = hb;
            ql[j] = f2t(xv[j] - __uint_as_float(hb));
        }
    }
    if (tid < 64) { ms[tid] = -1e30f; ls[tid] = 0.f; }

    float accO[4][4];
#pragma unroll
    for (int nt = 0; nt < 4; nt++)
#pragma unroll
        for (int t = 0; t < 4; t++) accO[nt][t] = 0.f;

    const float* kp = K + kvh * HD;
    const float* vp = V + kvh * HD;

    for (int kt = 0; kt < SEQ / 64; kt++) {
        // --- load K, V tiles (tf32 convert at load) ---
        for (int i = tid; i < 64 * 32; i += 512) {
            int row = i >> 5, c = (i & 31) * 4;
            size_t gofs = (size_t)(kt * 64 + row) * KVHID + c;
            float4 kx = *(const float4*)(kp + gofs);
            uint32_t* kd = Ks + row * QK_STRIDE + c;
            kd[0] = f2t(kx.x); kd[1] = f2t(kx.y); kd[2] = f2t(kx.z); kd[3] = f2t(kx.w);
            float4 vx = *(const float4*)(vp + gofs);
            uint32_t* vd = Vs + row * V_STRIDE + c;
            vd[0] = f2t(vx.x); vd[1] = f2t(vx.y); vd[2] = f2t(vx.z); vd[3] = f2t(vx.w);
        }
        __syncthreads();

        // --- S = Q K^T via mma (Q split: hi + lo) ---
        float accS[2][4];
#pragma unroll
        for (int nt = 0; nt < 2; nt++)
#pragma unroll
            for (int t = 0; t < 4; t++) accS[nt][t] = 0.f;

#pragma unroll
        for (int k0 = 0; k0 < 128; k0 += 8) {
            uint32_t ah[4], al[4];
            const int ra = (m0 + g) * QK_STRIDE + k0 + tg;
            const int rb = (m0 + g + 8) * QK_STRIDE + k0 + tg;
            ah[0] = Qh[ra];     ah[1] = Qh[rb];
            ah[2] = Qh[ra + 4]; ah[3] = Qh[rb + 4];
            al[0] = Ql[ra];     al[1] = Ql[rb];
            al[2] = Ql[ra + 4]; al[3] = Ql[rb + 4];
#pragma unroll
            for (int nt = 0; nt < 2; nt++) {
                uint32_t bb[2];
                const int kb = (nS0 + nt * 8 + g) * QK_STRIDE + k0 + tg;
                bb[0] = Ks[kb];
                bb[1] = Ks[kb + 4];
                mma_tf32(accS[nt], ah, bb);
                mma_tf32(accS[nt], al, bb);
            }
        }

        // --- write scores to smem ---
#pragma unroll
        for (int nt = 0; nt < 2; nt++) {
            int col = nS0 + nt * 8 + tg * 2;
            *(float2*)(Ss + (m0 + g) * S_STRIDE + col) =
                make_float2(accS[nt][0], accS[nt][1]);
            *(float2*)(Ss + (m0 + g + 8) * S_STRIDE + col) =
                make_float2(accS[nt][2], accS[nt][3]);
        }
        __syncthreads();

        // --- online softmax (8 lanes per row, 8 cols each) ---
        {
            int row = tid >> 3, qq = tid & 7;
            float* srow = Ss + row * S_STRIDE + qq * 8;
            float mx = srow[0];
#pragma unroll
            for (int j = 1; j < 8; j++) mx = fmaxf(mx, srow[j]);
            mx = fmaxf(mx, __shfl_xor_sync(0xffffffffu, mx, 1));
            mx = fmaxf(mx, __shfl_xor_sync(0xffffffffu, mx, 2));
            mx = fmaxf(mx, __shfl_xor_sync(0xffffffffu, mx, 4));
            float m_old = ms[row];
            float m_new = fmaxf(m_old, mx);
            float sum = 0.f;
#pragma unroll
            for (int j = 0; j < 8; j++) {
                float p = __expf(srow[j] - m_new);
                srow[j] = p;
                sum += p;
            }
            sum += __shfl_xor_sync(0xffffffffu, sum, 1);
            sum += __shfl_xor_sync(0xffffffffu, sum, 2);
            sum += __shfl_xor_sync(0xffffffffu, sum, 4);
            if (qq == 0) {
                float f = __expf(m_old - m_new);
                fct[row] = f;
                ls[row] = ls[row] * f + sum;
                ms[row] = m_new;
            }
        }
        __syncthreads();

        // --- rescale accumulators, O += P V via mma ---
        {
            float f0 = fct[m0 + g];
            float f1 = fct[m0 + g + 8];
#pragma unroll
            for (int nt = 0; nt < 4; nt++) {
                accO[nt][0] *= f0; accO[nt][1] *= f0;
                accO[nt][2] *= f1; accO[nt][3] *= f1;
            }
        }
#pragma unroll
        for (int k0 = 0; k0 < 64; k0 += 8) {
            uint32_t pa[4];
            pa[0] = f2t(Ss[(m0 + g) * S_STRIDE + k0 + tg]);
            pa[1] = f2t(Ss[(m0 + g + 8) * S_STRIDE + k0 + tg]);
            pa[2] = f2t(Ss[(m0 + g) * S_STRIDE + k0 + tg + 4]);
            pa[3] = f2t(Ss[(m0 + g + 8) * S_STRIDE + k0 + tg + 4]);
#pragma unroll
            for (int nt = 0; nt < 4; nt++) {
                uint32_t vb[2];
                int col = nO0 + nt * 8 + g;
                vb[0] = Vs[(k0 + tg) * V_STRIDE + col];
                vb[1] = Vs[(k0 + tg + 4) * V_STRIDE + col];
                mma_tf32(accO[nt], pa, vb);
            }
        }
        __syncthreads();
    }

    // --- finalize: divide by l, tf32-round, write out ---
    float inv0 = 1.0f / ls[m0 + g];
    float inv1 = 1.0f / ls[m0 + g + 8];
    float* op = O + (size_t)qt * 64 * HID + head * HD;
#pragma unroll
    for (int nt = 0; nt < 4; nt++) {
        int col = nO0 + nt * 8 + tg * 2;
        *(float2*)(op + (size_t)(m0 + g) * HID + col) =
            make_float2(__uint_as_float(f2t(accO[nt][0] * inv0)),
                        __uint_as_float(f2t(accO[nt][1] * inv0)));
        *(float2*)(op + (size_t)(m0 + g + 8) * HID + col) =
            make_float2(__uint_as_float(f2t(accO[nt][2] * inv1)),
                        __uint_as_float(f2t(accO[nt][3] * inv1)));
    }
}

// ---------------------------------------------------------------------------
// Launch
// ---------------------------------------------------------------------------
extern "C" void kernel_launch(void* const* d_in, const int* in_sizes, int n_in,
                              void* d_out, int out_size) {
    (void)in_sizes; (void)n_in; (void)out_size;
    const float* hs  = (const float*)d_in[0];
    const int*   pos = (const int*)d_in[1];
    const float* qw  = (const float*)d_in[2];
    const float* kw  = (const float*)d_in[3];
    const float* vw  = (const float*)d_in[4];
    const float* ow  = (const float*)d_in[5];
    float* out = (float*)d_out;

    float *q, *k, *v, *attn;
    float *hst, *qwt, *kwt, *vwt, *owt;
    cudaGetSymbolAddress((void**)&q, g_q);
    cudaGetSymbolAddress((void**)&k, g_k);
    cudaGetSymbolAddress((void**)&v, g_v);
    cudaGetSymbolAddress((void**)&attn, g_attn);
    cudaGetSymbolAddress((void**)&hst, g_hst);
    cudaGetSymbolAddress((void**)&qwt, g_qwt);
    cudaGetSymbolAddress((void**)&kwt, g_kwt);
    cudaGetSymbolAddress((void**)&vwt, g_vwt);
    cudaGetSymbolAddress((void**)&owt, g_owt);

    cudaFuncSetAttribute(gemm_tf32,
                         cudaFuncAttributeMaxDynamicSharedMemorySize, GEMM_SMEM);
    cudaFuncSetAttribute(attn_mma,
                         cudaFuncAttributeMaxDynamicSharedMemorySize, ATTN_SMEM);

    // Pre-truncate inputs to tf32 grid (removes cvt from GEMM hot loops)
    trunc_tf32<<<(SEQ * HID / 4 + 255) / 256, 256>>>(hs, hst, SEQ * HID / 4);
    trunc_tf32<<<(HID * HID / 4 + 255) / 256, 256>>>(qw, qwt, HID * HID / 4);
    trunc_tf32<<<(KVHID * HID / 4 + 255) / 256, 256>>>(kw, kwt, KVHID * HID / 4);
    trunc_tf32<<<(KVHID * HID / 4 + 255) / 256, 256>>>(vw, vwt, KVHID * HID / 4);
    trunc_tf32<<<(HID * HID / 4 + 255) / 256, 256>>>(ow, owt, HID * HID / 4);

    // QKV projections (TF32 tensor cores, cp.async pipelined, no in-loop cvt)
    gemm_tf32<<<dim3(HID / 128, SEQ / 128), 256, GEMM_SMEM>>>(hst, qwt, q, SEQ, HID, HID);
    gemm_tf32<<<dim3(KVHID / 128, SEQ / 128), 256, GEMM_SMEM>>>(hst, kwt, k, SEQ, KVHID, HID);
    gemm_tf32<<<dim3(KVHID / 128, SEQ / 128), 256, GEMM_SMEM>>>(hst, vwt, v, SEQ, KVHID, HID);

    // RoPE on Q and K
    rope_kernel<<<dim3(SEQ, NH + NKV), 64>>>(q, k, pos);

    // Attention (global softmax == ring-block softmax + LSE recombine)
    attn_mma<<<dim3(SEQ / 64, NH), 512, ATTN_SMEM>>>(q, k, v, attn);

    // Output projection (attn already tf32-rounded in epilogue)
    gemm_tf32<<<dim3(HID / 128, SEQ / 128), 256, GEMM_SMEM>>>(attn, owt, out, SEQ, HID, HID);
}

// round 7
// speedup vs baseline: 3.2148x; 1.0915x over previous
#include <cuda_runtime.h>
#include <cuda_bf16.h>
#include <stdint.h>
#include <math.h>

// Problem constants
#define SEQ   2048
#define HID   4096
#define NH    32
#define NKV   8
#define HD    128
#define KVHID 1024   // NKV*HD

// Scratch (device globals; allocation-free rule)
__device__ float g_q[SEQ * HID];      // q_proj output (pre-rope)
__device__ float g_k[SEQ * KVHID];    // k_proj output -> roped, tf32-rounded
__device__ float g_v[SEQ * KVHID];    // v_proj output -> tf32-rounded
__device__ float g_qh[SEQ * HID];     // roped, scaled, tf32 hi
__device__ float g_ql[SEQ * HID];     // roped, scaled, tf32 lo
__device__ float g_attn[SEQ * HID];   // attention output (tf32-rounded)

// Pre-truncated (tf32-representable fp32) copies of inputs
__device__ float g_hst[SEQ * HID];
__device__ float g_qwt[HID * HID];
__device__ float g_kwt[KVHID * HID];
__device__ float g_vwt[KVHID * HID];
__device__ float g_owt[HID * HID];

// ---------------------------------------------------------------------------
// TF32 helpers
// ---------------------------------------------------------------------------
__device__ __forceinline__ uint32_t f2t(float x) {
    uint32_t u;
    asm("cvt.rna.tf32.f32 %0, %1;" : "=r"(u) : "f"(x));
    return u;
}

__device__ __forceinline__ void mma_tf32(float* c, const uint32_t* a,
                                         const uint32_t* b) {
    asm volatile(
        "mma.sync.aligned.m16n8k8.row.col.f32.tf32.tf32.f32 "
        "{%0,%1,%2,%3}, {%4,%5,%6,%7}, {%8,%9}, {%0,%1,%2,%3};"
        : "+f"(c[0]), "+f"(c[1]), "+f"(c[2]), "+f"(c[3])
        : "r"(a[0]), "r"(a[1]), "r"(a[2]), "r"(a[3]), "r"(b[0]), "r"(b[1]));
}

__device__ __forceinline__ void cp16(uint32_t saddr, const void* gaddr) {
    asm volatile("cp.async.cg.shared.global [%0], [%1], 16;"
                 :: "r"(saddr), "l"(gaddr));
}
__device__ __forceinline__ void cp_commit() {
    asm volatile("cp.async.commit_group;");
}
template <int N>
__device__ __forceinline__ void cp_wait() {
    asm volatile("cp.async.wait_group %0;" :: "n"(N));
}

// ---------------------------------------------------------------------------
// Elementwise tf32 pre-truncation (in-place safe).
// ---------------------------------------------------------------------------
__global__ __launch_bounds__(256) void trunc_tf32(const float* __restrict__ in,
                                                  float* __restrict__ out,
                                                  int n4) {
    int i = blockIdx.x * 256 + threadIdx.x;
    if (i < n4) {
        float4 x = ((const float4*)in)[i];
        x.x = __uint_as_float(f2t(x.x));
        x.y = __uint_as_float(f2t(x.y));
        x.z = __uint_as_float(f2t(x.z));
        x.w = __uint_as_float(f2t(x.w));
        ((float4*)out)[i] = x;
    }
}

// ---------------------------------------------------------------------------
// TF32 GEMM, 128x128 tile (proven round-5/6 kernel) — used for K/V proj.
// ---------------------------------------------------------------------------
#define GSTRIDE 36
#define GSTAGES 3
#define GEMM_SMEM (GSTAGES * 2 * 128 * GSTRIDE * 4)

__global__ __launch_bounds__(256, 2) void gemm_tf32(const float* __restrict__ A,
                                                    const float* __restrict__ W,
                                                    float* __restrict__ C,
                                                    int M, int N, int K) {
    extern __shared__ float gsm[];
    float* As = gsm;
    float* Bs = gsm + GSTAGES * 128 * GSTRIDE;

    const int tid  = threadIdx.x;
    const int mb   = blockIdx.y * 128;
    const int nb   = blockIdx.x * 128;
    const int lane = tid & 31;
    const int wid  = tid >> 5;
    const int g    = lane >> 2;
    const int tg   = lane & 3;
    const int wm   = (wid >> 1) * 32;
    const int wn   = (wid & 1) * 64;

    const float* Ap = A + (size_t)mb * K;
    const float* Wp = W + (size_t)nb * K;

    const uint32_t sA = (uint32_t)__cvta_generic_to_shared(As);
    const uint32_t sB = (uint32_t)__cvta_generic_to_shared(Bs);

    auto issue_stage = [&](int stage, int k0) {
        const uint32_t so = (uint32_t)(stage * 128 * GSTRIDE * 4);
#pragma unroll
        for (int j = 0; j < 4; j++) {
            int idx = tid + 256 * j;
            int row = idx >> 3, ch = (idx & 7) * 4;
            uint32_t sofs = so + (uint32_t)(row * GSTRIDE + ch) * 4;
            cp16(sA + sofs, Ap + (size_t)row * K + k0 + ch);
            cp16(sB + sofs, Wp + (size_t)row * K + k0 + ch);
        }
    };

    float acc[2][8][4];
#pragma unroll
    for (int i = 0; i < 2; i++)
#pragma unroll
        for (int j = 0; j < 8; j++)
#pragma unroll
            for (int t = 0; t < 4; t++) acc[i][j][t] = 0.f;

    const int NIT = K / 32;
    issue_stage(0, 0);  cp_commit();
    issue_stage(1, 32); cp_commit();
    cp_wait<1>();
    __syncthreads();

    for (int it = 0; it < NIT; it++) {
        const int s = it % GSTAGES;
        const float* as = As + s * 128 * GSTRIDE;
        const float* bs = Bs + s * 128 * GSTRIDE;

#pragma unroll
        for (int kk = 0; kk < 32; kk += 8) {
            uint32_t af[2][4], bf[8][2];
#pragma unroll
            for (int i = 0; i < 2; i++) {
                const float* ar = as + (wm + i * 16 + g) * GSTRIDE + kk + tg;
                af[i][0] = __float_as_uint(ar[0]);
                af[i][1] = __float_as_uint(ar[8 * GSTRIDE]);
                af[i][2] = __float_as_uint(ar[4]);
                af[i][3] = __float_as_uint(ar[8 * GSTRIDE + 4]);
            }
#pragma unroll
            for (int j = 0; j < 8; j++) {
                const float* br = bs + (wn + j * 8 + g) * GSTRIDE + kk + tg;
                bf[j][0] = __float_as_uint(br[0]);
                bf[j][1] = __float_as_uint(br[4]);
            }
#pragma unroll
            for (int i = 0; i < 2; i++)
#pragma unroll
                for (int j = 0; j < 8; j++)
                    mma_tf32(acc[i][j], af[i], bf[j]);
        }

        if (it + 2 < NIT) issue_stage((it + 2) % GSTAGES, (it + 2) * 32);
        cp_commit();
        cp_wait<1>();
        __syncthreads();
    }

#pragma unroll
    for (int i = 0; i < 2; i++) {
        int row = mb + wm + i * 16 + g;
#pragma unroll
        for (int j = 0; j < 8; j++) {
            int col = nb + wn + j * 8 + tg * 2;
            *(float2*)(C + (size_t)row * N + col) =
                make_float2(acc[i][j][0], acc[i][j][1]);
            *(float2*)(C + (size_t)(row + 8) * N + col) =
                make_float2(acc[i][j][2], acc[i][j][3]);
        }
    }
}

// ---------------------------------------------------------------------------
// TF32 GEMM, 256x128 tile — used for q_proj / o_proj (the 2GB-traffic GEMMs).
// 8 warps 4(m) x 2(n), warp tile 64x64 = 4(m16) x 8(n8). LDS/mma drops to 1.0.
// ---------------------------------------------------------------------------
#define GEMM_SMEM_BIG (GSTAGES * (256 + 128) * GSTRIDE * 4)

__global__ __launch_bounds__(256, 1) void gemm_tf32_big(const float* __restrict__ A,
                                                        const float* __restrict__ W,
                                                        float* __restrict__ C,
                                                        int M, int N, int K) {
    extern __shared__ float gsm[];
    float* As = gsm;                             // [3][256][36]
    float* Bs = gsm + GSTAGES * 256 * GSTRIDE;   // [3][128][36]

    const int tid  = threadIdx.x;
    const int mb   = blockIdx.y * 256;
    const int nb   = blockIdx.x * 128;
    const int lane = tid & 31;
    const int wid  = tid >> 5;
    const int g    = lane >> 2;
    const int tg   = lane & 3;
    const int wm   = (wid >> 1) * 64;   // 0,64,128,192
    const int wn   = (wid & 1) * 64;    // 0,64

    const float* Ap = A + (size_t)mb * K;
    const float* Wp = W + (size_t)nb * K;

    const uint32_t sA = (uint32_t)__cvta_generic_to_shared(As);
    const uint32_t sB = (uint32_t)__cvta_generic_to_shared(Bs);

    auto issue_stage = [&](int stage, int k0) {
        const uint32_t soA = (uint32_t)(stage * 256 * GSTRIDE * 4);
        const uint32_t soB = (uint32_t)(stage * 128 * GSTRIDE * 4);
#pragma unroll
        for (int j = 0; j < 8; j++) {           // A: 2048 float4
            int idx = tid + 256 * j;
            int row = idx >> 3, ch = (idx & 7) * 4;
            cp16(sA + soA + (uint32_t)(row * GSTRIDE + ch) * 4,
                 Ap + (size_t)row * K + k0 + ch);
        }
#pragma unroll
        for (int j = 0; j < 4; j++) {           // B: 1024 float4
            int idx = tid + 256 * j;
            int row = idx >> 3, ch = (idx & 7) * 4;
            cp16(sB + soB + (uint32_t)(row * GSTRIDE + ch) * 4,
                 Wp + (size_t)row * K + k0 + ch);
        }
    };

    float acc[4][8][4];
#pragma unroll
    for (int i = 0; i < 4; i++)
#pragma unroll
        for (int j = 0; j < 8; j++)
#pragma unroll
            for (int t = 0; t < 4; t++) acc[i][j][t] = 0.f;

    const int NIT = K / 32;
    issue_stage(0, 0);  cp_commit();
    issue_stage(1, 32); cp_commit();
    cp_wait<1>();
    __syncthreads();

    for (int it = 0; it < NIT; it++) {
        const int s = it % GSTAGES;
        const float* as = As + s * 256 * GSTRIDE;
        const float* bs = Bs + s * 128 * GSTRIDE;

#pragma unroll
        for (int kk = 0; kk < 32; kk += 8) {
            uint32_t af[4][4], bf[8][2];
#pragma unroll
            for (int i = 0; i < 4; i++) {
                const float* ar = as + (wm + i * 16 + g) * GSTRIDE + kk + tg;
                af[i][0] = __float_as_uint(ar[0]);
                af[i][1] = __float_as_uint(ar[8 * GSTRIDE]);
                af[i][2] = __float_as_uint(ar[4]);
                af[i][3] = __float_as_uint(ar[8 * GSTRIDE + 4]);
            }
#pragma unroll
            for (int j = 0; j < 8; j++) {
                const float* br = bs + (wn + j * 8 + g) * GSTRIDE + kk + tg;
                bf[j][0] = __float_as_uint(br[0]);
                bf[j][1] = __float_as_uint(br[4]);
            }
#pragma unroll
            for (int i = 0; i < 4; i++)
#pragma unroll
                for (int j = 0; j < 8; j++)
                    mma_tf32(acc[i][j], af[i], bf[j]);
        }

        if (it + 2 < NIT) issue_stage((it + 2) % GSTAGES, (it + 2) * 32);
        cp_commit();
        cp_wait<1>();
        __syncthreads();
    }

#pragma unroll
    for (int i = 0; i < 4; i++) {
        int row = mb + wm + i * 16 + g;
#pragma unroll
        for (int j = 0; j < 8; j++) {
            int col = nb + wn + j * 8 + tg * 2;
            *(float2*)(C + (size_t)row * N + col) =
                make_float2(acc[i][j][0], acc[i][j][1]);
            *(float2*)(C + (size_t)(row + 8) * N + col) =
                make_float2(acc[i][j][2], acc[i][j][3]);
        }
    }
}

// ---------------------------------------------------------------------------
// RoPE + attention pre-processing.
// q heads: rope -> *sm_scale -> tf32 hi/lo split -> g_qh, g_ql.
// k heads: rope -> tf32 round (in place).
// Identical arithmetic to the round-6 attention loader.
// ---------------------------------------------------------------------------
__global__ void rope_kernel(const float* __restrict__ q, float* __restrict__ k,
                            float* __restrict__ qh, float* __restrict__ ql,
                            const int* __restrict__ pos_ids) {
    const int s = blockIdx.x;
    const int h = blockIdx.y;
    const int d = threadIdx.x;  // 0..63

    const float cexp = 0.20503692556210917f;  // ln(500000)/64
    float inv_freq = expf(-(float)d * cexp);
    float freq = (float)pos_ids[s] * inv_freq;
    float cs, sn;
    sincosf(freq, &sn, &cs);

    if (h < NH) {
        const float sm_scale = 0.08838834764831845f;  // 1/sqrt(128)
        size_t base = (size_t)s * HID + h * HD;
        float x1 = q[base + d];
        float x2 = q[base + d + 64];
        float r1 = (x1 * cs - x2 * sn) * sm_scale;
        float r2 = (x2 * cs + x1 * sn) * sm_scale;
        uint32_t h1 = f2t(r1), h2 = f2t(r2);
        qh[base + d]      = __uint_as_float(h1);
        qh[base + d + 64] = __uint_as_float(h2);
        ql[base + d]      = __uint_as_float(f2t(r1 - __uint_as_float(h1)));
        ql[base + d + 64] = __uint_as_float(f2t(r2 - __uint_as_float(h2)));
    } else {
        size_t base = (size_t)s * KVHID + (h - NH) * HD;
        float x1 = k[base + d];
        float x2 = k[base + d + 64];
        k[base + d]      = __uint_as_float(f2t(x1 * cs - x2 * sn));
        k[base + d + 64] = __uint_as_float(f2t(x2 * cs + x1 * sn));
    }
}

// ---------------------------------------------------------------------------
// TF32 mma flash attention v2: all inputs pre-tf32; loads are pure cp.async.
// K double-buffered (full-iter overlap), V single-buffered (issued post-PV,
// waited post-softmax), Q loaded once. Group FIFO: per iter commit K(t+1)
// early, V(t+1) late; wait<1> drains the right group each time.
// ---------------------------------------------------------------------------
#define QK_STRIDE 132
#define V_STRIDE  136
#define S_STRIDE  68
// words: Qh 8448 + Ql 8448 + K 2*8448 + V 8704 + Ss 4352 + aux 192
#define ATTN_SMEM ((4 * 64 * QK_STRIDE + 64 * V_STRIDE + 64 * S_STRIDE + 3 * 64) * 4)

__global__ __launch_bounds__(512) void attn_mma(const float* __restrict__ Qh_g,
                                                const float* __restrict__ Ql_g,
                                                const float* __restrict__ K,
                                                const float* __restrict__ V,
                                                float* __restrict__ O) {
    extern __shared__ uint32_t sm[];
    uint32_t* Qh = sm;                           // 64 x 132
    uint32_t* Ql = Qh + 64 * QK_STRIDE;          // 64 x 132
    uint32_t* Ks = Ql + 64 * QK_STRIDE;          // 2 stages x 64 x 132
    uint32_t* Vs = Ks + 2 * 64 * QK_STRIDE;      // 64 x 136
    float*    Ss = (float*)(Vs + 64 * V_STRIDE); // 64 x 68
    float*    ms = Ss + 64 * S_STRIDE;
    float*    ls = ms + 64;
    float*    fct = ls + 64;

    const uint32_t sbase = (uint32_t)__cvta_generic_to_shared(sm);
    const uint32_t sQh = sbase;
    const uint32_t sQl = sQh + 64 * QK_STRIDE * 4;
    const uint32_t sK  = sQl + 64 * QK_STRIDE * 4;
    const uint32_t sV  = sK + 2 * 64 * QK_STRIDE * 4;

    const int tid  = threadIdx.x;
    const int lane = tid & 31;
    const int wid  = tid >> 5;           // 0..15
    const int g    = lane >> 2;
    const int tg   = lane & 3;
    const int m0   = (wid >> 2) * 16;
    const int nS0  = (wid & 3) * 16;
    const int nO0  = (wid & 3) * 32;

    const int qt   = blockIdx.x;
    const int head = blockIdx.y;
    const int kvh  = head >> 2;

    const float* qhp = Qh_g + (size_t)qt * 64 * HID + head * HD;
    const float* qlp = Ql_g + (size_t)qt * 64 * HID + head * HD;
    const float* kp  = K + kvh * HD;
    const float* vp  = V + kvh * HD;

    // 64x128-float tile loader: 2048 16B-chunks, 4 per thread.
    auto load_tile = [&](uint32_t sdst, int stride_w, const float* gp, int grs) {
#pragma unroll
        for (int j = 0; j < 4; j++) {
            int idx = tid + 512 * j;
            int row = idx >> 5, ch = (idx & 31) * 4;
            cp16(sdst + (uint32_t)(row * stride_w + ch) * 4,
                 gp + (size_t)row * grs + ch);
        }
    };

    // Preload: Q (group0), K0 (group1), V0 (group2)
    load_tile(sQh, QK_STRIDE, qhp, HID);
    load_tile(sQl, QK_STRIDE, qlp, HID);
    cp_commit();
    load_tile(sK, QK_STRIDE, kp, KVHID);
    cp_commit();
    load_tile(sV, V_STRIDE, vp, KVHID);
    cp_commit();

    if (tid < 64) { ms[tid] = -1e30f; ls[tid] = 0.f; }

    float accO[4][4];
#pragma unroll
    for (int nt = 0; nt < 4; nt++)
#pragma unroll
        for (int t = 0; t < 4; t++) accO[nt][t] = 0.f;

    cp_wait<1>();          // Q + K0 done (V0 may be pending)
    __syncthreads();

    for (int kt = 0; kt < SEQ / 64; kt++) {
        const int kb = kt & 1;
        // issue K(t+1) into other stage (full-iteration overlap)
        if (kt + 1 < SEQ / 64)
            load_tile(sK + (uint32_t)((kb ^ 1) * 64 * QK_STRIDE * 4), QK_STRIDE,
                      kp + (size_t)(kt + 1) * 64 * KVHID, KVHID);
        cp_commit();

        // --- S = Q K^T via mma (Q split: hi + lo) ---
        const uint32_t* ksb = Ks + kb * 64 * QK_STRIDE;
        float accS[2][4];
#pragma unroll
        for (int nt = 0; nt < 2; nt++)
#pragma unroll
            for (int t = 0; t < 4; t++) accS[nt][t] = 0.f;

#pragma unroll
        for (int k0 = 0; k0 < 128; k0 += 8) {
            uint32_t ah[4], al[4];
            const int ra = (m0 + g) * QK_STRIDE + k0 + tg;
            const int rb = (m0 + g + 8) * QK_STRIDE + k0 + tg;
            ah[0] = Qh[ra];     ah[1] = Qh[rb];
            ah[2] = Qh[ra + 4]; ah[3] = Qh[rb + 4];
            al[0] = Ql[ra];     al[1] = Ql[rb];
            al[2] = Ql[ra + 4]; al[3] = Ql[rb + 4];
#pragma unroll
            for (int nt = 0; nt < 2; nt++) {
                uint32_t bb[2];
                const int kb2 = (nS0 + nt * 8 + g) * QK_STRIDE + k0 + tg;
                bb[0] = ksb[kb2];
                bb[1] = ksb[kb2 + 4];
                mma_tf32(accS[nt], ah, bb);
                mma_tf32(accS[nt], al, bb);
            }
        }

#pragma unroll
        for (int nt = 0; nt < 2; nt++) {
            int col = nS0 + nt * 8 + tg * 2;
            *(float2*)(Ss + (m0 + g) * S_STRIDE + col) =
                make_float2(accS[nt][0], accS[nt][1]);
            *(float2*)(Ss + (m0 + g + 8) * S_STRIDE + col) =
                make_float2(accS[nt][2], accS[nt][3]);
        }
        __syncthreads();

        // --- online softmax ---
        {
            int row = tid >> 3, qq = tid & 7;
            float* srow = Ss + row * S_STRIDE + qq * 8;
            float mx = srow[0];
#pragma unroll
            for (int j = 1; j < 8; j++) mx = fmaxf(mx, srow[j]);
            mx = fmaxf(mx, __shfl_xor_sync(0xffffffffu, mx, 1));
            mx = fmaxf(mx, __shfl_xor_sync(0xffffffffu, mx, 2));
            mx = fmaxf(mx, __shfl_xor_sync(0xffffffffu, mx, 4));
            float m_old = ms[row];
            float m_new = fmaxf(m_old, mx);
            float sum = 0.f;
#pragma unroll
            for (int j = 0; j < 8; j++) {
                float p = __expf(srow[j] - m_new);
                srow[j] = p;
                sum += p;
            }
            sum += __shfl_xor_sync(0xffffffffu, sum, 1);
            sum += __shfl_xor_sync(0xffffffffu, sum, 2);
            sum += __shfl_xor_sync(0xffffffffu, sum, 4);
            if (qq == 0) {
                float f = __expf(m_old - m_new);
                fct[row] = f;
                ls[row] = ls[row] * f + sum;
                ms[row] = m_new;
            }
        }
        __syncthreads();

        // --- V(t) guaranteed done here (only K(t+1) may stay pending) ---
        cp_wait<1>();
        __syncthreads();

        // --- rescale accumulators, O += P V via mma ---
        {
            float f0 = fct[m0 + g];
            float f1 = fct[m0 + g + 8];
#pragma unroll
            for (int nt = 0; nt < 4; nt++) {
                accO[nt][0] *= f0; accO[nt][1] *= f0;
                accO[nt][2] *= f1; accO[nt][3] *= f1;
            }
        }
#pragma unroll
        for (int k0 = 0; k0 < 64; k0 += 8) {
            uint32_t pa[4];
            pa[0] = f2t(Ss[(m0 + g) * S_STRIDE + k0 + tg]);
            pa[1] = f2t(Ss[(m0 + g + 8) * S_STRIDE + k0 + tg]);
            pa[2] = f2t(Ss[(m0 + g) * S_STRIDE + k0 + tg + 4]);
            pa[3] = f2t(Ss[(m0 + g + 8) * S_STRIDE + k0 + tg + 4]);
#pragma unroll
            for (int nt = 0; nt < 4; nt++) {
                uint32_t vb[2];
                int col = nO0 + nt * 8 + g;
                vb[0] = Vs[(k0 + tg) * V_STRIDE + col];
                vb[1] = Vs[(k0 + tg + 4) * V_STRIDE + col];
                mma_tf32(accO[nt], pa, vb);
            }
        }
        __syncthreads();   // all PV reads of Vs complete

        // issue V(t+1) into the (now free) single V buffer
        if (kt + 1 < SEQ / 64)
            load_tile(sV, V_STRIDE, vp + (size_t)(kt + 1) * 64 * KVHID, KVHID);
        cp_commit();

        cp_wait<1>();      // K(t+1) done (V(t+1) may stay pending)
        __syncthreads();
    }

    // --- finalize: divide by l, tf32-round, write out ---
    float inv0 = 1.0f / ls[m0 + g];
    float inv1 = 1.0f / ls[m0 + g + 8];
    float* op = O + (size_t)qt * 64 * HID + head * HD;
#pragma unroll
    for (int nt = 0; nt < 4; nt++) {
        int col = nO0 + nt * 8 + tg * 2;
        *(float2*)(op + (size_t)(m0 + g) * HID + col) =
            make_float2(__uint_as_float(f2t(accO[nt][0] * inv0)),
                        __uint_as_float(f2t(accO[nt][1] * inv0)));
        *(float2*)(op + (size_t)(m0 + g + 8) * HID + col) =
            make_float2(__uint_as_float(f2t(accO[nt][2] * inv1)),
                        __uint_as_float(f2t(accO[nt][3] * inv1)));
    }
}

// ---------------------------------------------------------------------------
// Launch
// ---------------------------------------------------------------------------
extern "C" void kernel_launch(void* const* d_in, const int* in_sizes, int n_in,
                              void* d_out, int out_size) {
    (void)in_sizes; (void)n_in; (void)out_size;
    const float* hs  = (const float*)d_in[0];
    const int*   pos = (const int*)d_in[1];
    const float* qw  = (const float*)d_in[2];
    const float* kw  = (const float*)d_in[3];
    const float* vw  = (const float*)d_in[4];
    const float* ow  = (const float*)d_in[5];
    float* out = (float*)d_out;

    float *q, *k, *v, *attn, *qh, *ql;
    float *hst, *qwt, *kwt, *vwt, *owt;
    cudaGetSymbolAddress((void**)&q, g_q);
    cudaGetSymbolAddress((void**)&k, g_k);
    cudaGetSymbolAddress((void**)&v, g_v);
    cudaGetSymbolAddress((void**)&attn, g_attn);
    cudaGetSymbolAddress((void**)&qh, g_qh);
    cudaGetSymbolAddress((void**)&ql, g_ql);
    cudaGetSymbolAddress((void**)&hst, g_hst);
    cudaGetSymbolAddress((void**)&qwt, g_qwt);
    cudaGetSymbolAddress((void**)&kwt, g_kwt);
    cudaGetSymbolAddress((void**)&vwt, g_vwt);
    cudaGetSymbolAddress((void**)&owt, g_owt);

    cudaFuncSetAttribute(gemm_tf32,
                         cudaFuncAttributeMaxDynamicSharedMemorySize, GEMM_SMEM);
    cudaFuncSetAttribute(gemm_tf32_big,
                         cudaFuncAttributeMaxDynamicSharedMemorySize, GEMM_SMEM_BIG);
    cudaFuncSetAttribute(attn_mma,
                         cudaFuncAttributeMaxDynamicSharedMemorySize, ATTN_SMEM);

    // Pre-truncate inputs to the tf32 grid
    trunc_tf32<<<(SEQ * HID / 4 + 255) / 256, 256>>>(hs, hst, SEQ * HID / 4);
    trunc_tf32<<<(HID * HID / 4 + 255) / 256, 256>>>(qw, qwt, HID * HID / 4);
    trunc_tf32<<<(KVHID * HID / 4 + 255) / 256, 256>>>(kw, kwt, KVHID * HID / 4);
    trunc_tf32<<<(KVHID * HID / 4 + 255) / 256, 256>>>(vw, vwt, KVHID * HID / 4);
    trunc_tf32<<<(HID * HID / 4 + 255) / 256, 256>>>(ow, owt, HID * HID / 4);

    // QKV projections
    gemm_tf32_big<<<dim3(HID / 128, SEQ / 256), 256, GEMM_SMEM_BIG>>>(hst, qwt, q, SEQ, HID, HID);
    gemm_tf32<<<dim3(KVHID / 128, SEQ / 128), 256, GEMM_SMEM>>>(hst, kwt, k, SEQ, KVHID, HID);
    gemm_tf32<<<dim3(KVHID / 128, SEQ / 128), 256, GEMM_SMEM>>>(hst, vwt, v, SEQ, KVHID, HID);

    // RoPE (+ scale + hi/lo split for q, tf32 round for k); v gets tf32 round
    rope_kernel<<<dim3(SEQ, NH + NKV), 64>>>(q, k, qh, ql, pos);
    trunc_tf32<<<(SEQ * KVHID / 4 + 255) / 256, 256>>>(v, v, SEQ * KVHID / 4);

    // Attention (pure cp.async pipeline; bit-identical math to round 6)
    attn_mma<<<dim3(SEQ / 64, NH), 512, ATTN_SMEM>>>(qh, ql, k, v, attn);

    // Output projection
    gemm_tf32_big<<<dim3(HID / 128, SEQ / 256), 256, GEMM_SMEM_BIG>>>(attn, owt, out, SEQ, HID, HID);
}

// round 9
// speedup vs baseline: 3.5455x; 1.1029x over previous
#include <cuda_runtime.h>
#include <cuda_bf16.h>
#include <stdint.h>
#include <math.h>

// Problem constants
#define SEQ   2048
#define HID   4096
#define NH    32
#define NKV   8
#define HD    128
#define KVHID 1024      // NKV*HD
#define KVW   2048      // merged k|v row width

// Scratch (device globals; allocation-free rule)
__device__ float g_q[SEQ * HID];       // q_proj output (pre-rope)
__device__ float g_qt[SEQ * HID];      // roped, scaled, tf32-rounded Q
__device__ float g_kv[SEQ * KVW];      // merged [k(1024) | v(1024)] per row
__device__ float g_attn[SEQ * HID];    // attention output (tf32-rounded)

// Pre-truncated (tf32-representable fp32) copies of inputs
__device__ float g_hst[SEQ * HID];
__device__ float g_qwt[HID * HID];
__device__ float g_kvwt[KVW * HID];    // rows 0-1023 = k_proj, 1024-2047 = v_proj
__device__ float g_owt[HID * HID];

// ---------------------------------------------------------------------------
// TF32 / async helpers
// ---------------------------------------------------------------------------
__device__ __forceinline__ uint32_t f2t(float x) {
    uint32_t u;
    asm("cvt.rna.tf32.f32 %0, %1;" : "=r"(u) : "f"(x));
    return u;
}

__device__ __forceinline__ void mma_tf32(float* c, const uint32_t* a,
                                         const uint32_t* b) {
    asm volatile(
        "mma.sync.aligned.m16n8k8.row.col.f32.tf32.tf32.f32 "
        "{%0,%1,%2,%3}, {%4,%5,%6,%7}, {%8,%9}, {%0,%1,%2,%3};"
        : "+f"(c[0]), "+f"(c[1]), "+f"(c[2]), "+f"(c[3])
        : "r"(a[0]), "r"(a[1]), "r"(a[2]), "r"(a[3]), "r"(b[0]), "r"(b[1]));
}

__device__ __forceinline__ void cp16(uint32_t saddr, const void* gaddr) {
    asm volatile("cp.async.cg.shared.global [%0], [%1], 16;"
                 :: "r"(saddr), "l"(gaddr));
}
__device__ __forceinline__ void cp_commit() {
    asm volatile("cp.async.commit_group;");
}
template <int N>
__device__ __forceinline__ void cp_wait() {
    asm volatile("cp.async.wait_group %0;" :: "n"(N));
}

// ---------------------------------------------------------------------------
// Elementwise tf32 pre-truncation (in-place safe).
// ---------------------------------------------------------------------------
__global__ __launch_bounds__(256) void trunc_tf32(const float* __restrict__ in,
                                                  float* __restrict__ out,
                                                  int n4) {
    int i = blockIdx.x * 256 + threadIdx.x;
    if (i < n4) {
        float4 x = ((const float4*)in)[i];
        x.x = __uint_as_float(f2t(x.x));
        x.y = __uint_as_float(f2t(x.y));
        x.z = __uint_as_float(f2t(x.z));
        x.w = __uint_as_float(f2t(x.w));
        ((float4*)out)[i] = x;
    }
}

// ---------------------------------------------------------------------------
// TF32 GEMM core (proven round-5/6 mainloop): one 128x128 tile of
// C[M,N] = A[M,K(=4096)] @ W[N,K]^T, inputs already tf32-representable.
// cp.async 3-stage ring, stride-36 smem (conflict-free fragment LDS).
// ---------------------------------------------------------------------------
#define GSTRIDE 36
#define GSTAGES 3
#define GEMM_SMEM (GSTAGES * 2 * 128 * GSTRIDE * 4)

__device__ __forceinline__ void gemm_tile_128(const float* __restrict__ A,
                                              const float* __restrict__ W,
                                              float* __restrict__ C,
                                              int N, int K,
                                              int mb, int nb, float* gsm) {
    float* As = gsm;
    float* Bs = gsm + GSTAGES * 128 * GSTRIDE;

    const int tid  = threadIdx.x;
    const int lane = tid & 31;
    const int wid  = tid >> 5;
    const int g    = lane >> 2;
    const int tg   = lane & 3;
    const int wm   = (wid >> 1) * 32;
    const int wn   = (wid & 1) * 64;

    const float* Ap = A + (size_t)mb * K;
    const float* Wp = W + (size_t)nb * K;

    const uint32_t sA = (uint32_t)__cvta_generic_to_shared(As);
    const uint32_t sB = (uint32_t)__cvta_generic_to_shared(Bs);

    auto issue_stage = [&](int stage, int k0) {
        const uint32_t so = (uint32_t)(stage * 128 * GSTRIDE * 4);
#pragma unroll
        for (int j = 0; j < 4; j++) {
            int idx = tid + 256 * j;
            int row = idx >> 3, ch = (idx & 7) * 4;
            uint32_t sofs = so + (uint32_t)(row * GSTRIDE + ch) * 4;
            cp16(sA + sofs, Ap + (size_t)row * K + k0 + ch);
            cp16(sB + sofs, Wp + (size_t)row * K + k0 + ch);
        }
    };

    float acc[2][8][4];
#pragma unroll
    for (int i = 0; i < 2; i++)
#pragma unroll
        for (int j = 0; j < 8; j++)
#pragma unroll
            for (int t = 0; t < 4; t++) acc[i][j][t] = 0.f;

    const int NIT = K / 32;
    issue_stage(0, 0);  cp_commit();
    issue_stage(1, 32); cp_commit();
    cp_wait<1>();
    __syncthreads();

    for (int it = 0; it < NIT; it++) {
        const int s = it % GSTAGES;
        const float* as = As + s * 128 * GSTRIDE;
        const float* bs = Bs + s * 128 * GSTRIDE;

#pragma unroll
        for (int kk = 0; kk < 32; kk += 8) {
            uint32_t af[2][4], bf[8][2];
#pragma unroll
            for (int i = 0; i < 2; i++) {
                const float* ar = as + (wm + i * 16 + g) * GSTRIDE + kk + tg;
                af[i][0] = __float_as_uint(ar[0]);
                af[i][1] = __float_as_uint(ar[8 * GSTRIDE]);
                af[i][2] = __float_as_uint(ar[4]);
                af[i][3] = __float_as_uint(ar[8 * GSTRIDE + 4]);
            }
#pragma unroll
            for (int j = 0; j < 8; j++) {
                const float* br = bs + (wn + j * 8 + g) * GSTRIDE + kk + tg;
                bf[j][0] = __float_as_uint(br[0]);
                bf[j][1] = __float_as_uint(br[4]);
            }
#pragma unroll
            for (int i = 0; i < 2; i++)
#pragma unroll
                for (int j = 0; j < 8; j++)
                    mma_tf32(acc[i][j], af[i], bf[j]);
        }

        if (it + 2 < NIT) issue_stage((it + 2) % GSTAGES, (it + 2) * 32);
        cp_commit();
        cp_wait<1>();
        __syncthreads();
    }

#pragma unroll
    for (int i = 0; i < 2; i++) {
        int row = mb + wm + i * 16 + g;
#pragma unroll
        for (int j = 0; j < 8; j++) {
            int col = nb + wn + j * 8 + tg * 2;
            *(float2*)(C + (size_t)row * N + col) =
                make_float2(acc[i][j][0], acc[i][j][1]);
            *(float2*)(C + (size_t)(row + 8) * N + col) =
                make_float2(acc[i][j][2], acc[i][j][3]);
        }
    }
}

// Generic 2D-grid GEMM (o_proj)
__global__ __launch_bounds__(256, 2) void gemm_tf32(const float* __restrict__ A,
                                                    const float* __restrict__ W,
                                                    float* __restrict__ C,
                                                    int M, int N, int K) {
    extern __shared__ float gsm[];
    gemm_tile_128(A, W, C, N, K, blockIdx.y * 128, blockIdx.x * 128, gsm);
}

// Merged QKV projection: linear grid of 768 CTAs.
//   bid <  512 : q part  (C=Cq, N=4096, 16x32 tiles)
//   bid >= 512 : kv part (C=Ckv, N=2048, 16x16 tiles)
__global__ __launch_bounds__(256, 2) void gemm_qkv(const float* __restrict__ A,
                                                   const float* __restrict__ Wq,
                                                   const float* __restrict__ Wkv,
                                                   float* __restrict__ Cq,
                                                   float* __restrict__ Ckv) {
    extern __shared__ float gsm[];
    const int bid = blockIdx.x;
    if (bid < 512) {
        gemm_tile_128(A, Wq, Cq, HID, HID,
                      (bid >> 5) * 128, (bid & 31) * 128, gsm);
    } else {
        const int b2 = bid - 512;
        gemm_tile_128(A, Wkv, Ckv, KVW, HID,
                      (b2 >> 4) * 128, (b2 & 15) * 128, gsm);
    }
}

// ---------------------------------------------------------------------------
// RoPE + attention pre-processing.
//   h <  NH        : q head -> rope, *sm_scale, tf32 round -> g_qt
//   NH <= h < NH+8 : k head (g_kv cols 0-1023) -> rope, tf32 round, in place
//   h >= NH+8      : v head (g_kv cols 1024-2047) -> tf32 round, in place
// ---------------------------------------------------------------------------
__global__ void rope_kernel(const float* __restrict__ q,
                            float* __restrict__ qt,
                            float* __restrict__ kv,
                            const int* __restrict__ pos_ids) {
    const int s = blockIdx.x;
    const int h = blockIdx.y;
    const int d = threadIdx.x;  // 0..63

    if (h >= NH + NKV) {   // v: plain tf32 round
        size_t base = (size_t)s * KVW + KVHID + (h - NH - NKV) * HD;
        kv[base + d]      = __uint_as_float(f2t(kv[base + d]));
        kv[base + d + 64] = __uint_as_float(f2t(kv[base + d + 64]));
        return;
    }

    const float cexp = 0.20503692556210917f;  // ln(500000)/64
    float inv_freq = expf(-(float)d * cexp);
    float freq = (float)pos_ids[s] * inv_freq;
    float cs, sn;
    sincosf(freq, &sn, &cs);

    if (h < NH) {
        const float sm_scale = 0.08838834764831845f;  // 1/sqrt(128)
        size_t base = (size_t)s * HID + h * HD;
        float x1 = q[base + d];
        float x2 = q[base + d + 64];
        qt[base + d]      = __uint_as_float(f2t((x1 * cs - x2 * sn) * sm_scale));
        qt[base + d + 64] = __uint_as_float(f2t((x2 * cs + x1 * sn) * sm_scale));
    } else {
        size_t base = (size_t)s * KVW + (h - NH) * HD;
        float x1 = kv[base + d];
        float x2 = kv[base + d + 64];
        kv[base + d]      = __uint_as_float(f2t(x1 * cs - x2 * sn));
        kv[base + d + 64] = __uint_as_float(f2t(x2 * cs + x1 * sn));
    }
}

// ---------------------------------------------------------------------------
// TF32 mma flash attention v3: single-Q (no hi/lo split), pure cp.async
// loads, K double-buffered, V single-buffered (round-7 proven pipeline).
// K/V live interleaved in g_kv (row stride KVW).
// ---------------------------------------------------------------------------
#define QK_STRIDE 132
#define V_STRIDE  136
#define S_STRIDE  68
// words: Q 8448 + K 2*8448 + V 8704 + Ss 4352 + aux 192
#define ATTN_SMEM ((3 * 64 * QK_STRIDE + 64 * V_STRIDE + 64 * S_STRIDE + 3 * 64) * 4)

__global__ __launch_bounds__(512) void attn_mma(const float* __restrict__ Qt,
                                                const float* __restrict__ KV,
                                                float* __restrict__ O) {
    extern __shared__ uint32_t sm[];
    uint32_t* Qs = sm;                           // 64 x 132
    uint32_t* Ks = Qs + 64 * QK_STRIDE;          // 2 stages x 64 x 132
    uint32_t* Vs = Ks + 2 * 64 * QK_STRIDE;      // 64 x 136
    float*    Ss = (float*)(Vs + 64 * V_STRIDE); // 64 x 68
    float*    ms = Ss + 64 * S_STRIDE;
    float*    ls = ms + 64;
    float*    fct = ls + 64;

    const uint32_t sbase = (uint32_t)__cvta_generic_to_shared(sm);
    const uint32_t sQ = sbase;
    const uint32_t sK = sQ + 64 * QK_STRIDE * 4;
    const uint32_t sV = sK + 2 * 64 * QK_STRIDE * 4;

    const int tid  = threadIdx.x;
    const int lane = tid & 31;
    const int wid  = tid >> 5;
    const int g    = lane >> 2;
    const int tg   = lane & 3;
    const int m0   = (wid >> 2) * 16;
    const int nS0  = (wid & 3) * 16;
    const int nO0  = (wid & 3) * 32;

    const int qt   = blockIdx.x;
    const int head = blockIdx.y;
    const int kvh  = head >> 2;

    const float* qp = Qt + (size_t)qt * 64 * HID + head * HD;
    const float* kp = KV + kvh * HD;            // stride KVW
    const float* vp = KV + KVHID + kvh * HD;    // stride KVW

    auto load_tile = [&](uint32_t sdst, int stride_w, const float* gp, int grs) {
#pragma unroll
        for (int j = 0; j < 4; j++) {
            int idx = tid + 512 * j;
            int row = idx >> 5, ch = (idx & 31) * 4;
            cp16(sdst + (uint32_t)(row * stride_w + ch) * 4,
                 gp + (size_t)row * grs + ch);
        }
    };

    // Preload: Q (group0), K0 (group1), V0 (group2)
    load_tile(sQ, QK_STRIDE, qp, HID);
    cp_commit();
    load_tile(sK, QK_STRIDE, kp, KVW);
    cp_commit();
    load_tile(sV, V_STRIDE, vp, KVW);
    cp_commit();

    if (tid < 64) { ms[tid] = -1e30f; ls[tid] = 0.f; }

    float accO[4][4];
#pragma unroll
    for (int nt = 0; nt < 4; nt++)
#pragma unroll
        for (int t = 0; t < 4; t++) accO[nt][t] = 0.f;

    cp_wait<1>();          // Q + K0 done
    __syncthreads();

    for (int kt = 0; kt < SEQ / 64; kt++) {
        const int kb = kt & 1;
        if (kt + 1 < SEQ / 64)
            load_tile(sK + (uint32_t)((kb ^ 1) * 64 * QK_STRIDE * 4), QK_STRIDE,
                      kp + (size_t)(kt + 1) * 64 * KVW, KVW);
        cp_commit();

        // --- S = Q K^T (plain tf32) ---
        const uint32_t* ksb = Ks + kb * 64 * QK_STRIDE;
        float accS[2][4];
#pragma unroll
        for (int nt = 0; nt < 2; nt++)
#pragma unroll
            for (int t = 0; t < 4; t++) accS[nt][t] = 0.f;

#pragma unroll
        for (int k0 = 0; k0 < 128; k0 += 8) {
            uint32_t aq[4];
            const int ra = (m0 + g) * QK_STRIDE + k0 + tg;
            const int rb = (m0 + g + 8) * QK_STRIDE + k0 + tg;
            aq[0] = Qs[ra];     aq[1] = Qs[rb];
            aq[2] = Qs[ra + 4]; aq[3] = Qs[rb + 4];
#pragma unroll
            for (int nt = 0; nt < 2; nt++) {
                uint32_t bb[2];
                const int kb2 = (nS0 + nt * 8 + g) * QK_STRIDE + k0 + tg;
                bb[0] = ksb[kb2];
                bb[1] = ksb[kb2 + 4];
                mma_tf32(accS[nt], aq, bb);
            }
        }

#pragma unroll
        for (int nt = 0; nt < 2; nt++) {
            int col = nS0 + nt * 8 + tg * 2;
            *(float2*)(Ss + (m0 + g) * S_STRIDE + col) =
                make_float2(accS[nt][0], accS[nt][1]);
            *(float2*)(Ss + (m0 + g + 8) * S_STRIDE + col) =
                make_float2(accS[nt][2], accS[nt][3]);
        }
        __syncthreads();

        // --- online softmax ---
        {
            int row = tid >> 3, qq = tid & 7;
            float* srow = Ss + row * S_STRIDE + qq * 8;
            float mx = srow[0];
#pragma unroll
            for (int j = 1; j < 8; j++) mx = fmaxf(mx, srow[j]);
            mx = fmaxf(mx, __shfl_xor_sync(0xffffffffu, mx, 1));
            mx = fmaxf(mx, __shfl_xor_sync(0xffffffffu, mx, 2));
            mx = fmaxf(mx, __shfl_xor_sync(0xffffffffu, mx, 4));
            float m_old = ms[row];
            float m_new = fmaxf(m_old, mx);
            float sum = 0.f;
#pragma unroll
            for (int j = 0; j < 8; j++) {
                float p = __expf(srow[j] - m_new);
                srow[j] = p;
                sum += p;
            }
            sum += __shfl_xor_sync(0xffffffffu, sum, 1);
            sum += __shfl_xor_sync(0xffffffffu, sum, 2);
            sum += __shfl_xor_sync(0xffffffffu, sum, 4);
            if (qq == 0) {
                float f = __expf(m_old - m_new);
                fct[row] = f;
                ls[row] = ls[row] * f + sum;
                ms[row] = m_new;
            }
        }
        __syncthreads();

        cp_wait<1>();      // V(t) done (only K(t+1) may stay pending)
        __syncthreads();

        // --- rescale accumulators, O += P V ---
        {
            float f0 = fct[m0 + g];
            float f1 = fct[m0 + g + 8];
#pragma unroll
            for (int nt = 0; nt < 4; nt++) {
                accO[nt][0] *= f0; accO[nt][1] *= f0;
                accO[nt][2] *= f1; accO[nt][3] *= f1;
            }
        }
#pragma unroll
        for (int k0 = 0; k0 < 64; k0 += 8) {
            uint32_t pa[4];
            pa[0] = f2t(Ss[(m0 + g) * S_STRIDE + k0 + tg]);
            pa[1] = f2t(Ss[(m0 + g + 8) * S_STRIDE + k0 + tg]);
            pa[2] = f2t(Ss[(m0 + g) * S_STRIDE + k0 + tg + 4]);
            pa[3] = f2t(Ss[(m0 + g + 8) * S_STRIDE + k0 + tg + 4]);
#pragma unroll
            for (int nt = 0; nt < 4; nt++) {
                uint32_t vb[2];
                int col = nO0 + nt * 8 + g;
                vb[0] = Vs[(k0 + tg) * V_STRIDE + col];
                vb[1] = Vs[(k0 + tg + 4) * V_STRIDE + col];
                mma_tf32(accO[nt], pa, vb);
            }
        }
        __syncthreads();

        if (kt + 1 < SEQ / 64)
            load_tile(sV, V_STRIDE, vp + (size_t)(kt + 1) * 64 * KVW, KVW);
        cp_commit();

        cp_wait<1>();      // K(t+1) done
        __syncthreads();
    }

    // --- finalize: divide by l, tf32-round, write out ---
    float inv0 = 1.0f / ls[m0 + g];
    float inv1 = 1.0f / ls[m0 + g + 8];
    float* op = O + (size_t)qt * 64 * HID + head * HD;
#pragma unroll
    for (int nt = 0; nt < 4; nt++) {
        int col = nO0 + nt * 8 + tg * 2;
        *(float2*)(op + (size_t)(m0 + g) * HID + col) =
            make_float2(__uint_as_float(f2t(accO[nt][0] * inv0)),
                        __uint_as_float(f2t(accO[nt][1] * inv0)));
        *(float2*)(op + (size_t)(m0 + g + 8) * HID + col) =
            make_float2(__uint_as_float(f2t(accO[nt][2] * inv1)),
                        __uint_as_float(f2t(accO[nt][3] * inv1)));
    }
}

// ---------------------------------------------------------------------------
// Launch
// ---------------------------------------------------------------------------
extern "C" void kernel_launch(void* const* d_in, const int* in_sizes, int n_in,
                              void* d_out, int out_size) {
    (void)in_sizes; (void)n_in; (void)out_size;
    const float* hs  = (const float*)d_in[0];
    const int*   pos = (const int*)d_in[1];
    const float* qw  = (const float*)d_in[2];
    const float* kw  = (const float*)d_in[3];
    const float* vw  = (const float*)d_in[4];
    const float* ow  = (const float*)d_in[5];
    float* out = (float*)d_out;

    float *q, *qt, *kv, *attn;
    float *hst, *qwt, *kvwt, *owt;
    cudaGetSymbolAddress((void**)&q, g_q);
    cudaGetSymbolAddress((void**)&qt, g_qt);
    cudaGetSymbolAddress((void**)&kv, g_kv);
    cudaGetSymbolAddress((void**)&attn, g_attn);
    cudaGetSymbolAddress((void**)&hst, g_hst);
    cudaGetSymbolAddress((void**)&qwt, g_qwt);
    cudaGetSymbolAddress((void**)&kvwt, g_kvwt);
    cudaGetSymbolAddress((void**)&owt, g_owt);

    cudaFuncSetAttribute(gemm_tf32,
                         cudaFuncAttributeMaxDynamicSharedMemorySize, GEMM_SMEM);
    cudaFuncSetAttribute(gemm_qkv,
                         cudaFuncAttributeMaxDynamicSharedMemorySize, GEMM_SMEM);
    cudaFuncSetAttribute(attn_mma,
                         cudaFuncAttributeMaxDynamicSharedMemorySize, ATTN_SMEM);

    // Pre-truncate inputs; k_proj/v_proj concatenated into one weight buffer
    trunc_tf32<<<(SEQ * HID / 4 + 255) / 256, 256>>>(hs, hst, SEQ * HID / 4);
    trunc_tf32<<<(HID * HID / 4 + 255) / 256, 256>>>(qw, qwt, HID * HID / 4);
    trunc_tf32<<<(KVHID * HID / 4 + 255) / 256, 256>>>(kw, kvwt, KVHID * HID / 4);
    trunc_tf32<<<(KVHID * HID / 4 + 255) / 256, 256>>>(vw, kvwt + (size_t)KVHID * HID,
                                                       KVHID * HID / 4);
    trunc_tf32<<<(HID * HID / 4 + 255) / 256, 256>>>(ow, owt, HID * HID / 4);

    // Fused Q + KV projections: one 768-CTA launch, occ 2
    gemm_qkv<<<768, 256, GEMM_SMEM>>>(hst, qwt, kvwt, q, kv);

    // RoPE (+ scale + tf32 round for q -> g_qt; rope+round k; round v)
    rope_kernel<<<dim3(SEQ, NH + 2 * NKV), 64>>>(q, qt, kv, pos);

    // Attention (single-Q tf32 mma, cp.async pipeline)
    attn_mma<<<dim3(SEQ / 64, NH), 512, ATTN_SMEM>>>(qt, kv, attn);

    // Output projection (128-tile, occ 2 -> fine-grained waves)
    gemm_tf32<<<dim3(HID / 128, SEQ / 128), 256, GEMM_SMEM>>>(attn, owt, out, SEQ, HID, HID);
}

// round 10
// speedup vs baseline: 4.8937x; 1.3803x over previous
#include <cuda_runtime.h>
#include <cuda_bf16.h>
#include <cuda_fp16.h>
#include <stdint.h>
#include <math.h>

// Problem constants
#define SEQ   2048
#define HID   4096
#define NH    32
#define NKV   8
#define HD    128
#define KVHID 1024      // NKV*HD
#define KVW   2048      // merged k|v row width

// Scratch (device globals; allocation-free rule)
__device__ float  g_q[SEQ * HID];       // q_proj output (pre-rope, fp32)
__device__ float  g_qt[SEQ * HID];      // roped, scaled, tf32-rounded Q
__device__ float  g_kv[SEQ * KVW];      // merged [k | v], roped+tf32-rounded
__device__ __half g_attnh[SEQ * HID];   // attention output (fp16)

// fp16 copies of inputs for tensor-core GEMMs
__device__ __half g_hsh[SEQ * HID];
__device__ __half g_qwh[HID * HID];
__device__ __half g_kvwh[KVW * HID];    // rows 0-1023 = k_proj, 1024-2047 = v_proj
__device__ __half g_owh[HID * HID];

// ---------------------------------------------------------------------------
// Helpers
// ---------------------------------------------------------------------------
__device__ __forceinline__ uint32_t f2t(float x) {
    uint32_t u;
    asm("cvt.rna.tf32.f32 %0, %1;" : "=r"(u) : "f"(x));
    return u;
}

__device__ __forceinline__ void mma_tf32(float* c, const uint32_t* a,
                                         const uint32_t* b) {
    asm volatile(
        "mma.sync.aligned.m16n8k8.row.col.f32.tf32.tf32.f32 "
        "{%0,%1,%2,%3}, {%4,%5,%6,%7}, {%8,%9}, {%0,%1,%2,%3};"
        : "+f"(c[0]), "+f"(c[1]), "+f"(c[2]), "+f"(c[3])
        : "r"(a[0]), "r"(a[1]), "r"(a[2]), "r"(a[3]), "r"(b[0]), "r"(b[1]));
}

__device__ __forceinline__ void mma_f16(float* c, const uint32_t* a,
                                        const uint32_t* b) {
    asm volatile(
        "mma.sync.aligned.m16n8k16.row.col.f32.f16.f16.f32 "
        "{%0,%1,%2,%3}, {%4,%5,%6,%7}, {%8,%9}, {%0,%1,%2,%3};"
        : "+f"(c[0]), "+f"(c[1]), "+f"(c[2]), "+f"(c[3])
        : "r"(a[0]), "r"(a[1]), "r"(a[2]), "r"(a[3]), "r"(b[0]), "r"(b[1]));
}

__device__ __forceinline__ void cp16(uint32_t saddr, const void* gaddr) {
    asm volatile("cp.async.cg.shared.global [%0], [%1], 16;"
                 :: "r"(saddr), "l"(gaddr));
}
__device__ __forceinline__ void cp_commit() {
    asm volatile("cp.async.commit_group;");
}
template <int N>
__device__ __forceinline__ void cp_wait() {
    asm volatile("cp.async.wait_group %0;" :: "n"(N));
}

// ---------------------------------------------------------------------------
// fp32 -> fp16 conversion (rn). Same 11-bit significand as tf32.
// ---------------------------------------------------------------------------
__global__ __launch_bounds__(256) void cvt_f2h(const float* __restrict__ in,
                                               __half* __restrict__ out,
                                               int n4) {
    int i = blockIdx.x * 256 + threadIdx.x;
    if (i < n4) {
        float4 x = ((const float4*)in)[i];
        __half2 a = __floats2half2_rn(x.x, x.y);
        __half2 b = __floats2half2_rn(x.z, x.w);
        ((__half2*)out)[i * 2]     = a;
        ((__half2*)out)[i * 2 + 1] = b;
    }
}

// ---------------------------------------------------------------------------
// fp16 tensor-core GEMM core: one 128x128 tile of
// C[M,N] = A[M,K(=4096)] @ W[N,K]^T, A/W fp16, C fp32.
// BK=64 halves, 3-stage cp.async ring, 256 threads, 8 warps 4(m)x2(n),
// warp tile 32x64, mma m16n8k16. Smem stride 72 halves (=144B): fragment
// LDS bank = (4g+tg) -> conflict-free; rows 16B-aligned.
// ---------------------------------------------------------------------------
#define HSTRIDE 72
#define HSTAGES 3
#define HGEMM_SMEM (HSTAGES * 2 * 128 * HSTRIDE * 2)   // 110592 B

__device__ __forceinline__ void hgemm_tile_128(const __half* __restrict__ A,
                                               const __half* __restrict__ W,
                                               float* __restrict__ C,
                                               int N, int K,
                                               int mb, int nb, char* gsm) {
    __half* As = (__half*)gsm;                       // [3][128][72]
    __half* Bs = As + HSTAGES * 128 * HSTRIDE;

    const int tid  = threadIdx.x;
    const int lane = tid & 31;
    const int wid  = tid >> 5;
    const int g    = lane >> 2;
    const int tg   = lane & 3;
    const int wm   = (wid >> 1) * 32;
    const int wn   = (wid & 1) * 64;

    const __half* Ap = A + (size_t)mb * K;
    const __half* Wp = W + (size_t)nb * K;

    const uint32_t sA = (uint32_t)__cvta_generic_to_shared(As);
    const uint32_t sB = (uint32_t)__cvta_generic_to_shared(Bs);

    // per stage: 128 rows x 8 16B-chunks (64 halves) per matrix = 1024 chunks
    auto issue_stage = [&](int stage, int k0) {
        const uint32_t so = (uint32_t)(stage * 128 * HSTRIDE * 2);
#pragma unroll
        for (int j = 0; j < 4; j++) {
            int idx = tid + 256 * j;
            int row = idx >> 3, ch = idx & 7;
            uint32_t sofs = so + (uint32_t)(row * HSTRIDE * 2 + ch * 16);
            cp16(sA + sofs, Ap + (size_t)row * K + k0 + ch * 8);
            cp16(sB + sofs, Wp + (size_t)row * K + k0 + ch * 8);
        }
    };

    float acc[2][8][4];
#pragma unroll
    for (int i = 0; i < 2; i++)
#pragma unroll
        for (int j = 0; j < 8; j++)
#pragma unroll
            for (int t = 0; t < 4; t++) acc[i][j][t] = 0.f;

    const int NIT = K / 64;
    issue_stage(0, 0);  cp_commit();
    issue_stage(1, 64); cp_commit();
    cp_wait<1>();
    __syncthreads();

    for (int it = 0; it < NIT; it++) {
        const int s = it % HSTAGES;
        const __half* as = As + s * 128 * HSTRIDE;
        const __half* bs = Bs + s * 128 * HSTRIDE;

#pragma unroll
        for (int kk = 0; kk < 4; kk++) {             // 4 x k16 per iter
            uint32_t af[2][4], bf[8][2];
#pragma unroll
            for (int i = 0; i < 2; i++) {
                const __half* ar = as + (wm + i * 16 + g) * HSTRIDE + kk * 16 + tg * 2;
                af[i][0] = *(const uint32_t*)ar;
                af[i][1] = *(const uint32_t*)(ar + 8 * HSTRIDE);
                af[i][2] = *(const uint32_t*)(ar + 8);
                af[i][3] = *(const uint32_t*)(ar + 8 * HSTRIDE + 8);
            }
#pragma unroll
            for (int j = 0; j < 8; j++) {
                const __half* br = bs + (wn + j * 8 + g) * HSTRIDE + kk * 16 + tg * 2;
                bf[j][0] = *(const uint32_t*)br;
                bf[j][1] = *(const uint32_t*)(br + 8);
            }
#pragma unroll
            for (int i = 0; i < 2; i++)
#pragma unroll
                for (int j = 0; j < 8; j++)
                    mma_f16(acc[i][j], af[i], bf[j]);
        }

        if (it + 2 < NIT) issue_stage((it + 2) % HSTAGES, (it + 2) * 64);
        cp_commit();
        cp_wait<1>();
        __syncthreads();
    }

#pragma unroll
    for (int i = 0; i < 2; i++) {
        int row = mb + wm + i * 16 + g;
#pragma unroll
        for (int j = 0; j < 8; j++) {
            int col = nb + wn + j * 8 + tg * 2;
            *(float2*)(C + (size_t)row * N + col) =
                make_float2(acc[i][j][0], acc[i][j][1]);
            *(float2*)(C + (size_t)(row + 8) * N + col) =
                make_float2(acc[i][j][2], acc[i][j][3]);
        }
    }
}

// Generic 2D-grid fp16 GEMM (o_proj)
__global__ __launch_bounds__(256, 2) void gemm_f16(const __half* __restrict__ A,
                                                   const __half* __restrict__ W,
                                                   float* __restrict__ C,
                                                   int M, int N, int K) {
    extern __shared__ char gsm[];
    hgemm_tile_128(A, W, C, N, K, blockIdx.y * 128, blockIdx.x * 128, gsm);
}

// Merged QKV projection: linear grid of 768 CTAs.
__global__ __launch_bounds__(256, 2) void gemm_qkv(const __half* __restrict__ A,
                                                   const __half* __restrict__ Wq,
                                                   const __half* __restrict__ Wkv,
                                                   float* __restrict__ Cq,
                                                   float* __restrict__ Ckv) {
    extern __shared__ char gsm[];
    const int bid = blockIdx.x;
    if (bid < 512) {
        hgemm_tile_128(A, Wq, Cq, HID, HID,
                       (bid >> 5) * 128, (bid & 31) * 128, gsm);
    } else {
        const int b2 = bid - 512;
        hgemm_tile_128(A, Wkv, Ckv, KVW, HID,
                       (b2 >> 4) * 128, (b2 & 15) * 128, gsm);
    }
}

// ---------------------------------------------------------------------------
// RoPE + attention pre-processing (unchanged from round 9).
// ---------------------------------------------------------------------------
__global__ void rope_kernel(const float* __restrict__ q,
                            float* __restrict__ qt,
                            float* __restrict__ kv,
                            const int* __restrict__ pos_ids) {
    const int s = blockIdx.x;
    const int h = blockIdx.y;
    const int d = threadIdx.x;  // 0..63

    if (h >= NH + NKV) {   // v: plain tf32 round
        size_t base = (size_t)s * KVW + KVHID + (h - NH - NKV) * HD;
        kv[base + d]      = __uint_as_float(f2t(kv[base + d]));
        kv[base + d + 64] = __uint_as_float(f2t(kv[base + d + 64]));
        return;
    }

    const float cexp = 0.20503692556210917f;  // ln(500000)/64
    float inv_freq = expf(-(float)d * cexp);
    float freq = (float)pos_ids[s] * inv_freq;
    float cs, sn;
    sincosf(freq, &sn, &cs);

    if (h < NH) {
        const float sm_scale = 0.08838834764831845f;  // 1/sqrt(128)
        size_t base = (size_t)s * HID + h * HD;
        float x1 = q[base + d];
        float x2 = q[base + d + 64];
        qt[base + d]      = __uint_as_float(f2t((x1 * cs - x2 * sn) * sm_scale));
        qt[base + d + 64] = __uint_as_float(f2t((x2 * cs + x1 * sn) * sm_scale));
    } else {
        size_t base = (size_t)s * KVW + (h - NH) * HD;
        float x1 = kv[base + d];
        float x2 = kv[base + d + 64];
        kv[base + d]      = __uint_as_float(f2t(x1 * cs - x2 * sn));
        kv[base + d + 64] = __uint_as_float(f2t(x2 * cs + x1 * sn));
    }
}

// ---------------------------------------------------------------------------
// TF32 mma flash attention (round-9 proven); epilogue now emits fp16 so
// o_proj consumes halves directly.
// ---------------------------------------------------------------------------
#define QK_STRIDE 132
#define V_STRIDE  136
#define S_STRIDE  68
#define ATTN_SMEM ((3 * 64 * QK_STRIDE + 64 * V_STRIDE + 64 * S_STRIDE + 3 * 64) * 4)

__global__ __launch_bounds__(512) void attn_mma(const float* __restrict__ Qt,
                                                const float* __restrict__ KV,
                                                __half* __restrict__ O) {
    extern __shared__ uint32_t sm[];
    uint32_t* Qs = sm;                           // 64 x 132
    uint32_t* Ks = Qs + 64 * QK_STRIDE;          // 2 stages x 64 x 132
    uint32_t* Vs = Ks + 2 * 64 * QK_STRIDE;      // 64 x 136
    float*    Ss = (float*)(Vs + 64 * V_STRIDE); // 64 x 68
    float*    ms = Ss + 64 * S_STRIDE;
    float*    ls = ms + 64;
    float*    fct = ls + 64;

    const uint32_t sbase = (uint32_t)__cvta_generic_to_shared(sm);
    const uint32_t sQ = sbase;
    const uint32_t sK = sQ + 64 * QK_STRIDE * 4;
    const uint32_t sV = sK + 2 * 64 * QK_STRIDE * 4;

    const int tid  = threadIdx.x;
    const int lane = tid & 31;
    const int wid  = tid >> 5;
    const int g    = lane >> 2;
    const int tg   = lane & 3;
    const int m0   = (wid >> 2) * 16;
    const int nS0  = (wid & 3) * 16;
    const int nO0  = (wid & 3) * 32;

    const int qt   = blockIdx.x;
    const int head = blockIdx.y;
    const int kvh  = head >> 2;

    const float* qp = Qt + (size_t)qt * 64 * HID + head * HD;
    const float* kp = KV + kvh * HD;            // stride KVW
    const float* vp = KV + KVHID + kvh * HD;    // stride KVW

    auto load_tile = [&](uint32_t sdst, int stride_w, const float* gp, int grs) {
#pragma unroll
        for (int j = 0; j < 4; j++) {
            int idx = tid + 512 * j;
            int row = idx >> 5, ch = (idx & 31) * 4;
            cp16(sdst + (uint32_t)(row * stride_w + ch) * 4,
                 gp + (size_t)row * grs + ch);
        }
    };

    load_tile(sQ, QK_STRIDE, qp, HID);
    cp_commit();
    load_tile(sK, QK_STRIDE, kp, KVW);
    cp_commit();
    load_tile(sV, V_STRIDE, vp, KVW);
    cp_commit();

    if (tid < 64) { ms[tid] = -1e30f; ls[tid] = 0.f; }

    float accO[4][4];
#pragma unroll
    for (int nt = 0; nt < 4; nt++)
#pragma unroll
        for (int t = 0; t < 4; t++) accO[nt][t] = 0.f;

    cp_wait<1>();
    __syncthreads();

    for (int kt = 0; kt < SEQ / 64; kt++) {
        const int kb = kt & 1;
        if (kt + 1 < SEQ / 64)
            load_tile(sK + (uint32_t)((kb ^ 1) * 64 * QK_STRIDE * 4), QK_STRIDE,
                      kp + (size_t)(kt + 1) * 64 * KVW, KVW);
        cp_commit();

        const uint32_t* ksb = Ks + kb * 64 * QK_STRIDE;
        float accS[2][4];
#pragma unroll
        for (int nt = 0; nt < 2; nt++)
#pragma unroll
            for (int t = 0; t < 4; t++) accS[nt][t] = 0.f;

#pragma unroll
        for (int k0 = 0; k0 < 128; k0 += 8) {
            uint32_t aq[4];
            const int ra = (m0 + g) * QK_STRIDE + k0 + tg;
            const int rb = (m0 + g + 8) * QK_STRIDE + k0 + tg;
            aq[0] = Qs[ra];     aq[1] = Qs[rb];
            aq[2] = Qs[ra + 4]; aq[3] = Qs[rb + 4];
#pragma unroll
            for (int nt = 0; nt < 2; nt++) {
                uint32_t bb[2];
                const int kb2 = (nS0 + nt * 8 + g) * QK_STRIDE + k0 + tg;
                bb[0] = ksb[kb2];
                bb[1] = ksb[kb2 + 4];
                mma_tf32(accS[nt], aq, bb);
            }
        }

#pragma unroll
        for (int nt = 0; nt < 2; nt++) {
            int col = nS0 + nt * 8 + tg * 2;
            *(float2*)(Ss + (m0 + g) * S_STRIDE + col) =
                make_float2(accS[nt][0], accS[nt][1]);
            *(float2*)(Ss + (m0 + g + 8) * S_STRIDE + col) =
                make_float2(accS[nt][2], accS[nt][3]);
        }
        __syncthreads();

        {
            int row = tid >> 3, qq = tid & 7;
            float* srow = Ss + row * S_STRIDE + qq * 8;
            float mx = srow[0];
#pragma unroll
            for (int j = 1; j < 8; j++) mx = fmaxf(mx, srow[j]);
            mx = fmaxf(mx, __shfl_xor_sync(0xffffffffu, mx, 1));
            mx = fmaxf(mx, __shfl_xor_sync(0xffffffffu, mx, 2));
            mx = fmaxf(mx, __shfl_xor_sync(0xffffffffu, mx, 4));
            float m_old = ms[row];
            float m_new = fmaxf(m_old, mx);
            float sum = 0.f;
#pragma unroll
            for (int j = 0; j < 8; j++) {
                float p = __expf(srow[j] - m_new);
                srow[j] = p;
                sum += p;
            }
            sum += __shfl_xor_sync(0xffffffffu, sum, 1);
            sum += __shfl_xor_sync(0xffffffffu, sum, 2);
            sum += __shfl_xor_sync(0xffffffffu, sum, 4);
            if (qq == 0) {
                float f = __expf(m_old - m_new);
                fct[row] = f;
                ls[row] = ls[row] * f + sum;
                ms[row] = m_new;
            }
        }
        __syncthreads();

        cp_wait<1>();
        __syncthreads();

        {
            float f0 = fct[m0 + g];
            float f1 = fct[m0 + g + 8];
#pragma unroll
            for (int nt = 0; nt < 4; nt++) {
                accO[nt][0] *= f0; accO[nt][1] *= f0;
                accO[nt][2] *= f1; accO[nt][3] *= f1;
            }
        }
#pragma unroll
        for (int k0 = 0; k0 < 64; k0 += 8) {
            uint32_t pa[4];
            pa[0] = f2t(Ss[(m0 + g) * S_STRIDE + k0 + tg]);
            pa[1] = f2t(Ss[(m0 + g + 8) * S_STRIDE + k0 + tg]);
            pa[2] = f2t(Ss[(m0 + g) * S_STRIDE + k0 + tg + 4]);
            pa[3] = f2t(Ss[(m0 + g + 8) * S_STRIDE + k0 + tg + 4]);
#pragma unroll
            for (int nt = 0; nt < 4; nt++) {
                uint32_t vb[2];
                int col = nO0 + nt * 8 + g;
                vb[0] = Vs[(k0 + tg) * V_STRIDE + col];
                vb[1] = Vs[(k0 + tg + 4) * V_STRIDE + col];
                mma_tf32(accO[nt], pa, vb);
            }
        }
        __syncthreads();

        if (kt + 1 < SEQ / 64)
            load_tile(sV, V_STRIDE, vp + (size_t)(kt + 1) * 64 * KVW, KVW);
        cp_commit();

        cp_wait<1>();
        __syncthreads();
    }

    // --- finalize: divide by l, emit fp16 (same 11-bit significand) ---
    float inv0 = 1.0f / ls[m0 + g];
    float inv1 = 1.0f / ls[m0 + g + 8];
    __half* op = O + (size_t)qt * 64 * HID + head * HD;
#pragma unroll
    for (int nt = 0; nt < 4; nt++) {
        int col = nO0 + nt * 8 + tg * 2;
        *(__half2*)(op + (size_t)(m0 + g) * HID + col) =
            __floats2half2_rn(accO[nt][0] * inv0, accO[nt][1] * inv0);
        *(__half2*)(op + (size_t)(m0 + g + 8) * HID + col) =
            __floats2half2_rn(accO[nt][2] * inv1, accO[nt][3] * inv1);
    }
}

// ---------------------------------------------------------------------------
// Launch
// ---------------------------------------------------------------------------
extern "C" void kernel_launch(void* const* d_in, const int* in_sizes, int n_in,
                              void* d_out, int out_size) {
    (void)in_sizes; (void)n_in; (void)out_size;
    const float* hs  = (const float*)d_in[0];
    const int*   pos = (const int*)d_in[1];
    const float* qw  = (const float*)d_in[2];
    const float* kw  = (const float*)d_in[3];
    const float* vw  = (const float*)d_in[4];
    const float* ow  = (const float*)d_in[5];
    float* out = (float*)d_out;

    float *q, *qt, *kv;
    __half *attnh, *hsh, *qwh, *kvwh, *owh;
    cudaGetSymbolAddress((void**)&q, g_q);
    cudaGetSymbolAddress((void**)&qt, g_qt);
    cudaGetSymbolAddress((void**)&kv, g_kv);
    cudaGetSymbolAddress((void**)&attnh, g_attnh);
    cudaGetSymbolAddress((void**)&hsh, g_hsh);
    cudaGetSymbolAddress((void**)&qwh, g_qwh);
    cudaGetSymbolAddress((void**)&kvwh, g_kvwh);
    cudaGetSymbolAddress((void**)&owh, g_owh);

    cudaFuncSetAttribute(gemm_f16,
                         cudaFuncAttributeMaxDynamicSharedMemorySize, HGEMM_SMEM);
    cudaFuncSetAttribute(gemm_qkv,
                         cudaFuncAttributeMaxDynamicSharedMemorySize, HGEMM_SMEM);
    cudaFuncSetAttribute(attn_mma,
                         cudaFuncAttributeMaxDynamicSharedMemorySize, ATTN_SMEM);

    // Convert inputs to fp16; k_proj/v_proj concatenated into one weight buffer
    cvt_f2h<<<(SEQ * HID / 4 + 255) / 256, 256>>>(hs, hsh, SEQ * HID / 4);
    cvt_f2h<<<(HID * HID / 4 + 255) / 256, 256>>>(qw, qwh, HID * HID / 4);
    cvt_f2h<<<(KVHID * HID / 4 + 255) / 256, 256>>>(kw, kvwh, KVHID * HID / 4);
    cvt_f2h<<<(KVHID * HID / 4 + 255) / 256, 256>>>(vw, kvwh + (size_t)KVHID * HID,
                                                    KVHID * HID / 4);
    cvt_f2h<<<(HID * HID / 4 + 255) / 256, 256>>>(ow, owh, HID * HID / 4);

    // Fused Q + KV projections: one 768-CTA launch, occ 2, fp16 mma
    gemm_qkv<<<768, 256, HGEMM_SMEM>>>(hsh, qwh, kvwh, q, kv);

    // RoPE (+ scale + tf32 round for q -> g_qt; rope+round k; round v)
    rope_kernel<<<dim3(SEQ, NH + 2 * NKV), 64>>>(q, qt, kv, pos);

    // Attention (tf32 mma, cp.async pipeline); emits fp16 for o_proj
    attn_mma<<<dim3(SEQ / 64, NH), 512, ATTN_SMEM>>>(qt, kv, attnh);

    // Output projection (fp16 mma)
    gemm_f16<<<dim3(HID / 128, SEQ / 128), 256, HGEMM_SMEM>>>(attnh, owh, out, SEQ, HID, HID);
}

// round 11
// speedup vs baseline: 6.4833x; 1.3248x over previous
#include <cuda_runtime.h>
#include <cuda_bf16.h>
#include <cuda_fp16.h>
#include <stdint.h>
#include <math.h>

// Problem constants
#define SEQ   2048
#define HID   4096
#define NH    32
#define NKV   8
#define HD    128
#define KVHID 1024      // NKV*HD
#define KVW   2048      // merged k|v row width

// Scratch (device globals; allocation-free rule)
__device__ float  g_q[SEQ * HID];        // q_proj output (pre-rope, fp32)
__device__ float  g_kv[SEQ * KVW];       // merged [k | v] fp32 from projection
__device__ __half g_qth[SEQ * HID];      // roped, scaled Q (fp16)
__device__ __half g_kh[SEQ * KVHID];     // roped K (fp16)
__device__ __half g_vth[NKV * HD * SEQ]; // V^T (fp16): [kvh][d][s]
__device__ __half g_attnh[SEQ * HID];    // attention output (fp16)

// fp16 copies of inputs for tensor-core GEMMs
__device__ __half g_hsh[SEQ * HID];
__device__ __half g_qwh[HID * HID];
__device__ __half g_kvwh[KVW * HID];     // rows 0-1023 = k_proj, 1024-2047 = v_proj
__device__ __half g_owh[HID * HID];

// ---------------------------------------------------------------------------
// Helpers
// ---------------------------------------------------------------------------
__device__ __forceinline__ void mma_f16(float* c, const uint32_t* a,
                                        const uint32_t* b) {
    asm volatile(
        "mma.sync.aligned.m16n8k16.row.col.f32.f16.f16.f32 "
        "{%0,%1,%2,%3}, {%4,%5,%6,%7}, {%8,%9}, {%0,%1,%2,%3};"
        : "+f"(c[0]), "+f"(c[1]), "+f"(c[2]), "+f"(c[3])
        : "r"(a[0]), "r"(a[1]), "r"(a[2]), "r"(a[3]), "r"(b[0]), "r"(b[1]));
}

__device__ __forceinline__ void cp16(uint32_t saddr, const void* gaddr) {
    asm volatile("cp.async.cg.shared.global [%0], [%1], 16;"
                 :: "r"(saddr), "l"(gaddr));
}
__device__ __forceinline__ void cp_commit() {
    asm volatile("cp.async.commit_group;");
}
template <int N>
__device__ __forceinline__ void cp_wait() {
    asm volatile("cp.async.wait_group %0;" :: "n"(N));
}

// ---------------------------------------------------------------------------
// fp32 -> fp16 conversion (rn).
// ---------------------------------------------------------------------------
__global__ __launch_bounds__(256) void cvt_f2h(const float* __restrict__ in,
                                               __half* __restrict__ out,
                                               int n4) {
    int i = blockIdx.x * 256 + threadIdx.x;
    if (i < n4) {
        float4 x = ((const float4*)in)[i];
        ((__half2*)out)[i * 2]     = __floats2half2_rn(x.x, x.y);
        ((__half2*)out)[i * 2 + 1] = __floats2half2_rn(x.z, x.w);
    }
}

// ---------------------------------------------------------------------------
// fp16 tensor-core GEMM core (round-10 proven): one 128x128 tile of
// C[M,N] = A[M,K(=4096)] @ W[N,K]^T, A/W fp16, C fp32.
// ---------------------------------------------------------------------------
#define HSTRIDE 72
#define HSTAGES 3
#define HGEMM_SMEM (HSTAGES * 2 * 128 * HSTRIDE * 2)   // 110592 B

__device__ __forceinline__ void hgemm_tile_128(const __half* __restrict__ A,
                                               const __half* __restrict__ W,
                                               float* __restrict__ C,
                                               int N, int K,
                                               int mb, int nb, char* gsm) {
    __half* As = (__half*)gsm;                       // [3][128][72]
    __half* Bs = As + HSTAGES * 128 * HSTRIDE;

    const int tid  = threadIdx.x;
    const int lane = tid & 31;
    const int wid  = tid >> 5;
    const int g    = lane >> 2;
    const int tg   = lane & 3;
    const int wm   = (wid >> 1) * 32;
    const int wn   = (wid & 1) * 64;

    const __half* Ap = A + (size_t)mb * K;
    const __half* Wp = W + (size_t)nb * K;

    const uint32_t sA = (uint32_t)__cvta_generic_to_shared(As);
    const uint32_t sB = (uint32_t)__cvta_generic_to_shared(Bs);

    auto issue_stage = [&](int stage, int k0) {
        const uint32_t so = (uint32_t)(stage * 128 * HSTRIDE * 2);
#pragma unroll
        for (int j = 0; j < 4; j++) {
            int idx = tid + 256 * j;
            int row = idx >> 3, ch = idx & 7;
            uint32_t sofs = so + (uint32_t)(row * HSTRIDE * 2 + ch * 16);
            cp16(sA + sofs, Ap + (size_t)row * K + k0 + ch * 8);
            cp16(sB + sofs, Wp + (size_t)row * K + k0 + ch * 8);
        }
    };

    float acc[2][8][4];
#pragma unroll
    for (int i = 0; i < 2; i++)
#pragma unroll
        for (int j = 0; j < 8; j++)
#pragma unroll
            for (int t = 0; t < 4; t++) acc[i][j][t] = 0.f;

    const int NIT = K / 64;
    issue_stage(0, 0);  cp_commit();
    issue_stage(1, 64); cp_commit();
    cp_wait<1>();
    __syncthreads();

    for (int it = 0; it < NIT; it++) {
        const int s = it % HSTAGES;
        const __half* as = As + s * 128 * HSTRIDE;
        const __half* bs = Bs + s * 128 * HSTRIDE;

#pragma unroll
        for (int kk = 0; kk < 4; kk++) {
            uint32_t af[2][4], bf[8][2];
#pragma unroll
            for (int i = 0; i < 2; i++) {
                const __half* ar = as + (wm + i * 16 + g) * HSTRIDE + kk * 16 + tg * 2;
                af[i][0] = *(const uint32_t*)ar;
                af[i][1] = *(const uint32_t*)(ar + 8 * HSTRIDE);
                af[i][2] = *(const uint32_t*)(ar + 8);
                af[i][3] = *(const uint32_t*)(ar + 8 * HSTRIDE + 8);
            }
#pragma unroll
            for (int j = 0; j < 8; j++) {
                const __half* br = bs + (wn + j * 8 + g) * HSTRIDE + kk * 16 + tg * 2;
                bf[j][0] = *(const uint32_t*)br;
                bf[j][1] = *(const uint32_t*)(br + 8);
            }
#pragma unroll
            for (int i = 0; i < 2; i++)
#pragma unroll
                for (int j = 0; j < 8; j++)
                    mma_f16(acc[i][j], af[i], bf[j]);
        }

        if (it + 2 < NIT) issue_stage((it + 2) % HSTAGES, (it + 2) * 64);
        cp_commit();
        cp_wait<1>();
        __syncthreads();
    }

#pragma unroll
    for (int i = 0; i < 2; i++) {
        int row = mb + wm + i * 16 + g;
#pragma unroll
        for (int j = 0; j < 8; j++) {
            int col = nb + wn + j * 8 + tg * 2;
            *(float2*)(C + (size_t)row * N + col) =
                make_float2(acc[i][j][0], acc[i][j][1]);
            *(float2*)(C + (size_t)(row + 8) * N + col) =
                make_float2(acc[i][j][2], acc[i][j][3]);
        }
    }
}

__global__ __launch_bounds__(256, 2) void gemm_f16(const __half* __restrict__ A,
                                                   const __half* __restrict__ W,
                                                   float* __restrict__ C,
                                                   int M, int N, int K) {
    extern __shared__ char gsm[];
    hgemm_tile_128(A, W, C, N, K, blockIdx.y * 128, blockIdx.x * 128, gsm);
}

__global__ __launch_bounds__(256, 2) void gemm_qkv(const __half* __restrict__ A,
                                                   const __half* __restrict__ Wq,
                                                   const __half* __restrict__ Wkv,
                                                   float* __restrict__ Cq,
                                                   float* __restrict__ Ckv) {
    extern __shared__ char gsm[];
    const int bid = blockIdx.x;
    if (bid < 512) {
        hgemm_tile_128(A, Wq, Cq, HID, HID,
                       (bid >> 5) * 128, (bid & 31) * 128, gsm);
    } else {
        const int b2 = bid - 512;
        hgemm_tile_128(A, Wkv, Ckv, KVW, HID,
                       (b2 >> 4) * 128, (b2 & 15) * 128, gsm);
    }
}

// ---------------------------------------------------------------------------
// RoPE: q -> rope, *sm_scale, fp16 -> g_qth; k -> rope, fp16 -> g_kh.
// ---------------------------------------------------------------------------
__global__ void rope_kernel(const float* __restrict__ q,
                            const float* __restrict__ kv,
                            __half* __restrict__ qth,
                            __half* __restrict__ kh,
                            const int* __restrict__ pos_ids) {
    const int s = blockIdx.x;
    const int h = blockIdx.y;
    const int d = threadIdx.x;  // 0..63

    const float cexp = 0.20503692556210917f;  // ln(500000)/64
    float inv_freq = expf(-(float)d * cexp);
    float freq = (float)pos_ids[s] * inv_freq;
    float cs, sn;
    sincosf(freq, &sn, &cs);

    if (h < NH) {
        const float sm_scale = 0.08838834764831845f;  // 1/sqrt(128)
        size_t base = (size_t)s * HID + h * HD;
        float x1 = q[base + d];
        float x2 = q[base + d + 64];
        qth[base + d]      = __float2half_rn((x1 * cs - x2 * sn) * sm_scale);
        qth[base + d + 64] = __float2half_rn((x2 * cs + x1 * sn) * sm_scale);
    } else {
        size_t src = (size_t)s * KVW + (h - NH) * HD;
        size_t dst = (size_t)s * KVHID + (h - NH) * HD;
        float x1 = kv[src + d];
        float x2 = kv[src + d + 64];
        kh[dst + d]      = __float2half_rn(x1 * cs - x2 * sn);
        kh[dst + d + 64] = __float2half_rn(x2 * cs + x1 * sn);
    }
}

// ---------------------------------------------------------------------------
// V transpose: g_kv v-part fp32 [s][kvh][d] -> g_vth fp16 [kvh][d][s].
// 32x32 tiles via smem; block (32,8), grid (SEQ/32, HD/32, NKV).
// ---------------------------------------------------------------------------
__global__ __launch_bounds__(256) void vt_kernel(const float* __restrict__ kv,
                                                 __half* __restrict__ vt) {
    __shared__ __half tile[32][33];
    const int head = blockIdx.z;
    const int s0 = blockIdx.x * 32;
    const int d0 = blockIdx.y * 32;
    const int tx = threadIdx.x, ty = threadIdx.y;

#pragma unroll
    for (int i = 0; i < 4; i++) {
        int s = s0 + ty + i * 8;
        tile[ty + i * 8][tx] = __float2half_rn(
            kv[(size_t)s * KVW + KVHID + head * HD + d0 + tx]);
    }
    __syncthreads();
#pragma unroll
    for (int i = 0; i < 4; i++) {
        int d = d0 + ty + i * 8;
        vt[(size_t)head * HD * SEQ + (size_t)d * SEQ + s0 + tx] =
            tile[tx][ty + i * 8];
    }
}

// ---------------------------------------------------------------------------
// fp16 mma flash attention v4.
// QK^T: m16n8k16 on fp16 Q,K (16 mmas/warp-iter). Softmax fp32 in smem,
// packs P to fp16. PV: m16n8k16 on fp16 P, V^T (16 mmas/warp-iter).
// cp.async pipeline: K double-buffered, V^T single-buffered (proven FIFO).
// Strides (halves): Q/K 136 (68 words, bank 4g+tg), V^T/P 72 (36 words, same).
// ---------------------------------------------------------------------------
#define QKH 136
#define VTH 72
#define PH  72
#define SSW 68
// bytes: Q 17408 + K 34816 + Vt 18432 + Ss 17408 + Ph 9216 + aux 768
#define ATTN_SMEM (64*QKH*2 + 2*64*QKH*2 + 128*VTH*2 + 64*SSW*4 + 64*PH*2 + 3*64*4)

__global__ __launch_bounds__(512) void attn_mma(const __half* __restrict__ Qt,
                                                const __half* __restrict__ Kh,
                                                const __half* __restrict__ Vt_g,
                                                __half* __restrict__ O) {
    extern __shared__ char asm_[];
    __half* Qs = (__half*)asm_;                  // 64 x 136
    __half* Ks = Qs + 64 * QKH;                  // 2 x 64 x 136
    __half* Vt = Ks + 2 * 64 * QKH;              // 128 x 72 (d-major)
    float*  Ss = (float*)(Vt + 128 * VTH);       // 64 x 68 fp32
    __half* Php = (__half*)(Ss + 64 * SSW);      // 64 x 72 fp16
    float*  ms = (float*)(Php + 64 * PH);
    float*  ls = ms + 64;
    float*  fct = ls + 64;

    const uint32_t sbase = (uint32_t)__cvta_generic_to_shared(asm_);
    const uint32_t sQ = sbase;
    const uint32_t sK = sQ + 64 * QKH * 2;
    const uint32_t sV = sK + 2 * 64 * QKH * 2;

    const int tid  = threadIdx.x;
    const int lane = tid & 31;
    const int wid  = tid >> 5;
    const int g    = lane >> 2;
    const int tg   = lane & 3;
    const int m0   = (wid >> 2) * 16;
    const int nS0  = (wid & 3) * 16;
    const int nO0  = (wid & 3) * 32;

    const int qt   = blockIdx.x;
    const int head = blockIdx.y;
    const int kvh  = head >> 2;

    const __half* qp  = Qt + (size_t)qt * 64 * HID + head * HD;
    const __half* kp  = Kh + kvh * HD;                  // stride KVHID
    const __half* vtp = Vt_g + (size_t)kvh * HD * SEQ;  // [d][s]

    // 64x128-half tile (Q/K): 1024 16B-chunks, 2/thread
    auto load_qk = [&](uint32_t sdst, const __half* gp, int grs) {
#pragma unroll
        for (int j = 0; j < 2; j++) {
            int idx = tid + 512 * j;
            int row = idx >> 4, ch = idx & 15;
            cp16(sdst + (uint32_t)(row * QKH * 2 + ch * 16),
                 gp + (size_t)row * grs + ch * 8);
        }
    };
    // V^T tile: 128 d-rows x 64 keys: 1024 chunks, 2/thread
    auto load_vt = [&](int kt) {
#pragma unroll
        for (int j = 0; j < 2; j++) {
            int idx = tid + 512 * j;
            int d = idx >> 3, ch = idx & 7;
            cp16(sV + (uint32_t)(d * VTH * 2 + ch * 16),
                 vtp + (size_t)d * SEQ + kt * 64 + ch * 8);
        }
    };

    // Preload: Q (g0), K0 (g1), V0 (g2)
    load_qk(sQ, qp, HID);
    cp_commit();
    load_qk(sK, kp, KVHID);
    cp_commit();
    load_vt(0);
    cp_commit();

    if (tid < 64) { ms[tid] = -1e30f; ls[tid] = 0.f; }

    float accO[4][4];
#pragma unroll
    for (int nt = 0; nt < 4; nt++)
#pragma unroll
        for (int t = 0; t < 4; t++) accO[nt][t] = 0.f;

    cp_wait<1>();          // Q + K0 done
    __syncthreads();

    for (int kt = 0; kt < SEQ / 64; kt++) {
        const int kb = kt & 1;
        if (kt + 1 < SEQ / 64)
            load_qk(sK + (uint32_t)((kb ^ 1) * 64 * QKH * 2),
                    kp + (size_t)(kt + 1) * 64 * KVHID, KVHID);
        cp_commit();

        // --- S = Q K^T (fp16 m16n8k16) ---
        const __half* ksb = Ks + kb * 64 * QKH;
        float accS[2][4];
#pragma unroll
        for (int nt = 0; nt < 2; nt++)
#pragma unroll
            for (int t = 0; t < 4; t++) accS[nt][t] = 0.f;

#pragma unroll
        for (int k0 = 0; k0 < 128; k0 += 16) {
            uint32_t aq[4];
            const __half* ar = Qs + (m0 + g) * QKH + k0 + tg * 2;
            aq[0] = *(const uint32_t*)ar;
            aq[1] = *(const uint32_t*)(ar + 8 * QKH);
            aq[2] = *(const uint32_t*)(ar + 8);
            aq[3] = *(const uint32_t*)(ar + 8 * QKH + 8);
#pragma unroll
            for (int nt = 0; nt < 2; nt++) {
                uint32_t bb[2];
                const __half* br = ksb + (nS0 + nt * 8 + g) * QKH + k0 + tg * 2;
                bb[0] = *(const uint32_t*)br;
                bb[1] = *(const uint32_t*)(br + 8);
                mma_f16(accS[nt], aq, bb);
            }
        }

#pragma unroll
        for (int nt = 0; nt < 2; nt++) {
            int col = nS0 + nt * 8 + tg * 2;
            *(float2*)(Ss + (m0 + g) * SSW + col) =
                make_float2(accS[nt][0], accS[nt][1]);
            *(float2*)(Ss + (m0 + g + 8) * SSW + col) =
                make_float2(accS[nt][2], accS[nt][3]);
        }
        __syncthreads();

        // --- online softmax; pack P to fp16 ---
        {
            int row = tid >> 3, qq = tid & 7;
            const float* srow = Ss + row * SSW + qq * 8;
            float sv[8];
#pragma unroll
            for (int j = 0; j < 8; j++) sv[j] = srow[j];
            float mx = sv[0];
#pragma unroll
            for (int j = 1; j < 8; j++) mx = fmaxf(mx, sv[j]);
            mx = fmaxf(mx, __shfl_xor_sync(0xffffffffu, mx, 1));
            mx = fmaxf(mx, __shfl_xor_sync(0xffffffffu, mx, 2));
            mx = fmaxf(mx, __shfl_xor_sync(0xffffffffu, mx, 4));
            float m_old = ms[row];
            float m_new = fmaxf(m_old, mx);
            float sum = 0.f;
#pragma unroll
            for (int j = 0; j < 8; j++) {
                sv[j] = __expf(sv[j] - m_new);
                sum += sv[j];
            }
            __half2* ph = (__half2*)(Php + row * PH + qq * 8);
#pragma unroll
            for (int j = 0; j < 4; j++)
                ph[j] = __floats2half2_rn(sv[2 * j], sv[2 * j + 1]);
            sum += __shfl_xor_sync(0xffffffffu, sum, 1);
            sum += __shfl_xor_sync(0xffffffffu, sum, 2);
            sum += __shfl_xor_sync(0xffffffffu, sum, 4);
            if (qq == 0) {
                float f = __expf(m_old - m_new);
                fct[row] = f;
                ls[row] = ls[row] * f + sum;
                ms[row] = m_new;
            }
        }
        __syncthreads();

        cp_wait<1>();      // V(t) done (only K(t+1) may stay pending)
        __syncthreads();

        // --- rescale accumulators, O += P V (fp16 m16n8k16) ---
        {
            float f0 = fct[m0 + g];
            float f1 = fct[m0 + g + 8];
#pragma unroll
            for (int nt = 0; nt < 4; nt++) {
                accO[nt][0] *= f0; accO[nt][1] *= f0;
                accO[nt][2] *= f1; accO[nt][3] *= f1;
            }
        }
#pragma unroll
        for (int k0 = 0; k0 < 64; k0 += 16) {
            uint32_t pa[4];
            const __half* pr = Php + (m0 + g) * PH + k0 + tg * 2;
            pa[0] = *(const uint32_t*)pr;
            pa[1] = *(const uint32_t*)(pr + 8 * PH);
            pa[2] = *(const uint32_t*)(pr + 8);
            pa[3] = *(const uint32_t*)(pr + 8 * PH + 8);
#pragma unroll
            for (int nt = 0; nt < 4; nt++) {
                uint32_t vb[2];
                const __half* vr = Vt + (nO0 + nt * 8 + g) * VTH + k0 + tg * 2;
                vb[0] = *(const uint32_t*)vr;
                vb[1] = *(const uint32_t*)(vr + 8);
                mma_f16(accO[nt], pa, vb);
            }
        }
        __syncthreads();   // all PV reads of Vt complete

        if (kt + 1 < SEQ / 64) load_vt(kt + 1);
        cp_commit();

        cp_wait<1>();      // K(t+1) done
        __syncthreads();
    }

    // --- finalize: divide by l, emit fp16 ---
    float inv0 = 1.0f / ls[m0 + g];
    float inv1 = 1.0f / ls[m0 + g + 8];
    __half* op = O + (size_t)qt * 64 * HID + head * HD;
#pragma unroll
    for (int nt = 0; nt < 4; nt++) {
        int col = nO0 + nt * 8 + tg * 2;
        *(__half2*)(op + (size_t)(m0 + g) * HID + col) =
            __floats2half2_rn(accO[nt][0] * inv0, accO[nt][1] * inv0);
        *(__half2*)(op + (size_t)(m0 + g + 8) * HID + col) =
            __floats2half2_rn(accO[nt][2] * inv1, accO[nt][3] * inv1);
    }
}

// ---------------------------------------------------------------------------
// Launch
// ---------------------------------------------------------------------------
extern "C" void kernel_launch(void* const* d_in, const int* in_sizes, int n_in,
                              void* d_out, int out_size) {
    (void)in_sizes; (void)n_in; (void)out_size;
    const float* hs  = (const float*)d_in[0];
    const int*   pos = (const int*)d_in[1];
    const float* qw  = (const float*)d_in[2];
    const float* kw  = (const float*)d_in[3];
    const float* vw  = (const float*)d_in[4];
    const float* ow  = (const float*)d_in[5];
    float* out = (float*)d_out;

    float *q, *kv;
    __half *qth, *kh, *vth, *attnh, *hsh, *qwh, *kvwh, *owh;
    cudaGetSymbolAddress((void**)&q, g_q);
    cudaGetSymbolAddress((void**)&kv, g_kv);
    cudaGetSymbolAddress((void**)&qth, g_qth);
    cudaGetSymbolAddress((void**)&kh, g_kh);
    cudaGetSymbolAddress((void**)&vth, g_vth);
    cudaGetSymbolAddress((void**)&attnh, g_attnh);
    cudaGetSymbolAddress((void**)&hsh, g_hsh);
    cudaGetSymbolAddress((void**)&qwh, g_qwh);
    cudaGetSymbolAddress((void**)&kvwh, g_kvwh);
    cudaGetSymbolAddress((void**)&owh, g_owh);

    cudaFuncSetAttribute(gemm_f16,
                         cudaFuncAttributeMaxDynamicSharedMemorySize, HGEMM_SMEM);
    cudaFuncSetAttribute(gemm_qkv,
                         cudaFuncAttributeMaxDynamicSharedMemorySize, HGEMM_SMEM);
    cudaFuncSetAttribute(attn_mma,
                         cudaFuncAttributeMaxDynamicSharedMemorySize, ATTN_SMEM);

    // Convert inputs to fp16; k_proj/v_proj concatenated into one weight buffer
    cvt_f2h<<<(SEQ * HID / 4 + 255) / 256, 256>>>(hs, hsh, SEQ * HID / 4);
    cvt_f2h<<<(HID * HID / 4 + 255) / 256, 256>>>(qw, qwh, HID * HID / 4);
    cvt_f2h<<<(KVHID * HID / 4 + 255) / 256, 256>>>(kw, kvwh, KVHID * HID / 4);
    cvt_f2h<<<(KVHID * HID / 4 + 255) / 256, 256>>>(vw, kvwh + (size_t)KVHID * HID,
                                                    KVHID * HID / 4);
    cvt_f2h<<<(HID * HID / 4 + 255) / 256, 256>>>(ow, owh, HID * HID / 4);

    // Fused Q + KV projections: one 768-CTA launch, occ 2, fp16 mma
    gemm_qkv<<<768, 256, HGEMM_SMEM>>>(hsh, qwh, kvwh, q, kv);

    // RoPE -> fp16 Q (scaled) and K; V -> transposed fp16
    rope_kernel<<<dim3(SEQ, NH + NKV), 64>>>(q, kv, qth, kh, pos);
    vt_kernel<<<dim3(SEQ / 32, HD / 32, NKV), dim3(32, 8)>>>(kv, vth);

    // Attention (full fp16 mma path)
    attn_mma<<<dim3(SEQ / 64, NH), 512, ATTN_SMEM>>>(qth, kh, vth, attnh);

    // Output projection (fp16 mma)
    gemm_f16<<<dim3(HID / 128, SEQ / 128), 256, HGEMM_SMEM>>>(attnh, owh, out, SEQ, HID, HID);
}

// round 12
// speedup vs baseline: 6.6192x; 1.0210x over previous
#include <cuda_runtime.h>
#include <cuda_bf16.h>
#include <cuda_fp16.h>
#include <stdint.h>
#include <math.h>

// Problem constants
#define SEQ   2048
#define HID   4096
#define NH    32
#define NKV   8
#define HD    128
#define KVHID 1024      // NKV*HD
#define KVW   2048      // merged k|v row width

// Scratch (device globals; allocation-free rule)
__device__ float  g_q[SEQ * HID];        // q_proj output (pre-rope, fp32)
__device__ float  g_kv[SEQ * KVW];       // merged [k | v] fp32 from projection
__device__ __half g_qth[SEQ * HID];      // roped, scaled Q (fp16)
__device__ __half g_kh[SEQ * KVHID];     // roped K (fp16)
__device__ __half g_vth[NKV * HD * SEQ]; // V^T (fp16): [kvh][d][s]
__device__ __half g_attnh[SEQ * HID];    // attention output (fp16)

// fp16 copies of inputs for tensor-core GEMMs
__device__ __half g_hsh[SEQ * HID];
__device__ __half g_qwh[HID * HID];
__device__ __half g_kvwh[KVW * HID];     // rows 0-1023 = k_proj, 1024-2047 = v_proj
__device__ __half g_owh[HID * HID];

// ---------------------------------------------------------------------------
// Helpers
// ---------------------------------------------------------------------------
__device__ __forceinline__ void mma_f16(float* c, const uint32_t* a,
                                        const uint32_t* b) {
    asm volatile(
        "mma.sync.aligned.m16n8k16.row.col.f32.f16.f16.f32 "
        "{%0,%1,%2,%3}, {%4,%5,%6,%7}, {%8,%9}, {%0,%1,%2,%3};"
        : "+f"(c[0]), "+f"(c[1]), "+f"(c[2]), "+f"(c[3])
        : "r"(a[0]), "r"(a[1]), "r"(a[2]), "r"(a[3]), "r"(b[0]), "r"(b[1]));
}

__device__ __forceinline__ void cp16(uint32_t saddr, const void* gaddr) {
    asm volatile("cp.async.cg.shared.global [%0], [%1], 16;"
                 :: "r"(saddr), "l"(gaddr));
}
__device__ __forceinline__ void cp_commit() {
    asm volatile("cp.async.commit_group;");
}
template <int N>
__device__ __forceinline__ void cp_wait() {
    asm volatile("cp.async.wait_group %0;" :: "n"(N));
}

// ---------------------------------------------------------------------------
// Fused fp32->fp16 conversion of all 5 inputs, one launch, MLP=4.
// Virtual concatenation in float4 units; every segment is a multiple of 1024
// float4s, so a 1024-float4 block never straddles segments.
// ---------------------------------------------------------------------------
#define CVT_S0 (SEQ * HID / 4)                         // hs    : 2M
#define CVT_S1 (CVT_S0 + HID * HID / 4)                // qw    : +4M
#define CVT_S2 (CVT_S1 + KVHID * HID / 4)              // kw    : +1M
#define CVT_S3 (CVT_S2 + KVHID * HID / 4)              // vw    : +1M
#define CVT_S4 (CVT_S3 + HID * HID / 4)                // ow    : +4M
#define CVT_BLOCKS (CVT_S4 / 1024)

__global__ __launch_bounds__(256) void cvt_all(const float* __restrict__ hs,
                                               const float* __restrict__ qw,
                                               const float* __restrict__ kw,
                                               const float* __restrict__ vw,
                                               const float* __restrict__ ow,
                                               __half* __restrict__ hsh,
                                               __half* __restrict__ qwh,
                                               __half* __restrict__ kvwh,
                                               __half* __restrict__ owh) {
    const long long base = (long long)blockIdx.x * 1024;
    const float* src;
    __half2* dst;
    long long off;
    if (base < CVT_S0)      { src = hs; dst = (__half2*)hsh;  off = base; }
    else if (base < CVT_S1) { src = qw; dst = (__half2*)qwh;  off = base - CVT_S0; }
    else if (base < CVT_S2) { src = kw; dst = (__half2*)kvwh; off = base - CVT_S1; }
    else if (base < CVT_S3) { src = vw; dst = (__half2*)(kvwh + (size_t)KVHID * HID);
                              off = base - CVT_S2; }
    else                    { src = ow; dst = (__half2*)owh;  off = base - CVT_S3; }

    float4 x[4];
#pragma unroll
    for (int j = 0; j < 4; j++)
        x[j] = ((const float4*)src)[off + threadIdx.x + j * 256];
#pragma unroll
    for (int j = 0; j < 4; j++) {
        long long f = off + threadIdx.x + j * 256;
        dst[2 * f]     = __floats2half2_rn(x[j].x, x[j].y);
        dst[2 * f + 1] = __floats2half2_rn(x[j].z, x[j].w);
    }
}

// ---------------------------------------------------------------------------
// fp16 tensor-core GEMM core (round-10/11 proven).
// ---------------------------------------------------------------------------
#define HSTRIDE 72
#define HSTAGES 3
#define HGEMM_SMEM (HSTAGES * 2 * 128 * HSTRIDE * 2)   // 110592 B

__device__ __forceinline__ void hgemm_tile_128(const __half* __restrict__ A,
                                               const __half* __restrict__ W,
                                               float* __restrict__ C,
                                               int N, int K,
                                               int mb, int nb, char* gsm) {
    __half* As = (__half*)gsm;                       // [3][128][72]
    __half* Bs = As + HSTAGES * 128 * HSTRIDE;

    const int tid  = threadIdx.x;
    const int lane = tid & 31;
    const int wid  = tid >> 5;
    const int g    = lane >> 2;
    const int tg   = lane & 3;
    const int wm   = (wid >> 1) * 32;
    const int wn   = (wid & 1) * 64;

    const __half* Ap = A + (size_t)mb * K;
    const __half* Wp = W + (size_t)nb * K;

    const uint32_t sA = (uint32_t)__cvta_generic_to_shared(As);
    const uint32_t sB = (uint32_t)__cvta_generic_to_shared(Bs);

    auto issue_stage = [&](int stage, int k0) {
        const uint32_t so = (uint32_t)(stage * 128 * HSTRIDE * 2);
#pragma unroll
        for (int j = 0; j < 4; j++) {
            int idx = tid + 256 * j;
            int row = idx >> 3, ch = idx & 7;
            uint32_t sofs = so + (uint32_t)(row * HSTRIDE * 2 + ch * 16);
            cp16(sA + sofs, Ap + (size_t)row * K + k0 + ch * 8);
            cp16(sB + sofs, Wp + (size_t)row * K + k0 + ch * 8);
        }
    };

    float acc[2][8][4];
#pragma unroll
    for (int i = 0; i < 2; i++)
#pragma unroll
        for (int j = 0; j < 8; j++)
#pragma unroll
            for (int t = 0; t < 4; t++) acc[i][j][t] = 0.f;

    const int NIT = K / 64;
    issue_stage(0, 0);  cp_commit();
    issue_stage(1, 64); cp_commit();
    cp_wait<1>();
    __syncthreads();

    for (int it = 0; it < NIT; it++) {
        const int s = it % HSTAGES;
        const __half* as = As + s * 128 * HSTRIDE;
        const __half* bs = Bs + s * 128 * HSTRIDE;

#pragma unroll
        for (int kk = 0; kk < 4; kk++) {
            uint32_t af[2][4], bf[8][2];
#pragma unroll
            for (int i = 0; i < 2; i++) {
                const __half* ar = as + (wm + i * 16 + g) * HSTRIDE + kk * 16 + tg * 2;
                af[i][0] = *(const uint32_t*)ar;
                af[i][1] = *(const uint32_t*)(ar + 8 * HSTRIDE);
                af[i][2] = *(const uint32_t*)(ar + 8);
                af[i][3] = *(const uint32_t*)(ar + 8 * HSTRIDE + 8);
            }
#pragma unroll
            for (int j = 0; j < 8; j++) {
                const __half* br = bs + (wn + j * 8 + g) * HSTRIDE + kk * 16 + tg * 2;
                bf[j][0] = *(const uint32_t*)br;
                bf[j][1] = *(const uint32_t*)(br + 8);
            }
#pragma unroll
            for (int i = 0; i < 2; i++)
#pragma unroll
                for (int j = 0; j < 8; j++)
                    mma_f16(acc[i][j], af[i], bf[j]);
        }

        if (it + 2 < NIT) issue_stage((it + 2) % HSTAGES, (it + 2) * 64);
        cp_commit();
        cp_wait<1>();
        __syncthreads();
    }

#pragma unroll
    for (int i = 0; i < 2; i++) {
        int row = mb + wm + i * 16 + g;
#pragma unroll
        for (int j = 0; j < 8; j++) {
            int col = nb + wn + j * 8 + tg * 2;
            *(float2*)(C + (size_t)row * N + col) =
                make_float2(acc[i][j][0], acc[i][j][1]);
            *(float2*)(C + (size_t)(row + 8) * N + col) =
                make_float2(acc[i][j][2], acc[i][j][3]);
        }
    }
}

__global__ __launch_bounds__(256, 2) void gemm_f16(const __half* __restrict__ A,
                                                   const __half* __restrict__ W,
                                                   float* __restrict__ C,
                                                   int M, int N, int K) {
    extern __shared__ char gsm[];
    hgemm_tile_128(A, W, C, N, K, blockIdx.y * 128, blockIdx.x * 128, gsm);
}

__global__ __launch_bounds__(256, 2) void gemm_qkv(const __half* __restrict__ A,
                                                   const __half* __restrict__ Wq,
                                                   const __half* __restrict__ Wkv,
                                                   float* __restrict__ Cq,
                                                   float* __restrict__ Ckv) {
    extern __shared__ char gsm[];
    const int bid = blockIdx.x;
    if (bid < 512) {
        hgemm_tile_128(A, Wq, Cq, HID, HID,
                       (bid >> 5) * 128, (bid & 31) * 128, gsm);
    } else {
        const int b2 = bid - 512;
        hgemm_tile_128(A, Wkv, Ckv, KVW, HID,
                       (b2 >> 4) * 128, (b2 & 15) * 128, gsm);
    }
}

// ---------------------------------------------------------------------------
// RoPE v2: one block per sequence position; sincos computed ONCE per (s,d)
// and reused for all 40 heads (was recomputed per head).
// ---------------------------------------------------------------------------
__global__ __launch_bounds__(64) void rope_kernel(const float* __restrict__ q,
                                                  const float* __restrict__ kv,
                                                  __half* __restrict__ qth,
                                                  __half* __restrict__ kh,
                                                  const int* __restrict__ pos_ids) {
    const int s = blockIdx.x;
    const int d = threadIdx.x;  // 0..63

    const float cexp = 0.20503692556210917f;  // ln(500000)/64
    float inv_freq = expf(-(float)d * cexp);
    float freq = (float)pos_ids[s] * inv_freq;
    float cs, sn;
    sincosf(freq, &sn, &cs);

    const float sm_scale = 0.08838834764831845f;  // 1/sqrt(128)
    const float* qrow = q + (size_t)s * HID;
    __half* qtrow = qth + (size_t)s * HID;
#pragma unroll 4
    for (int h = 0; h < NH; h++) {
        float x1 = qrow[h * HD + d];
        float x2 = qrow[h * HD + d + 64];
        qtrow[h * HD + d]      = __float2half_rn((x1 * cs - x2 * sn) * sm_scale);
        qtrow[h * HD + d + 64] = __float2half_rn((x2 * cs + x1 * sn) * sm_scale);
    }
    const float* krow = kv + (size_t)s * KVW;
    __half* khrow = kh + (size_t)s * KVHID;
#pragma unroll
    for (int h = 0; h < NKV; h++) {
        float x1 = krow[h * HD + d];
        float x2 = krow[h * HD + d + 64];
        khrow[h * HD + d]      = __float2half_rn(x1 * cs - x2 * sn);
        khrow[h * HD + d + 64] = __float2half_rn(x2 * cs + x1 * sn);
    }
}

// ---------------------------------------------------------------------------
// V transpose: g_kv v-part fp32 [s][kvh][d] -> g_vth fp16 [kvh][d][s].
// ---------------------------------------------------------------------------
__global__ __launch_bounds__(256) void vt_kernel(const float* __restrict__ kv,
                                                 __half* __restrict__ vt) {
    __shared__ __half tile[32][33];
    const int head = blockIdx.z;
    const int s0 = blockIdx.x * 32;
    const int d0 = blockIdx.y * 32;
    const int tx = threadIdx.x, ty = threadIdx.y;

#pragma unroll
    for (int i = 0; i < 4; i++) {
        int s = s0 + ty + i * 8;
        tile[ty + i * 8][tx] = __float2half_rn(
            kv[(size_t)s * KVW + KVHID + head * HD + d0 + tx]);
    }
    __syncthreads();
#pragma unroll
    for (int i = 0; i < 4; i++) {
        int d = d0 + ty + i * 8;
        vt[(size_t)head * HD * SEQ + (size_t)d * SEQ + s0 + tx] =
            tile[tx][ty + i * 8];
    }
}

// ---------------------------------------------------------------------------
// fp16 mma flash attention v5: 64 queries x 128-key tiles (16 iters).
// Q fragments hoisted to registers. Softmax fp32 in smem, P packed fp16.
// cp.async pipeline: K double-buffered, V^T single-buffered (proven FIFO).
// Strides (halves): Q/K/Vt/P 136 (68 words = 4 mod 32, conflict-free),
// Ss 132 floats (= 4 mod 32).
// ---------------------------------------------------------------------------
#define QKH 136
#define SSW 132
#define KT  128
// bytes: Q 17408 + K 2x34816 + Vt 34816 + Ss 33792 + Ph 17408 + aux 768
#define ATTN_SMEM (64*QKH*2 + 2*KT*QKH*2 + KT*QKH*2 + 64*SSW*4 + 64*QKH*2 + 3*64*4)

__global__ __launch_bounds__(512) void attn_mma(const __half* __restrict__ Qt,
                                                const __half* __restrict__ Kh,
                                                const __half* __restrict__ Vt_g,
                                                __half* __restrict__ O) {
    extern __shared__ char asm_[];
    __half* Qs = (__half*)asm_;                  // 64 x 136
    __half* Ks = Qs + 64 * QKH;                  // 2 x 128 x 136
    __half* Vt = Ks + 2 * KT * QKH;              // 128(d) x 136
    float*  Ss = (float*)(Vt + KT * QKH);        // 64 x 132 fp32
    __half* Php = (__half*)(Ss + 64 * SSW);      // 64 x 136 fp16
    float*  ms = (float*)(Php + 64 * QKH);
    float*  ls = ms + 64;
    float*  fct = ls + 64;

    const uint32_t sbase = (uint32_t)__cvta_generic_to_shared(asm_);
    const uint32_t sQ = sbase;
    const uint32_t sK = sQ + 64 * QKH * 2;
    const uint32_t sV = sK + 2 * KT * QKH * 2;

    const int tid  = threadIdx.x;
    const int lane = tid & 31;
    const int wid  = tid >> 5;
    const int g    = lane >> 2;
    const int tg   = lane & 3;
    const int m0   = (wid >> 2) * 16;
    const int n0   = (wid & 3) * 32;   // both score cols (QK) and d cols (PV)

    const int qt   = blockIdx.x;
    const int head = blockIdx.y;
    const int kvh  = head >> 2;

    const __half* qp  = Qt + (size_t)qt * 64 * HID + head * HD;
    const __half* kp  = Kh + kvh * HD;                  // stride KVHID
    const __half* vtp = Vt_g + (size_t)kvh * HD * SEQ;  // [d][s]

    // Q: 64 rows x 16 chunks = 1024, 2/thread
    auto load_q = [&]() {
#pragma unroll
        for (int j = 0; j < 2; j++) {
            int idx = tid + 512 * j;
            int row = idx >> 4, ch = idx & 15;
            cp16(sQ + (uint32_t)(row * QKH * 2 + ch * 16),
                 qp + (size_t)row * HID + ch * 8);
        }
    };
    // K tile: 128 rows x 16 chunks = 2048, 4/thread
    auto load_k = [&](int kt, int buf) {
        const uint32_t sdst = sK + (uint32_t)(buf * KT * QKH * 2);
#pragma unroll
        for (int j = 0; j < 4; j++) {
            int idx = tid + 512 * j;
            int row = idx >> 4, ch = idx & 15;
            cp16(sdst + (uint32_t)(row * QKH * 2 + ch * 16),
                 kp + (size_t)(kt * KT + row) * KVHID + ch * 8);
        }
    };
    // V^T tile: 128 d-rows x 16 chunks = 2048, 4/thread
    auto load_vt = [&](int kt) {
#pragma unroll
        for (int j = 0; j < 4; j++) {
            int idx = tid + 512 * j;
            int d = idx >> 4, ch = idx & 15;
            cp16(sV + (uint32_t)(d * QKH * 2 + ch * 16),
                 vtp + (size_t)d * SEQ + kt * KT + ch * 8);
        }
    };

    // Preload: Q (g0), K0 (g1), V0 (g2)
    load_q();
    cp_commit();
    load_k(0, 0);
    cp_commit();
    load_vt(0);
    cp_commit();

    if (tid < 64) { ms[tid] = -1e30f; ls[tid] = 0.f; }

    float accO[4][4];
#pragma unroll
    for (int nt = 0; nt < 4; nt++)
#pragma unroll
        for (int t = 0; t < 4; t++) accO[nt][t] = 0.f;

    cp_wait<1>();          // Q + K0 done
    __syncthreads();

    // Hoist Q fragments (8 k-steps x 4 regs)
    uint32_t qf[8][4];
#pragma unroll
    for (int k0 = 0; k0 < 8; k0++) {
        const __half* ar = Qs + (m0 + g) * QKH + k0 * 16 + tg * 2;
        qf[k0][0] = *(const uint32_t*)ar;
        qf[k0][1] = *(const uint32_t*)(ar + 8 * QKH);
        qf[k0][2] = *(const uint32_t*)(ar + 8);
        qf[k0][3] = *(const uint32_t*)(ar + 8 * QKH + 8);
    }

    for (int kt = 0; kt < SEQ / KT; kt++) {
        const int kb = kt & 1;
        if (kt + 1 < SEQ / KT) load_k(kt + 1, kb ^ 1);
        cp_commit();

        // --- S = Q K^T (fp16 m16n8k16): 32 mmas/warp ---
        const __half* ksb = Ks + kb * KT * QKH;
        float accS[4][4];
#pragma unroll
        for (int nt = 0; nt < 4; nt++)
#pragma unroll
            for (int t = 0; t < 4; t++) accS[nt][t] = 0.f;

#pragma unroll
        for (int k0 = 0; k0 < 8; k0++) {
#pragma unroll
            for (int nt = 0; nt < 4; nt++) {
                uint32_t bb[2];
                const __half* br = ksb + (n0 + nt * 8 + g) * QKH + k0 * 16 + tg * 2;
                bb[0] = *(const uint32_t*)br;
                bb[1] = *(const uint32_t*)(br + 8);
                mma_f16(accS[nt], qf[k0], bb);
            }
        }

#pragma unroll
        for (int nt = 0; nt < 4; nt++) {
            int col = n0 + nt * 8 + tg * 2;
            *(float2*)(Ss + (m0 + g) * SSW + col) =
                make_float2(accS[nt][0], accS[nt][1]);
            *(float2*)(Ss + (m0 + g + 8) * SSW + col) =
                make_float2(accS[nt][2], accS[nt][3]);
        }
        __syncthreads();

        // --- online softmax over 128 cols; pack P to fp16 ---
        {
            int row = tid >> 3, qq = tid & 7;
            const float* srow = Ss + row * SSW + qq * 16;
            float sv[16];
#pragma unroll
            for (int j = 0; j < 16; j++) sv[j] = srow[j];
            float mx = sv[0];
#pragma unroll
            for (int j = 1; j < 16; j++) mx = fmaxf(mx, sv[j]);
            mx = fmaxf(mx, __shfl_xor_sync(0xffffffffu, mx, 1));
            mx = fmaxf(mx, __shfl_xor_sync(0xffffffffu, mx, 2));
            mx = fmaxf(mx, __shfl_xor_sync(0xffffffffu, mx, 4));
            float m_old = ms[row];
            float m_new = fmaxf(m_old, mx);
            float sum = 0.f;
#pragma unroll
            for (int j = 0; j < 16; j++) {
                sv[j] = __expf(sv[j] - m_new);
                sum += sv[j];
            }
            __half2* ph = (__half2*)(Php + row * QKH + qq * 16);
#pragma unroll
            for (int j = 0; j < 8; j++)
                ph[j] = __floats2half2_rn(sv[2 * j], sv[2 * j + 1]);
            sum += __shfl_xor_sync(0xffffffffu, sum, 1);
            sum += __shfl_xor_sync(0xffffffffu, sum, 2);
            sum += __shfl_xor_sync(0xffffffffu, sum, 4);
            if (qq == 0) {
                float f = __expf(m_old - m_new);
                fct[row] = f;
                ls[row] = ls[row] * f + sum;
                ms[row] = m_new;
            }
        }
        __syncthreads();

        cp_wait<1>();      // V(t) done (only K(t+1) may stay pending)
        __syncthreads();

        // --- rescale accumulators, O += P V (32 mmas/warp) ---
        {
            float f0 = fct[m0 + g];
            float f1 = fct[m0 + g + 8];
#pragma unroll
            for (int nt = 0; nt < 4; nt++) {
                accO[nt][0] *= f0; accO[nt][1] *= f0;
                accO[nt][2] *= f1; accO[nt][3] *= f1;
            }
        }
#pragma unroll
        for (int k0 = 0; k0 < 8; k0++) {
            uint32_t pa[4];
            const __half* pr = Php + (m0 + g) * QKH + k0 * 16 + tg * 2;
            pa[0] = *(const uint32_t*)pr;
            pa[1] = *(const uint32_t*)(pr + 8 * QKH);
            pa[2] = *(const uint32_t*)(pr + 8);
            pa[3] = *(const uint32_t*)(pr + 8 * QKH + 8);
#pragma unroll
            for (int nt = 0; nt < 4; nt++) {
                uint32_t vb[2];
                const __half* vr = Vt + (n0 + nt * 8 + g) * QKH + k0 * 16 + tg * 2;
                vb[0] = *(const uint32_t*)vr;
                vb[1] = *(const uint32_t*)(vr + 8);
                mma_f16(accO[nt], pa, vb);
            }
        }
        __syncthreads();   // all PV reads of Vt complete

        if (kt + 1 < SEQ / KT) load_vt(kt + 1);
        cp_commit();

        cp_wait<1>();      // K(t+1) done
        __syncthreads();
    }

    // --- finalize: divide by l, emit fp16 ---
    float inv0 = 1.0f / ls[m0 + g];
    float inv1 = 1.0f / ls[m0 + g + 8];
    __half* op = O + (size_t)qt * 64 * HID + head * HD;
#pragma unroll
    for (int nt = 0; nt < 4; nt++) {
        int col = n0 + nt * 8 + tg * 2;
        *(__half2*)(op + (size_t)(m0 + g) * HID + col) =
            __floats2half2_rn(accO[nt][0] * inv0, accO[nt][1] * inv0);
        *(__half2*)(op + (size_t)(m0 + g + 8) * HID + col) =
            __floats2half2_rn(accO[nt][2] * inv1, accO[nt][3] * inv1);
    }
}

// ---------------------------------------------------------------------------
// Launch
// ---------------------------------------------------------------------------
extern "C" void kernel_launch(void* const* d_in, const int* in_sizes, int n_in,
                              void* d_out, int out_size) {
    (void)in_sizes; (void)n_in; (void)out_size;
    const float* hs  = (const float*)d_in[0];
    const int*   pos = (const int*)d_in[1];
    const float* qw  = (const float*)d_in[2];
    const float* kw  = (const float*)d_in[3];
    const float* vw  = (const float*)d_in[4];
    const float* ow  = (const float*)d_in[5];
    float* out = (float*)d_out;

    float *q, *kv;
    __half *qth, *kh, *vth, *attnh, *hsh, *qwh, *kvwh, *owh;
    cudaGetSymbolAddress((void**)&q, g_q);
    cudaGetSymbolAddress((void**)&kv, g_kv);
    cudaGetSymbolAddress((void**)&qth, g_qth);
    cudaGetSymbolAddress((void**)&kh, g_kh);
    cudaGetSymbolAddress((void**)&vth, g_vth);
    cudaGetSymbolAddress((void**)&attnh, g_attnh);
    cudaGetSymbolAddress((void**)&hsh, g_hsh);
    cudaGetSymbolAddress((void**)&qwh, g_qwh);
    cudaGetSymbolAddress((void**)&kvwh, g_kvwh);
    cudaGetSymbolAddress((void**)&owh, g_owh);

    cudaFuncSetAttribute(gemm_f16,
                         cudaFuncAttributeMaxDynamicSharedMemorySize, HGEMM_SMEM);
    cudaFuncSetAttribute(gemm_qkv,
                         cudaFuncAttributeMaxDynamicSharedMemorySize, HGEMM_SMEM);
    cudaFuncSetAttribute(attn_mma,
                         cudaFuncAttributeMaxDynamicSharedMemorySize, ATTN_SMEM);

    // Fused fp16 conversion of all inputs (one launch, MLP 4)
    cvt_all<<<CVT_BLOCKS, 256>>>(hs, qw, kw, vw, ow, hsh, qwh, kvwh, owh);

    // Fused Q + KV projections: one 768-CTA launch, occ 2, fp16 mma
    gemm_qkv<<<768, 256, HGEMM_SMEM>>>(hsh, qwh, kvwh, q, kv);

    // RoPE -> fp16 Q (scaled) and K (sincos once per (s,d)); V -> transposed fp16
    rope_kernel<<<SEQ, 64>>>(q, kv, qth, kh, pos);
    vt_kernel<<<dim3(SEQ / 32, HD / 32, NKV), dim3(32, 8)>>>(kv, vth);

    // Attention (fp16 mma, 128-key tiles)
    attn_mma<<<dim3(SEQ / 64, NH), 512, ATTN_SMEM>>>(qth, kh, vth, attnh);

    // Output projection (fp16 mma)
    gemm_f16<<<dim3(HID / 128, SEQ / 128), 256, HGEMM_SMEM>>>(attnh, owh, out, SEQ, HID, HID);
}

// round 14
// speedup vs baseline: 6.6457x; 1.0040x over previous
#include <cuda_runtime.h>
#include <cuda_bf16.h>
#include <cuda_fp16.h>
#include <stdint.h>
#include <math.h>

// Problem constants
#define SEQ   2048
#define HID   4096
#define NH    32
#define NKV   8
#define HD    128
#define KVHID 1024      // NKV*HD
#define KVW   2048      // merged k|v row width

// Scratch (device globals; allocation-free rule)
__device__ __half g_qth[SEQ * HID];      // roped, scaled Q (fp16)
__device__ __half g_kh[SEQ * KVHID];     // roped K (fp16)
__device__ __half g_vth[NKV * HD * SEQ]; // V^T (fp16): [kvh][d][s]
__device__ __half g_attnh[SEQ * HID];    // attention output (fp16)

// fp16 copies of inputs for tensor-core GEMMs
__device__ __half g_hsh[SEQ * HID];
__device__ __half g_qwh[HID * HID];
__device__ __half g_kvwh[KVW * HID];     // rows 0-1023 = k_proj, 1024-2047 = v_proj
__device__ __half g_owh[HID * HID];

// ---------------------------------------------------------------------------
// Helpers
// ---------------------------------------------------------------------------
__device__ __forceinline__ void mma_f16(float* c, const uint32_t* a,
                                        const uint32_t* b) {
    asm volatile(
        "mma.sync.aligned.m16n8k16.row.col.f32.f16.f16.f32 "
        "{%0,%1,%2,%3}, {%4,%5,%6,%7}, {%8,%9}, {%0,%1,%2,%3};"
        : "+f"(c[0]), "+f"(c[1]), "+f"(c[2]), "+f"(c[3])
        : "r"(a[0]), "r"(a[1]), "r"(a[2]), "r"(a[3]), "r"(b[0]), "r"(b[1]));
}

__device__ __forceinline__ void cp16(uint32_t saddr, const void* gaddr) {
    asm volatile("cp.async.cg.shared.global [%0], [%1], 16;"
                 :: "r"(saddr), "l"(gaddr));
}
__device__ __forceinline__ void cp_commit() {
    asm volatile("cp.async.commit_group;");
}
template <int N>
__device__ __forceinline__ void cp_wait() {
    asm volatile("cp.async.wait_group %0;" :: "n"(N));
}

// ---------------------------------------------------------------------------
// Fused fp32->fp16 conversion of all 5 inputs, one launch, MLP=4.
// ---------------------------------------------------------------------------
#define CVT_S0 (SEQ * HID / 4)                         // hs    : 2M
#define CVT_S1 (CVT_S0 + HID * HID / 4)                // qw    : +4M
#define CVT_S2 (CVT_S1 + KVHID * HID / 4)              // kw    : +1M
#define CVT_S3 (CVT_S2 + KVHID * HID / 4)              // vw    : +1M
#define CVT_S4 (CVT_S3 + HID * HID / 4)                // ow    : +4M
#define CVT_BLOCKS (CVT_S4 / 1024)

__global__ __launch_bounds__(256) void cvt_all(const float* __restrict__ hs,
                                               const float* __restrict__ qw,
                                               const float* __restrict__ kw,
                                               const float* __restrict__ vw,
                                               const float* __restrict__ ow,
                                               __half* __restrict__ hsh,
                                               __half* __restrict__ qwh,
                                               __half* __restrict__ kvwh,
                                               __half* __restrict__ owh) {
    const long long base = (long long)blockIdx.x * 1024;
    const float* src;
    __half2* dst;
    long long off;
    if (base < CVT_S0)      { src = hs; dst = (__half2*)hsh;  off = base; }
    else if (base < CVT_S1) { src = qw; dst = (__half2*)qwh;  off = base - CVT_S0; }
    else if (base < CVT_S2) { src = kw; dst = (__half2*)kvwh; off = base - CVT_S1; }
    else if (base < CVT_S3) { src = vw; dst = (__half2*)(kvwh + (size_t)KVHID * HID);
                              off = base - CVT_S2; }
    else                    { src = ow; dst = (__half2*)owh;  off = base - CVT_S3; }

    float4 x[4];
#pragma unroll
    for (int j = 0; j < 4; j++)
        x[j] = ((const float4*)src)[off + threadIdx.x + j * 256];
#pragma unroll
    for (int j = 0; j < 4; j++) {
        long long f = off + threadIdx.x + j * 256;
        dst[2 * f]     = __floats2half2_rn(x[j].x, x[j].y);
        dst[2 * f + 1] = __floats2half2_rn(x[j].z, x[j].w);
    }
}

// ---------------------------------------------------------------------------
// fp16 tensor-core GEMM core, templated epilogue.
// ---------------------------------------------------------------------------
#define HSTRIDE 72
#define HSTAGES 3
#define HGEMM_SMEM (HSTAGES * 2 * 128 * HSTRIDE * 2)   // 110592 B
#define SST 132   // fp32 smem staging stride (EVEN -> float2-aligned; 4 mod 32)

template <typename EPI>
__device__ __forceinline__ void hgemm_tile_core(const __half* __restrict__ A,
                                                const __half* __restrict__ W,
                                                int K, int mb, int nb,
                                                char* gsm, EPI&& epi) {
    __half* As = (__half*)gsm;                       // [3][128][72]
    __half* Bs = As + HSTAGES * 128 * HSTRIDE;

    const int tid  = threadIdx.x;
    const int lane = tid & 31;
    const int wid  = tid >> 5;
    const int g    = lane >> 2;
    const int tg   = lane & 3;
    const int wm   = (wid >> 1) * 32;
    const int wn   = (wid & 1) * 64;

    const __half* Ap = A + (size_t)mb * K;
    const __half* Wp = W + (size_t)nb * K;

    const uint32_t sA = (uint32_t)__cvta_generic_to_shared(As);
    const uint32_t sB = (uint32_t)__cvta_generic_to_shared(Bs);

    auto issue_stage = [&](int stage, int k0) {
        const uint32_t so = (uint32_t)(stage * 128 * HSTRIDE * 2);
#pragma unroll
        for (int j = 0; j < 4; j++) {
            int idx = tid + 256 * j;
            int row = idx >> 3, ch = idx & 7;
            uint32_t sofs = so + (uint32_t)(row * HSTRIDE * 2 + ch * 16);
            cp16(sA + sofs, Ap + (size_t)row * K + k0 + ch * 8);
            cp16(sB + sofs, Wp + (size_t)row * K + k0 + ch * 8);
        }
    };

    float acc[2][8][4];
#pragma unroll
    for (int i = 0; i < 2; i++)
#pragma unroll
        for (int j = 0; j < 8; j++)
#pragma unroll
            for (int t = 0; t < 4; t++) acc[i][j][t] = 0.f;

    const int NIT = K / 64;
    issue_stage(0, 0);  cp_commit();
    issue_stage(1, 64); cp_commit();
    cp_wait<1>();
    __syncthreads();

    for (int it = 0; it < NIT; it++) {
        const int s = it % HSTAGES;
        const __half* as = As + s * 128 * HSTRIDE;
        const __half* bs = Bs + s * 128 * HSTRIDE;

#pragma unroll
        for (int kk = 0; kk < 4; kk++) {
            uint32_t af[2][4], bf[8][2];
#pragma unroll
            for (int i = 0; i < 2; i++) {
                const __half* ar = as + (wm + i * 16 + g) * HSTRIDE + kk * 16 + tg * 2;
                af[i][0] = *(const uint32_t*)ar;
                af[i][1] = *(const uint32_t*)(ar + 8 * HSTRIDE);
                af[i][2] = *(const uint32_t*)(ar + 8);
                af[i][3] = *(const uint32_t*)(ar + 8 * HSTRIDE + 8);
            }
#pragma unroll
            for (int j = 0; j < 8; j++) {
                const __half* br = bs + (wn + j * 8 + g) * HSTRIDE + kk * 16 + tg * 2;
                bf[j][0] = *(const uint32_t*)br;
                bf[j][1] = *(const uint32_t*)(br + 8);
            }
#pragma unroll
            for (int i = 0; i < 2; i++)
#pragma unroll
                for (int j = 0; j < 8; j++)
                    mma_f16(acc[i][j], af[i], bf[j]);
        }

        if (it + 2 < NIT) issue_stage((it + 2) % HSTAGES, (it + 2) * 64);
        cp_commit();
        cp_wait<1>();
        __syncthreads();
    }

    epi(acc, wm, wn, g, tg);
}

// o_proj: plain fp32 store epilogue
__global__ __launch_bounds__(256, 2) void gemm_f16(const __half* __restrict__ A,
                                                   const __half* __restrict__ W,
                                                   float* __restrict__ C,
                                                   int N, int K) {
    extern __shared__ char gsm[];
    const int mb = blockIdx.y * 128, nb = blockIdx.x * 128;
    hgemm_tile_core(A, W, K, mb, nb, gsm,
        [&](float acc[2][8][4], int wm, int wn, int g, int tg) {
#pragma unroll
            for (int i = 0; i < 2; i++) {
                int row = mb + wm + i * 16 + g;
#pragma unroll
                for (int j = 0; j < 8; j++) {
                    int col = nb + wn + j * 8 + tg * 2;
                    *(float2*)(C + (size_t)row * N + col) =
                        make_float2(acc[i][j][0], acc[i][j][1]);
                    *(float2*)(C + (size_t)(row + 8) * N + col) =
                        make_float2(acc[i][j][2], acc[i][j][3]);
                }
            }
        });
}

// Fused QKV projection + RoPE + V-transpose epilogues.
// Each 128-wide tile covers exactly one head; rope pairs (d, d+64) in-tile.
// Accumulators staged to smem (stride 132, EVEN), then transformed.
__global__ __launch_bounds__(256, 2) void gemm_qkv(const __half* __restrict__ A,
                                                   const __half* __restrict__ Wq,
                                                   const __half* __restrict__ Wkv,
                                                   __half* __restrict__ qth,
                                                   __half* __restrict__ kh,
                                                   __half* __restrict__ vth,
                                                   const int* __restrict__ pos_ids) {
    extern __shared__ char gsm[];
    float* st = (float*)gsm;   // 128 x 132 fp32 staging (reuses pipeline smem)
    const int tid = threadIdx.x;
    const int bid = blockIdx.x;

    int mb, nb;
    const __half* Wp;
    if (bid < 512) { mb = (bid >> 5) * 128; nb = (bid & 31) * 128; Wp = Wq; }
    else { int b2 = bid - 512; mb = (b2 >> 4) * 128; nb = (b2 & 15) * 128; Wp = Wkv; }

    hgemm_tile_core(A, Wp, HID, mb, nb, gsm,
        [&](float acc[2][8][4], int wm, int wn, int g, int tg) {
            // stage accumulators to smem (even stride -> aligned float2)
#pragma unroll
            for (int i = 0; i < 2; i++) {
                int r = wm + i * 16 + g;
#pragma unroll
                for (int j = 0; j < 8; j++) {
                    int c = wn + j * 8 + tg * 2;
                    *(float2*)&st[r * SST + c] =
                        make_float2(acc[i][j][0], acc[i][j][1]);
                    *(float2*)&st[(r + 8) * SST + c] =
                        make_float2(acc[i][j][2], acc[i][j][3]);
                }
            }
            __syncthreads();

            const float cexp = 0.20503692556210917f;   // ln(500000)/64
            const float sm_scale = 0.08838834764831845f;

            if (bid < 512 || nb < 1024) {
                // q or k head: rope (+scale for q)
                const bool is_q = (bid < 512);
                const int head = nb >> 7;
                __half* dst = is_q ? (qth + head * HD) : (kh + head * HD);
                const int rs = is_q ? HID : KVHID;
                const float scl = is_q ? sm_scale : 1.0f;
#pragma unroll 4
                for (int j = 0; j < 32; j++) {
                    int idx = tid + 256 * j;        // 8192 = 128 rows x 64 d
                    int d = idx & 63, r = idx >> 6;
                    float x1 = st[r * SST + d];
                    float x2 = st[r * SST + d + 64];
                    float inv_freq = expf(-(float)d * cexp);
                    float fr = (float)pos_ids[mb + r] * inv_freq;
                    float cs, sn;
                    sincosf(fr, &sn, &cs);
                    size_t o = (size_t)(mb + r) * rs + d;
                    dst[o]      = __float2half_rn((x1 * cs - x2 * sn) * scl);
                    dst[o + 64] = __float2half_rn((x2 * cs + x1 * sn) * scl);
                }
            } else {
                // v head: transpose to [kvh][d][s]
                const int head = (nb - 1024) >> 7;
                __half* dst = vth + (size_t)head * HD * SEQ;
#pragma unroll 4
                for (int j = 0; j < 64; j++) {
                    int idx = tid + 256 * j;        // 16384 = 128 d x 128 rows
                    int d = idx >> 7, r = idx & 127;
                    dst[(size_t)d * SEQ + mb + r] =
                        __float2half_rn(st[r * SST + d]);
                }
            }
        });
}

// ---------------------------------------------------------------------------
// fp16 mma flash attention v5 (round-12 proven): 64 q x 128-key tiles.
// ---------------------------------------------------------------------------
#define QKH 136
#define SSW 132
#define KT  128
#define ATTN_SMEM (64*QKH*2 + 2*KT*QKH*2 + KT*QKH*2 + 64*SSW*4 + 64*QKH*2 + 3*64*4)

__global__ __launch_bounds__(512) void attn_mma(const __half* __restrict__ Qt,
                                                const __half* __restrict__ Kh,
                                                const __half* __restrict__ Vt_g,
                                                __half* __restrict__ O) {
    extern __shared__ char asm_[];
    __half* Qs = (__half*)asm_;                  // 64 x 136
    __half* Ks = Qs + 64 * QKH;                  // 2 x 128 x 136
    __half* Vt = Ks + 2 * KT * QKH;              // 128(d) x 136
    float*  Ss = (float*)(Vt + KT * QKH);        // 64 x 132 fp32
    __half* Php = (__half*)(Ss + 64 * SSW);      // 64 x 136 fp16
    float*  ms = (float*)(Php + 64 * QKH);
    float*  ls = ms + 64;
    float*  fct = ls + 64;

    const uint32_t sbase = (uint32_t)__cvta_generic_to_shared(asm_);
    const uint32_t sQ = sbase;
    const uint32_t sK = sQ + 64 * QKH * 2;
    const uint32_t sV = sK + 2 * KT * QKH * 2;

    const int tid  = threadIdx.x;
    const int lane = tid & 31;
    const int wid  = tid >> 5;
    const int g    = lane >> 2;
    const int tg   = lane & 3;
    const int m0   = (wid >> 2) * 16;
    const int n0   = (wid & 3) * 32;

    const int qt   = blockIdx.x;
    const int head = blockIdx.y;
    const int kvh  = head >> 2;

    const __half* qp  = Qt + (size_t)qt * 64 * HID + head * HD;
    const __half* kp  = Kh + kvh * HD;
    const __half* vtp = Vt_g + (size_t)kvh * HD * SEQ;

    auto load_q = [&]() {
#pragma unroll
        for (int j = 0; j < 2; j++) {
            int idx = tid + 512 * j;
            int row = idx >> 4, ch = idx & 15;
            cp16(sQ + (uint32_t)(row * QKH * 2 + ch * 16),
                 qp + (size_t)row * HID + ch * 8);
        }
    };
    auto load_k = [&](int kt, int buf) {
        const uint32_t sdst = sK + (uint32_t)(buf * KT * QKH * 2);
#pragma unroll
        for (int j = 0; j < 4; j++) {
            int idx = tid + 512 * j;
            int row = idx >> 4, ch = idx & 15;
            cp16(sdst + (uint32_t)(row * QKH * 2 + ch * 16),
                 kp + (size_t)(kt * KT + row) * KVHID + ch * 8);
        }
    };
    auto load_vt = [&](int kt) {
#pragma unroll
        for (int j = 0; j < 4; j++) {
            int idx = tid + 512 * j;
            int d = idx >> 4, ch = idx & 15;
            cp16(sV + (uint32_t)(d * QKH * 2 + ch * 16),
                 vtp + (size_t)d * SEQ + kt * KT + ch * 8);
        }
    };

    load_q();
    cp_commit();
    load_k(0, 0);
    cp_commit();
    load_vt(0);
    cp_commit();

    if (tid < 64) { ms[tid] = -1e30f; ls[tid] = 0.f; }

    float accO[4][4];
#pragma unroll
    for (int nt = 0; nt < 4; nt++)
#pragma unroll
        for (int t = 0; t < 4; t++) accO[nt][t] = 0.f;

    cp_wait<1>();
    __syncthreads();

    uint32_t qf[8][4];
#pragma unroll
    for (int k0 = 0; k0 < 8; k0++) {
        const __half* ar = Qs + (m0 + g) * QKH + k0 * 16 + tg * 2;
        qf[k0][0] = *(const uint32_t*)ar;
        qf[k0][1] = *(const uint32_t*)(ar + 8 * QKH);
        qf[k0][2] = *(const uint32_t*)(ar + 8);
        qf[k0][3] = *(const uint32_t*)(ar + 8 * QKH + 8);
    }

    for (int kt = 0; kt < SEQ / KT; kt++) {
        const int kb = kt & 1;
        if (kt + 1 < SEQ / KT) load_k(kt + 1, kb ^ 1);
        cp_commit();

        const __half* ksb = Ks + kb * KT * QKH;
        float accS[4][4];
#pragma unroll
        for (int nt = 0; nt < 4; nt++)
#pragma unroll
            for (int t = 0; t < 4; t++) accS[nt][t] = 0.f;

#pragma unroll
        for (int k0 = 0; k0 < 8; k0++) {
#pragma unroll
            for (int nt = 0; nt < 4; nt++) {
                uint32_t bb[2];
                const __half* br = ksb + (n0 + nt * 8 + g) * QKH + k0 * 16 + tg * 2;
                bb[0] = *(const uint32_t*)br;
                bb[1] = *(const uint32_t*)(br + 8);
                mma_f16(accS[nt], qf[k0], bb);
            }
        }

#pragma unroll
        for (int nt = 0; nt < 4; nt++) {
            int col = n0 + nt * 8 + tg * 2;
            *(float2*)(Ss + (m0 + g) * SSW + col) =
                make_float2(accS[nt][0], accS[nt][1]);
            *(float2*)(Ss + (m0 + g + 8) * SSW + col) =
                make_float2(accS[nt][2], accS[nt][3]);
        }
        __syncthreads();

        {
            int row = tid >> 3, qq = tid & 7;
            const float* srow = Ss + row * SSW + qq * 16;
            float sv[16];
#pragma unroll
            for (int j = 0; j < 16; j++) sv[j] = srow[j];
            float mx = sv[0];
#pragma unroll
            for (int j = 1; j < 16; j++) mx = fmaxf(mx, sv[j]);
            mx = fmaxf(mx, __shfl_xor_sync(0xffffffffu, mx, 1));
            mx = fmaxf(mx, __shfl_xor_sync(0xffffffffu, mx, 2));
            mx = fmaxf(mx, __shfl_xor_sync(0xffffffffu, mx, 4));
            float m_old = ms[row];
            float m_new = fmaxf(m_old, mx);
            float sum = 0.f;
#pragma unroll
            for (int j = 0; j < 16; j++) {
                sv[j] = __expf(sv[j] - m_new);
                sum += sv[j];
            }
            __half2* ph = (__half2*)(Php + row * QKH + qq * 16);
#pragma unroll
            for (int j = 0; j < 8; j++)
                ph[j] = __floats2half2_rn(sv[2 * j], sv[2 * j + 1]);
            sum += __shfl_xor_sync(0xffffffffu, sum, 1);
            sum += __shfl_xor_sync(0xffffffffu, sum, 2);
            sum += __shfl_xor_sync(0xffffffffu, sum, 4);
            if (qq == 0) {
                float f = __expf(m_old - m_new);
                fct[row] = f;
                ls[row] = ls[row] * f + sum;
                ms[row] = m_new;
            }
        }
        __syncthreads();

        cp_wait<1>();
        __syncthreads();

        {
            float f0 = fct[m0 + g];
            float f1 = fct[m0 + g + 8];
#pragma unroll
            for (int nt = 0; nt < 4; nt++) {
                accO[nt][0] *= f0; accO[nt][1] *= f0;
                accO[nt][2] *= f1; accO[nt][3] *= f1;
            }
        }
#pragma unroll
        for (int k0 = 0; k0 < 8; k0++) {
            uint32_t pa[4];
            const __half* pr = Php + (m0 + g) * QKH + k0 * 16 + tg * 2;
            pa[0] = *(const uint32_t*)pr;
            pa[1] = *(const uint32_t*)(pr + 8 * QKH);
            pa[2] = *(const uint32_t*)(pr + 8);
            pa[3] = *(const uint32_t*)(pr + 8 * QKH + 8);
#pragma unroll
            for (int nt = 0; nt < 4; nt++) {
                uint32_t vb[2];
                const __half* vr = Vt + (n0 + nt * 8 + g) * QKH + k0 * 16 + tg * 2;
                vb[0] = *(const uint32_t*)vr;
                vb[1] = *(const uint32_t*)(vr + 8);
                mma_f16(accO[nt], pa, vb);
            }
        }
        __syncthreads();

        if (kt + 1 < SEQ / KT) load_vt(kt + 1);
        cp_commit();

        cp_wait<1>();
        __syncthreads();
    }

    float inv0 = 1.0f / ls[m0 + g];
    float inv1 = 1.0f / ls[m0 + g + 8];
    __half* op = O + (size_t)qt * 64 * HID + head * HD;
#pragma unroll
    for (int nt = 0; nt < 4; nt++) {
        int col = n0 + nt * 8 + tg * 2;
        *(__half2*)(op + (size_t)(m0 + g) * HID + col) =
            __floats2half2_rn(accO[nt][0] * inv0, accO[nt][1] * inv0);
        *(__half2*)(op + (size_t)(m0 + g + 8) * HID + col) =
            __floats2half2_rn(accO[nt][2] * inv1, accO[nt][3] * inv1);
    }
}

// ---------------------------------------------------------------------------
// Launch
// ---------------------------------------------------------------------------
extern "C" void kernel_launch(void* const* d_in, const int* in_sizes, int n_in,
                              void* d_out, int out_size) {
    (void)in_sizes; (void)n_in; (void)out_size;
    const float* hs  = (const float*)d_in[0];
    const int*   pos = (const int*)d_in[1];
    const float* qw  = (const float*)d_in[2];
    const float* kw  = (const float*)d_in[3];
    const float* vw  = (const float*)d_in[4];
    const float* ow  = (const float*)d_in[5];
    float* out = (float*)d_out;

    __half *qth, *kh, *vth, *attnh, *hsh, *qwh, *kvwh, *owh;
    cudaGetSymbolAddress((void**)&qth, g_qth);
    cudaGetSymbolAddress((void**)&kh, g_kh);
    cudaGetSymbolAddress((void**)&vth, g_vth);
    cudaGetSymbolAddress((void**)&attnh, g_attnh);
    cudaGetSymbolAddress((void**)&hsh, g_hsh);
    cudaGetSymbolAddress((void**)&qwh, g_qwh);
    cudaGetSymbolAddress((void**)&kvwh, g_kvwh);
    cudaGetSymbolAddress((void**)&owh, g_owh);

    cudaFuncSetAttribute(gemm_f16,
                         cudaFuncAttributeMaxDynamicSharedMemorySize, HGEMM_SMEM);
    cudaFuncSetAttribute(gemm_qkv,
                         cudaFuncAttributeMaxDynamicSharedMemorySize, HGEMM_SMEM);
    cudaFuncSetAttribute(attn_mma,
                         cudaFuncAttributeMaxDynamicSharedMemorySize, ATTN_SMEM);

    // Fused fp16 conversion of all inputs (one launch, MLP 4)
    cvt_all<<<CVT_BLOCKS, 256>>>(hs, qw, kw, vw, ow, hsh, qwh, kvwh, owh);

    // Fused Q + KV projections with RoPE / V-transpose epilogues
    gemm_qkv<<<768, 256, HGEMM_SMEM>>>(hsh, qwh, kvwh, qth, kh, vth, pos);

    // Attention (fp16 mma, 128-key tiles)
    attn_mma<<<dim3(SEQ / 64, NH), 512, ATTN_SMEM>>>(qth, kh, vth, attnh);

    // Output projection (fp16 mma)
    gemm_f16<<<dim3(HID / 128, SEQ / 128), 256, HGEMM_SMEM>>>(attnh, owh, out, HID, HID);
}